// round 10
// baseline (speedup 1.0000x reference)
#include <cuda_runtime.h>
#include <cuda_bf16.h>
#include <cstdint>

#define Bn 8
#define Cn 256
#define Pn 1024
#define HEADS 8
#define HD 32

// ---- fp32 scratch ----
__device__ float g_off[Bn*2*Pn];

// ---- split-bf16 interchange planes (hi/lo) ----
__device__ __nv_bfloat16 g_qh[Bn*Cn*Pn], g_ql[Bn*Cn*Pn];   // unscaled q
__device__ __nv_bfloat16 g_kh[Bn*Cn*Pn], g_kl[Bn*Cn*Pn];   // scale folded via Wk
__device__ __nv_bfloat16 g_vh[Bn*Cn*Pn], g_vl[Bn*Cn*Pn];
__device__ __nv_bfloat16 g_sh[Bn*Cn*Pn], g_sl[Bn*Cn*Pn];   // sampled kv
__device__ __nv_bfloat16 g_oh[Bn*Cn*Pn], g_ol[Bn*Cn*Pn];   // attn out

// ---- pre-split weights ----
__device__ __nv_bfloat16 w_qh[Cn*Cn], w_ql[Cn*Cn];
__device__ __nv_bfloat16 w_kh[Cn*Cn], w_kl[Cn*Cn];         // pre-scaled by qscale
__device__ __nv_bfloat16 w_vh[Cn*Cn], w_vl[Cn*Cn];
__device__ __nv_bfloat16 w_oh[Cn*Cn], w_ol[Cn*Cn];
__device__ __nv_bfloat16 w_ch[128*2304], w_cl[128*2304];   // [o][t*256+c]

// ---- helpers ----
__device__ __forceinline__ uint32_t smem_u32(const void* p) {
    uint32_t a;
    asm("{ .reg .u64 t; cvta.to.shared.u64 t, %1; cvt.u32.u64 %0, t; }"
        : "=r"(a) : "l"(p));
    return a;
}
__device__ __forceinline__ void ldsm_x4(uint32_t r[4], uint32_t addr) {
    asm volatile("ldmatrix.sync.aligned.m8n8.x4.shared.b16 {%0,%1,%2,%3}, [%4];"
        : "=r"(r[0]), "=r"(r[1]), "=r"(r[2]), "=r"(r[3]) : "r"(addr));
}
__device__ __forceinline__ void ldsm_x4_t(uint32_t r[4], uint32_t addr) {
    asm volatile("ldmatrix.sync.aligned.m8n8.x4.trans.shared.b16 {%0,%1,%2,%3}, [%4];"
        : "=r"(r[0]), "=r"(r[1]), "=r"(r[2]), "=r"(r[3]) : "r"(addr));
}
__device__ __forceinline__ void mma_bf16(float d[4], const uint32_t a[4],
                                         const uint32_t b[2]) {
    asm volatile(
        "mma.sync.aligned.m16n8k16.row.col.f32.bf16.bf16.f32 "
        "{%0,%1,%2,%3}, {%4,%5,%6,%7}, {%8,%9}, {%0,%1,%2,%3};"
        : "+f"(d[0]), "+f"(d[1]), "+f"(d[2]), "+f"(d[3])
        : "r"(a[0]), "r"(a[1]), "r"(a[2]), "r"(a[3]), "r"(b[0]), "r"(b[1]));
}
__device__ __forceinline__ void split_bf16(float x, __nv_bfloat16& hi,
                                           __nv_bfloat16& lo) {
    hi = __float2bfloat16_rn(x);
    lo = __float2bfloat16_rn(x - __bfloat162float(hi));
}
__device__ __forceinline__ uint32_t pack_bf2(__nv_bfloat16 a, __nv_bfloat16 b) {
    __nv_bfloat162 t = __halves2bfloat162(a, b);
    return *reinterpret_cast<uint32_t*>(&t);
}
__device__ __forceinline__ void split2(float a, float b, uint32_t& hi, uint32_t& lo) {
    __nv_bfloat16 ha, la, hb, lb;
    split_bf16(a, ha, la);
    split_bf16(b, hb, lb);
    hi = pack_bf2(ha, hb);
    lo = pack_bf2(la, lb);
}
__device__ __forceinline__ float ex2f(float x) {
    float y; asm("ex2.approx.ftz.f32 %0, %1;" : "=f"(y) : "f"(x)); return y;
}

#define SA_STRIDE 40
#define SB_STRIDE 136
#define SC_STRIDE 72

// =====================================================================
// One-shot weight prep: split all weights; Wk scaled by kscale;
// conv W reordered [o][c*9+t] -> [o][t*256+c]. grid 2176 x 256.
// =====================================================================
__global__ void __launch_bounds__(256) split_all(
    const float* __restrict__ Wq, const float* __restrict__ Wk,
    const float* __restrict__ Wv, const float* __restrict__ Wout,
    const float* __restrict__ Woff1, float kscale)
{
    int idx = blockIdx.x * 256 + threadIdx.x;
    if (idx < 4 * 65536) {
        int w = idx >> 16, i = idx & 65535;
        const float* srcs[4] = {Wq, Wk, Wv, Wout};
        __nv_bfloat16* dh[4] = {w_qh, w_kh, w_vh, w_oh};
        __nv_bfloat16* dl[4] = {w_ql, w_kl, w_vl, w_ol};
        float v = srcs[w][i] * (w == 1 ? kscale : 1.0f);
        split_bf16(v, dh[w][i], dl[w][i]);
    } else {
        int i = idx - 4 * 65536;            // [0, 294912)
        int o = i / 2304;
        int r = i - o * 2304;
        int c = r / 9;
        int t = r - c * 9;
        int dst = o * 2304 + t * 256 + c;
        split_bf16(Woff1[i], w_ch[dst], w_cl[dst]);
    }
}

// =====================================================================
// GEMM via mma.sync bf16-split, software-pipelined k-loop.
// BMODE: 0 = fp32 B (split at store), 1 = split-plane B.
// OMODE bit0: fp32 out (+bias); bit1: split planes out (scaled).
// CTA tile 128x128, grid (8, O/128, 8), 256 threads.
// =====================================================================
template<int BMODE, int OMODE>
__global__ void __launch_bounds__(256) gemm_mma(
    const __nv_bfloat16* __restrict__ Ah, const __nv_bfloat16* __restrict__ Al,
    const float* __restrict__ Bf,
    const __nv_bfloat16* __restrict__ Bh, const __nv_bfloat16* __restrict__ Bl,
    const float* __restrict__ bias,
    float* __restrict__ Yf,
    __nv_bfloat16* __restrict__ Yh, __nv_bfloat16* __restrict__ Yl,
    float yscale, int Cin)
{
    __shared__ __align__(16) __nv_bfloat16 sA[2][128][SA_STRIDE];
    __shared__ __align__(16) __nv_bfloat16 sB[2][32][SB_STRIDE];
    const int b  = blockIdx.z;
    const int o0 = blockIdx.y * 128;
    const int p0 = blockIdx.x * 128;
    const int O  = gridDim.y * 128;
    const size_t bB = (size_t)b * Cin * Pn;
    const size_t bY = (size_t)b * O * Pn;
    const int tid  = threadIdx.x;
    const int lane = tid & 31;
    const int wid  = tid >> 5;
    const int wm   = wid & 3;
    const int wn   = wid >> 2;

    float d[2][8][4];
    #pragma unroll
    for (int mf = 0; mf < 2; mf++)
        #pragma unroll
        for (int nf = 0; nf < 8; nf++)
            #pragma unroll
            for (int i = 0; i < 4; i++) d[mf][nf][i] = 0.0f;

    const int a_row  = (lane & 7) + ((lane >> 3) & 1) * 8;
    const int a_colk = ((lane >> 4) & 1) * 8;
    const int b_rowk = (lane & 7) + ((lane >> 3) & 1) * 8;
    const int b_ncol = ((lane >> 4) & 1) * 8;

    uint4  ra[2][2];
    float4 rbf[4];
    uint4  rb[2][2];

    auto loadA = [&](int c0) {
        #pragma unroll
        for (int t = 0; t < 2; t++) {
            const __nv_bfloat16* Ap = t ? Al : Ah;
            #pragma unroll
            for (int i = 0; i < 2; i++) {
                int e = tid + i * 256;
                int o = e >> 2, c8 = (e & 3) * 8;
                ra[t][i] = *reinterpret_cast<const uint4*>(
                    Ap + (size_t)(o0 + o) * Cin + c0 + c8);
            }
        }
    };
    auto storeA = [&]() {
        #pragma unroll
        for (int t = 0; t < 2; t++)
            #pragma unroll
            for (int i = 0; i < 2; i++) {
                int e = tid + i * 256;
                int o = e >> 2, c8 = (e & 3) * 8;
                *reinterpret_cast<uint4*>(&sA[t][o][c8]) = ra[t][i];
            }
    };
    auto loadB = [&](int c0) {
        if (BMODE == 0) {
            #pragma unroll
            for (int i = 0; i < 4; i++) {
                int e = tid + i * 256;
                int k = e >> 5, p4 = (e & 31) * 4;
                rbf[i] = *reinterpret_cast<const float4*>(
                    Bf + bB + (size_t)(c0 + k) * Pn + p0 + p4);
            }
        } else {
            #pragma unroll
            for (int t = 0; t < 2; t++) {
                const __nv_bfloat16* Bp = t ? Bl : Bh;
                #pragma unroll
                for (int i = 0; i < 2; i++) {
                    int e = tid + i * 256;
                    int k = e >> 4, p8 = (e & 15) * 8;
                    rb[t][i] = *reinterpret_cast<const uint4*>(
                        Bp + bB + (size_t)(c0 + k) * Pn + p0 + p8);
                }
            }
        }
    };
    auto storeB = [&]() {
        if (BMODE == 0) {
            #pragma unroll
            for (int i = 0; i < 4; i++) {
                int e = tid + i * 256;
                int k = e >> 5, p4 = (e & 31) * 4;
                float4 x = rbf[i];
                __nv_bfloat16 h0, l0, h1, l1, h2, l2, h3, l3;
                split_bf16(x.x, h0, l0); split_bf16(x.y, h1, l1);
                split_bf16(x.z, h2, l2); split_bf16(x.w, h3, l3);
                *reinterpret_cast<__nv_bfloat162*>(&sB[0][k][p4])     = __halves2bfloat162(h0, h1);
                *reinterpret_cast<__nv_bfloat162*>(&sB[0][k][p4 + 2]) = __halves2bfloat162(h2, h3);
                *reinterpret_cast<__nv_bfloat162*>(&sB[1][k][p4])     = __halves2bfloat162(l0, l1);
                *reinterpret_cast<__nv_bfloat162*>(&sB[1][k][p4 + 2]) = __halves2bfloat162(l2, l3);
            }
        } else {
            #pragma unroll
            for (int t = 0; t < 2; t++)
                #pragma unroll
                for (int i = 0; i < 2; i++) {
                    int e = tid + i * 256;
                    int k = e >> 4, p8 = (e & 15) * 8;
                    *reinterpret_cast<uint4*>(&sB[t][k][p8]) = rb[t][i];
                }
        }
    };

    loadA(0); loadB(0);
    storeA(); storeB();
    __syncthreads();

    for (int c0 = 0; c0 < Cin; c0 += 32) {
        bool more = (c0 + 32 < Cin);
        if (more) { loadA(c0 + 32); loadB(c0 + 32); }

        #pragma unroll
        for (int kk = 0; kk < 32; kk += 16) {
            uint32_t afr[2][2][4];
            #pragma unroll
            for (int t2 = 0; t2 < 2; t2++)
                #pragma unroll
                for (int mf = 0; mf < 2; mf++)
                    ldsm_x4(afr[t2][mf],
                        smem_u32(&sA[t2][wm * 32 + mf * 16 + a_row][kk + a_colk]));
            uint32_t bfr[2][8][2];
            #pragma unroll
            for (int t2 = 0; t2 < 2; t2++)
                #pragma unroll
                for (int nf2 = 0; nf2 < 4; nf2++) {
                    uint32_t r[4];
                    ldsm_x4_t(r, smem_u32(
                        &sB[t2][kk + b_rowk][wn * 64 + nf2 * 16 + b_ncol]));
                    bfr[t2][2 * nf2][0] = r[0]; bfr[t2][2 * nf2][1] = r[1];
                    bfr[t2][2 * nf2 + 1][0] = r[2]; bfr[t2][2 * nf2 + 1][1] = r[3];
                }
            #pragma unroll
            for (int mf = 0; mf < 2; mf++)
                #pragma unroll
                for (int nf = 0; nf < 8; nf++) {
                    mma_bf16(d[mf][nf], afr[0][mf], bfr[0][nf]);
                    mma_bf16(d[mf][nf], afr[0][mf], bfr[1][nf]);
                    mma_bf16(d[mf][nf], afr[1][mf], bfr[0][nf]);
                }
        }
        __syncthreads();
        if (more) { storeA(); storeB(); __syncthreads(); }
    }

    #pragma unroll
    for (int mf = 0; mf < 2; mf++) {
        int r = o0 + wm * 32 + mf * 16 + (lane >> 2);
        float b0v = bias ? bias[r] : 0.0f;
        float b1v = bias ? bias[r + 8] : 0.0f;
        #pragma unroll
        for (int nf = 0; nf < 8; nf++) {
            int cb = p0 + wn * 64 + nf * 8 + (lane & 3) * 2;
            float v00 = d[mf][nf][0] + b0v, v01 = d[mf][nf][1] + b0v;
            float v10 = d[mf][nf][2] + b1v, v11 = d[mf][nf][3] + b1v;
            if (OMODE & 1) {
                *reinterpret_cast<float2*>(Yf + bY + (size_t)r * Pn + cb) =
                    make_float2(v00, v01);
                *reinterpret_cast<float2*>(Yf + bY + (size_t)(r + 8) * Pn + cb) =
                    make_float2(v10, v11);
            }
            if (OMODE & 2) {
                uint32_t h0, l0, h1, l1;
                split2(v00 * yscale, v01 * yscale, h0, l0);
                split2(v10 * yscale, v11 * yscale, h1, l1);
                *reinterpret_cast<uint32_t*>(Yh + bY + (size_t)r * Pn + cb)       = h0;
                *reinterpret_cast<uint32_t*>(Yl + bY + (size_t)r * Pn + cb)       = l0;
                *reinterpret_cast<uint32_t*>(Yh + bY + (size_t)(r + 8) * Pn + cb) = h1;
                *reinterpret_cast<uint32_t*>(Yl + bY + (size_t)(r + 8) * Pn + cb) = l1;
            }
        }
    }
}

// =====================================================================
// Fused K+V projection. grid (8, 4, 8), 256 threads.
// =====================================================================
__global__ void __launch_bounds__(256) gemm_kv()
{
    __shared__ __align__(16) __nv_bfloat16 sAk[2][64][SA_STRIDE];
    __shared__ __align__(16) __nv_bfloat16 sAv[2][64][SA_STRIDE];
    __shared__ __align__(16) __nv_bfloat16 sB[2][32][SB_STRIDE];
    const int b  = blockIdx.z;
    const int o0 = blockIdx.y * 64;
    const int p0 = blockIdx.x * 128;
    const size_t bB = (size_t)b * Cn * Pn;
    const int tid  = threadIdx.x;
    const int lane = tid & 31;
    const int wid  = tid >> 5;
    const int half = wid >> 2;
    const int w2   = wid & 3;
    const int wm   = w2 & 1;
    const int wn   = w2 >> 1;

    float d[2][8][4];
    #pragma unroll
    for (int mf = 0; mf < 2; mf++)
        #pragma unroll
        for (int nf = 0; nf < 8; nf++)
            #pragma unroll
            for (int i = 0; i < 4; i++) d[mf][nf][i] = 0.0f;

    const int a_row  = (lane & 7) + ((lane >> 3) & 1) * 8;
    const int a_colk = ((lane >> 4) & 1) * 8;
    const int b_rowk = (lane & 7) + ((lane >> 3) & 1) * 8;
    const int b_ncol = ((lane >> 4) & 1) * 8;

    const int ao = tid >> 2, ac8 = (tid & 3) * 8;
    uint4 ra[4];
    uint4 rb[2][2];
    auto loadA = [&](int c0) {
        size_t off = (size_t)(o0 + ao) * Cn + c0 + ac8;
        ra[0] = *reinterpret_cast<const uint4*>(w_kh + off);
        ra[1] = *reinterpret_cast<const uint4*>(w_kl + off);
        ra[2] = *reinterpret_cast<const uint4*>(w_vh + off);
        ra[3] = *reinterpret_cast<const uint4*>(w_vl + off);
    };
    auto storeA = [&]() {
        *reinterpret_cast<uint4*>(&sAk[0][ao][ac8]) = ra[0];
        *reinterpret_cast<uint4*>(&sAk[1][ao][ac8]) = ra[1];
        *reinterpret_cast<uint4*>(&sAv[0][ao][ac8]) = ra[2];
        *reinterpret_cast<uint4*>(&sAv[1][ao][ac8]) = ra[3];
    };
    auto loadB = [&](int c0) {
        #pragma unroll
        for (int t = 0; t < 2; t++) {
            const __nv_bfloat16* Bp = t ? g_sl : g_sh;
            #pragma unroll
            for (int i = 0; i < 2; i++) {
                int e = tid + i * 256;
                int k = e >> 4, p8 = (e & 15) * 8;
                rb[t][i] = *reinterpret_cast<const uint4*>(
                    Bp + bB + (size_t)(c0 + k) * Pn + p0 + p8);
            }
        }
    };
    auto storeB = [&]() {
        #pragma unroll
        for (int t = 0; t < 2; t++)
            #pragma unroll
            for (int i = 0; i < 2; i++) {
                int e = tid + i * 256;
                int k = e >> 4, p8 = (e & 15) * 8;
                *reinterpret_cast<uint4*>(&sB[t][k][p8]) = rb[t][i];
            }
    };

    loadA(0); loadB(0);
    storeA(); storeB();
    __syncthreads();

    for (int c0 = 0; c0 < Cn; c0 += 32) {
        bool more = (c0 + 32 < Cn);
        if (more) { loadA(c0 + 32); loadB(c0 + 32); }

        #pragma unroll
        for (int kk = 0; kk < 32; kk += 16) {
            uint32_t afr[2][2][4];
            #pragma unroll
            for (int t2 = 0; t2 < 2; t2++)
                #pragma unroll
                for (int mf = 0; mf < 2; mf++) {
                    const __nv_bfloat16* base = half
                        ? &sAv[t2][wm * 32 + mf * 16 + a_row][kk + a_colk]
                        : &sAk[t2][wm * 32 + mf * 16 + a_row][kk + a_colk];
                    ldsm_x4(afr[t2][mf], smem_u32(base));
                }
            uint32_t bfr[2][8][2];
            #pragma unroll
            for (int t2 = 0; t2 < 2; t2++)
                #pragma unroll
                for (int nf2 = 0; nf2 < 4; nf2++) {
                    uint32_t r[4];
                    ldsm_x4_t(r, smem_u32(
                        &sB[t2][kk + b_rowk][wn * 64 + nf2 * 16 + b_ncol]));
                    bfr[t2][2 * nf2][0] = r[0]; bfr[t2][2 * nf2][1] = r[1];
                    bfr[t2][2 * nf2 + 1][0] = r[2]; bfr[t2][2 * nf2 + 1][1] = r[3];
                }
            #pragma unroll
            for (int mf = 0; mf < 2; mf++)
                #pragma unroll
                for (int nf = 0; nf < 8; nf++) {
                    mma_bf16(d[mf][nf], afr[0][mf], bfr[0][nf]);
                    mma_bf16(d[mf][nf], afr[0][mf], bfr[1][nf]);
                    mma_bf16(d[mf][nf], afr[1][mf], bfr[0][nf]);
                }
        }
        __syncthreads();
        if (more) { storeA(); storeB(); __syncthreads(); }
    }

    __nv_bfloat16* Yh = (half ? g_vh : g_kh) + bB;
    __nv_bfloat16* Yl = (half ? g_vl : g_kl) + bB;
    #pragma unroll
    for (int mf = 0; mf < 2; mf++) {
        int r = o0 + wm * 32 + mf * 16 + (lane >> 2);
        #pragma unroll
        for (int nf = 0; nf < 8; nf++) {
            int cb = p0 + wn * 64 + nf * 8 + (lane & 3) * 2;
            uint32_t h0, l0, h1, l1;
            split2(d[mf][nf][0], d[mf][nf][1], h0, l0);
            split2(d[mf][nf][2], d[mf][nf][3], h1, l1);
            *reinterpret_cast<uint32_t*>(Yh + (size_t)r * Pn + cb)       = h0;
            *reinterpret_cast<uint32_t*>(Yl + (size_t)r * Pn + cb)       = l0;
            *reinterpret_cast<uint32_t*>(Yh + (size_t)(r + 8) * Pn + cb) = h1;
            *reinterpret_cast<uint32_t*>(Yl + (size_t)(r + 8) * Pn + cb) = l1;
        }
    }
}

// =====================================================================
// Conv GEMM with FUSED shift and FUSED offsets epilogue.
// CTA tile 128(o) x 64(p): one CTA owns ALL conv output channels for
// its 64 pixels -> compute offsets (Woff2 rows 0,1 contraction over
// relu(conv+boff1)) directly in the epilogue; h1 never hits memory.
// Full K=2304 (no splitK). grid (16, 8), 256 threads.
// =====================================================================
__global__ void __launch_bounds__(256) conv_mma4(
    const float* __restrict__ Woff2, const float* __restrict__ boff2,
    const float* __restrict__ boff1)
{
    __shared__ __align__(16) __nv_bfloat16 sA[2][128][SA_STRIDE];
    __shared__ __align__(16) __nv_bfloat16 sB[2][32][SC_STRIDE];
    __shared__ float red[4][2][64];
    const int b  = blockIdx.y;
    const int p0 = blockIdx.x * 64;
    const size_t bQ = (size_t)b * Cn * Pn;
    const int tid  = threadIdx.x;
    const int lane = tid & 31;
    const int wid  = tid >> 5;
    const int wm   = wid & 3;
    const int wn   = wid >> 2;

    float d[2][4][4];
    #pragma unroll
    for (int mf = 0; mf < 2; mf++)
        #pragma unroll
        for (int nf = 0; nf < 4; nf++)
            #pragma unroll
            for (int i = 0; i < 4; i++) d[mf][nf][i] = 0.0f;

    const int a_row  = (lane & 7) + ((lane >> 3) & 1) * 8;
    const int a_colk = ((lane >> 4) & 1) * 8;
    const int b_rowk = (lane & 7) + ((lane >> 3) & 1) * 8;
    const int b_ncol = ((lane >> 4) & 1) * 8;

    uint4 ra[2][2], rb[2];
    auto loadA = [&](int c0) {
        #pragma unroll
        for (int t = 0; t < 2; t++) {
            const __nv_bfloat16* Ap = t ? w_cl : w_ch;
            #pragma unroll
            for (int i = 0; i < 2; i++) {
                int e = tid + i * 256;
                int o = e >> 2, c8 = (e & 3) * 8;
                ra[t][i] = *reinterpret_cast<const uint4*>(
                    Ap + (size_t)o * 2304 + c0 + c8);
            }
        }
    };
    auto storeA = [&]() {
        #pragma unroll
        for (int t = 0; t < 2; t++)
            #pragma unroll
            for (int i = 0; i < 2; i++) {
                int e = tid + i * 256;
                int o = e >> 2, c8 = (e & 3) * 8;
                *reinterpret_cast<uint4*>(&sA[t][o][c8]) = ra[t][i];
            }
    };
    const int bk = tid >> 3, bp8 = (tid & 7) * 8;
    const int P  = p0 + bp8;
    const int x0 = P & 31;
    const int yb = P >> 5;
    auto loadB = [&](int c0) {
        int t  = c0 >> 8;
        int cc = (c0 & 255) + bk;
        int ty = t / 3;
        int dy = ty - 1;
        int dx = t - ty * 3 - 1;
        int ys = yb + dy;
        bool yok = (unsigned)ys < 32u;
        size_t rowoff = bQ + (size_t)cc * Pn + ys * 32;
        #pragma unroll
        for (int pl = 0; pl < 2; pl++) {
            const __nv_bfloat16* Qp = pl ? g_ql : g_qh;
            uint4 v = make_uint4(0u, 0u, 0u, 0u);
            if (yok) {
                uint4 w = *reinterpret_cast<const uint4*>(Qp + rowoff + x0);
                if (dx == 0) {
                    v = w;
                } else if (dx > 0) {
                    uint32_t extra = 0;
                    if (x0 != 24)
                        extra = *reinterpret_cast<const uint16_t*>(
                            Qp + rowoff + x0 + 8);
                    v.x = __funnelshift_r(w.x, w.y, 16);
                    v.y = __funnelshift_r(w.y, w.z, 16);
                    v.z = __funnelshift_r(w.z, w.w, 16);
                    v.w = (w.w >> 16) | (extra << 16);
                } else {
                    uint32_t extra = 0;
                    if (x0 != 0)
                        extra = *reinterpret_cast<const uint16_t*>(
                            Qp + rowoff + x0 - 1);
                    v.x = (w.x << 16) | extra;
                    v.y = __funnelshift_l(w.x, w.y, 16);
                    v.z = __funnelshift_l(w.y, w.z, 16);
                    v.w = __funnelshift_l(w.z, w.w, 16);
                }
            }
            rb[pl] = v;
        }
    };
    auto storeB = [&]() {
        *reinterpret_cast<uint4*>(&sB[0][bk][bp8]) = rb[0];
        *reinterpret_cast<uint4*>(&sB[1][bk][bp8]) = rb[1];
    };

    loadA(0); loadB(0);
    storeA(); storeB();
    __syncthreads();

    for (int c0 = 0; c0 < 2304; c0 += 32) {
        bool more = (c0 + 32 < 2304);
        if (more) { loadA(c0 + 32); loadB(c0 + 32); }

        #pragma unroll
        for (int kk = 0; kk < 32; kk += 16) {
            uint32_t afr[2][2][4];
            #pragma unroll
            for (int t2 = 0; t2 < 2; t2++)
                #pragma unroll
                for (int mf = 0; mf < 2; mf++)
                    ldsm_x4(afr[t2][mf],
                        smem_u32(&sA[t2][wm * 32 + mf * 16 + a_row][kk + a_colk]));
            uint32_t bfr[2][4][2];
            #pragma unroll
            for (int t2 = 0; t2 < 2; t2++)
                #pragma unroll
                for (int nf2 = 0; nf2 < 2; nf2++) {
                    uint32_t r[4];
                    ldsm_x4_t(r, smem_u32(
                        &sB[t2][kk + b_rowk][wn * 32 + nf2 * 16 + b_ncol]));
                    bfr[t2][2 * nf2][0] = r[0]; bfr[t2][2 * nf2][1] = r[1];
                    bfr[t2][2 * nf2 + 1][0] = r[2]; bfr[t2][2 * nf2 + 1][1] = r[3];
                }
            #pragma unroll
            for (int mf = 0; mf < 2; mf++)
                #pragma unroll
                for (int nf = 0; nf < 4; nf++) {
                    mma_bf16(d[mf][nf], afr[0][mf], bfr[0][nf]);
                    mma_bf16(d[mf][nf], afr[0][mf], bfr[1][nf]);
                    mma_bf16(d[mf][nf], afr[1][mf], bfr[0][nf]);
                }
        }
        __syncthreads();
        if (more) { storeA(); storeB(); __syncthreads(); }
    }

    // ---- fused offsets epilogue ----
    // channels owned by this thread: r0(mf) = wm*32+mf*16+(lane>>2), r1 = r0+8
    float w2x[2][2], w2y[2][2], bb[2][2];
    #pragma unroll
    for (int mf = 0; mf < 2; mf++) {
        int r = wm * 32 + mf * 16 + (lane >> 2);
        w2x[mf][0] = Woff2[r];        w2x[mf][1] = Woff2[r + 8];
        w2y[mf][0] = Woff2[128 + r];  w2y[mf][1] = Woff2[136 + r];
        bb[mf][0]  = boff1[r];        bb[mf][1]  = boff1[r + 8];
    }
    float ox[8], oy[8];
    #pragma unroll
    for (int i = 0; i < 8; i++) { ox[i] = 0.0f; oy[i] = 0.0f; }
    #pragma unroll
    for (int mf = 0; mf < 2; mf++)
        #pragma unroll
        for (int nf = 0; nf < 4; nf++) {
            float h0 = fmaxf(d[mf][nf][0] + bb[mf][0], 0.0f);
            float h1 = fmaxf(d[mf][nf][1] + bb[mf][0], 0.0f);
            float h2 = fmaxf(d[mf][nf][2] + bb[mf][1], 0.0f);
            float h3 = fmaxf(d[mf][nf][3] + bb[mf][1], 0.0f);
            ox[nf*2]   += w2x[mf][0] * h0 + w2x[mf][1] * h2;
            ox[nf*2+1] += w2x[mf][0] * h1 + w2x[mf][1] * h3;
            oy[nf*2]   += w2y[mf][0] * h0 + w2y[mf][1] * h2;
            oy[nf*2+1] += w2y[mf][0] * h1 + w2y[mf][1] * h3;
        }
    // reduce over channel-groups: lane bits 2..4 (lane&3 and pixels fixed)
    #pragma unroll
    for (int s = 4; s <= 16; s <<= 1)
        #pragma unroll
        for (int i = 0; i < 8; i++) {
            ox[i] += __shfl_xor_sync(0xffffffffu, ox[i], s);
            oy[i] += __shfl_xor_sync(0xffffffffu, oy[i], s);
        }
    if (lane < 4) {
        #pragma unroll
        for (int nf = 0; nf < 4; nf++)
            #pragma unroll
            for (int j = 0; j < 2; j++) {
                int px = wn * 32 + nf * 8 + lane * 2 + j;
                red[wm][0][px] = ox[nf*2+j];
                red[wm][1][px] = oy[nf*2+j];
            }
    }
    __syncthreads();
    if (tid < 64) {
        float sx = red[0][0][tid] + red[1][0][tid] + red[2][0][tid]
                 + red[3][0][tid] + boff2[0];
        float sy = red[0][1][tid] + red[1][1][tid] + red[2][1][tid]
                 + red[3][1][tid] + boff2[1];
        g_off[((size_t)b * 2 + 0) * Pn + p0 + tid] = sx * 0.1f;
        g_off[((size_t)b * 2 + 1) * Pn + p0 + tid] = sy * 0.1f;
    }
}

// =====================================================================
// Bilinear grid sample -> split planes. grid (4, 8, 16).
// =====================================================================
__global__ void __launch_bounds__(256) samp_kernel(const float* __restrict__ kv)
{
    const int b  = blockIdx.y;
    const int p  = blockIdx.x * 256 + threadIdx.x;
    const int c0 = blockIdx.z * 16;
    float ox = g_off[((size_t)b * 2 + 0) * Pn + p];
    float oy = g_off[((size_t)b * 2 + 1) * Pn + p];
    int px = p & 31, py = p >> 5;
    float gx = -1.0f + px * (2.0f / 31.0f);
    float gy = -1.0f + py * (2.0f / 31.0f);
    float x = (gx + ox + 1.0f) * 0.5f * 31.0f;
    float y = (gy + oy + 1.0f) * 0.5f * 31.0f;
    x = fminf(fmaxf(x, 0.0f), 31.0f);
    y = fminf(fmaxf(y, 0.0f), 31.0f);
    float x0f = floorf(x), y0f = floorf(y);
    float wx = x - x0f, wy = y - y0f;
    int x0 = (int)x0f, y0 = (int)y0f;
    int x1 = min(x0 + 1, 31), y1 = min(y0 + 1, 31);
    float w00 = (1.0f - wx) * (1.0f - wy);
    float w01 = wx * (1.0f - wy);
    float w10 = (1.0f - wx) * wy;
    float w11 = wx * wy;
    int i00 = (y0 << 5) + x0, i01 = (y0 << 5) + x1;
    int i10 = (y1 << 5) + x0, i11 = (y1 << 5) + x1;
    const float* kvb = kv + (size_t)b * Cn * Pn;
    const size_t ob = (size_t)b * Cn * Pn;
    #pragma unroll 4
    for (int c = c0; c < c0 + 16; c++) {
        const float* pl = kvb + (size_t)c * Pn;
        float v = w00 * pl[i00] + w01 * pl[i01] + w10 * pl[i10] + w11 * pl[i11];
        __nv_bfloat16 h, l;
        split_bf16(v, h, l);
        g_sh[ob + (size_t)c * Pn + p] = h;
        g_sl[ob + (size_t)c * Pn + p] = l;
    }
}

// =====================================================================
// Flash attention on tensor cores. grid (8, 64), 256 threads.
// =====================================================================
__global__ void __launch_bounds__(256) attn_mma()
{
    __shared__ __align__(16) __nv_bfloat16 sK[2][32][SB_STRIDE];
    __shared__ __align__(16) __nv_bfloat16 sV[2][32][SB_STRIDE];

    const int bh = blockIdx.y;
    const int b  = bh >> 3, h = bh & 7;
    const int p0 = blockIdx.x * 128;
    const int tid  = threadIdx.x;
    const int lane = tid & 31;
    const int wm   = tid >> 5;
    const size_t base = ((size_t)b * Cn + h * HD) * Pn;

    const int krow = (lane & 7) + ((lane >> 3) & 1) * 8;
    const int ncol = ((lane >> 4) & 1) * 8;

    #pragma unroll
    for (int t = 0; t < 2; t++) {
        const __nv_bfloat16* Qp = (t ? g_ql : g_qh) + base;
        #pragma unroll
        for (int i = 0; i < 2; i++) {
            int e = tid + i * 256;
            int d = e >> 4, p8 = (e & 15) * 8;
            uint4 v = *reinterpret_cast<const uint4*>(Qp + (size_t)d * Pn + p0 + p8);
            *reinterpret_cast<uint4*>(&sK[t][d][p8]) = v;
        }
    }
    __syncthreads();
    uint32_t aQ[2][2][4];
    #pragma unroll
    for (int t = 0; t < 2; t++)
        #pragma unroll
        for (int ks = 0; ks < 2; ks++) {
            uint32_t r[4];
            ldsm_x4_t(r, smem_u32(&sK[t][ks * 16 + krow][wm * 16 + ncol]));
            aQ[t][ks][0] = r[0]; aQ[t][ks][1] = r[2];
            aQ[t][ks][2] = r[1]; aQ[t][ks][3] = r[3];
        }

    float O[4][4];
    #pragma unroll
    for (int nf = 0; nf < 4; nf++)
        #pragma unroll
        for (int i = 0; i < 4; i++) O[nf][i] = 0.0f;
    float lsum0 = 0.0f, lsum1 = 0.0f;

    const int vrow = (lane & 7) + ((lane >> 3) & 1) * 8;
    const int vcol = ((lane >> 4) & 1) * 8;

    for (int kt = 0; kt < 8; kt++) {
        const int kv0 = kt * 128;
        __syncthreads();
        #pragma unroll
        for (int t = 0; t < 2; t++) {
            const __nv_bfloat16* Kp = (t ? g_kl : g_kh) + base;
            const __nv_bfloat16* Vp = (t ? g_vl : g_vh) + base;
            #pragma unroll
            for (int i = 0; i < 2; i++) {
                int e = tid + i * 256;
                int d = e >> 4, p8 = (e & 15) * 8;
                uint4 kv4 = *reinterpret_cast<const uint4*>(Kp + (size_t)d * Pn + kv0 + p8);
                *reinterpret_cast<uint4*>(&sK[t][d][p8]) = kv4;
                uint4 vv4 = *reinterpret_cast<const uint4*>(Vp + (size_t)d * Pn + kv0 + p8);
                *reinterpret_cast<uint4*>(&sV[t][d][p8]) = vv4;
            }
        }
        __syncthreads();

        float S[16][4];
        #pragma unroll
        for (int f = 0; f < 16; f++)
            #pragma unroll
            for (int i = 0; i < 4; i++) S[f][i] = 0.0f;

        #pragma unroll
        for (int nb = 0; nb < 8; nb++) {
            uint32_t bk[2][2][4];
            #pragma unroll
            for (int t = 0; t < 2; t++)
                #pragma unroll
                for (int ks = 0; ks < 2; ks++)
                    ldsm_x4_t(bk[t][ks],
                        smem_u32(&sK[t][ks * 16 + krow][nb * 16 + ncol]));
            #pragma unroll
            for (int half = 0; half < 2; half++) {
                float* s = S[nb * 2 + half];
                #pragma unroll
                for (int ks = 0; ks < 2; ks++) {
                    uint32_t bhi[2] = {bk[0][ks][2 * half], bk[0][ks][2 * half + 1]};
                    uint32_t blo[2] = {bk[1][ks][2 * half], bk[1][ks][2 * half + 1]};
                    mma_bf16(s, aQ[0][ks], bhi);
                    mma_bf16(s, aQ[1][ks], bhi);
                    mma_bf16(s, aQ[0][ks], blo);
                }
            }
        }
        #pragma unroll
        for (int f = 0; f < 16; f++) {
            S[f][0] = ex2f(S[f][0]); S[f][1] = ex2f(S[f][1]);
            S[f][2] = ex2f(S[f][2]); S[f][3] = ex2f(S[f][3]);
            lsum0 += S[f][0] + S[f][1];
            lsum1 += S[f][2] + S[f][3];
        }
        #pragma unroll
        for (int ks8 = 0; ks8 < 8; ks8++) {
            uint32_t ah[4], al[4];
            const float* f0 = S[2 * ks8];
            const float* f1 = S[2 * ks8 + 1];
            split2(f0[0], f0[1], ah[0], al[0]);
            split2(f0[2], f0[3], ah[1], al[1]);
            split2(f1[0], f1[1], ah[2], al[2]);
            split2(f1[2], f1[3], ah[3], al[3]);
            uint32_t bv[2][2][4];
            #pragma unroll
            for (int t = 0; t < 2; t++)
                #pragma unroll
                for (int db = 0; db < 2; db++)
                    ldsm_x4(bv[t][db],
                        smem_u32(&sV[t][db * 16 + vrow][ks8 * 16 + vcol]));
            #pragma unroll
            for (int nf = 0; nf < 4; nf++) {
                int db = nf >> 1, wh = nf & 1;
                uint32_t vhi[2] = {bv[0][db][wh], bv[0][db][wh + 2]};
                uint32_t vlo[2] = {bv[1][db][wh], bv[1][db][wh + 2]};
                mma_bf16(O[nf], ah, vhi);
                mma_bf16(O[nf], al, vhi);
                mma_bf16(O[nf], ah, vlo);
            }
        }
    }
    lsum0 += __shfl_xor_sync(0xffffffffu, lsum0, 1);
    lsum0 += __shfl_xor_sync(0xffffffffu, lsum0, 2);
    lsum1 += __shfl_xor_sync(0xffffffffu, lsum1, 1);
    lsum1 += __shfl_xor_sync(0xffffffffu, lsum1, 2);
    float inv0 = 1.0f / lsum0, inv1 = 1.0f / lsum1;
    int p = p0 + wm * 16 + (lane >> 2);
    #pragma unroll
    for (int nf = 0; nf < 4; nf++) {
        int d = nf * 8 + (lane & 3) * 2;
        float v0 = O[nf][0] * inv0, v1 = O[nf][1] * inv0;
        float v2 = O[nf][2] * inv1, v3 = O[nf][3] * inv1;
        __nv_bfloat16 hh, ll;
        split_bf16(v0, hh, ll);
        g_oh[base + (size_t)d * Pn + p] = hh;       g_ol[base + (size_t)d * Pn + p] = ll;
        split_bf16(v1, hh, ll);
        g_oh[base + (size_t)(d + 1) * Pn + p] = hh; g_ol[base + (size_t)(d + 1) * Pn + p] = ll;
        split_bf16(v2, hh, ll);
        g_oh[base + (size_t)d * Pn + p + 8] = hh;   g_ol[base + (size_t)d * Pn + p + 8] = ll;
        split_bf16(v3, hh, ll);
        g_oh[base + (size_t)(d + 1) * Pn + p + 8] = hh;
        g_ol[base + (size_t)(d + 1) * Pn + p + 8] = ll;
    }
}

// =====================================================================
extern "C" void kernel_launch(void* const* d_in, const int* in_sizes, int n_in,
                              void* d_out, int out_size)
{
    (void)in_sizes; (void)n_in; (void)out_size;
    const float* query_map = (const float*)d_in[0];
    const float* kv_map    = (const float*)d_in[1];
    const float* Wq        = (const float*)d_in[2];
    const float* Wk        = (const float*)d_in[3];
    const float* Wv        = (const float*)d_in[4];
    const float* Woff1     = (const float*)d_in[5];
    const float* boff1     = (const float*)d_in[6];
    const float* Woff2     = (const float*)d_in[7];
    const float* boff2     = (const float*)d_in[8];
    const float* Wout      = (const float*)d_in[9];
    const float* bout      = (const float*)d_in[10];
    float* out = (float*)d_out;

    const float kscale = 0.17677669529663687f * 1.4426950408889634f;

    __nv_bfloat16 *pqh, *pql, *poh, *pol;
    __nv_bfloat16 *pwqh, *pwql, *pwoh, *pwol;
    cudaGetSymbolAddress((void**)&pqh, g_qh);  cudaGetSymbolAddress((void**)&pql, g_ql);
    cudaGetSymbolAddress((void**)&poh, g_oh);  cudaGetSymbolAddress((void**)&pol, g_ol);
    cudaGetSymbolAddress((void**)&pwqh, w_qh); cudaGetSymbolAddress((void**)&pwql, w_ql);
    cudaGetSymbolAddress((void**)&pwoh, w_oh); cudaGetSymbolAddress((void**)&pwol, w_ol);

    // 0) one-shot weight prep (Wk pre-scaled; conv W reordered)
    split_all<<<2176, 256>>>(Wq, Wk, Wv, Wout, Woff1, kscale);
    // 1) q projection -> unscaled split planes (conv + attn)
    gemm_mma<0, 2><<<dim3(8, 2, 8), 256>>>(
        pwqh, pwql, query_map, nullptr, nullptr, nullptr,
        nullptr, pqh, pql, 1.0f, 256);
    // 2) conv GEMM (fused shift + fused offsets epilogue; h1 never stored)
    conv_mma4<<<dim3(16, 8), 256>>>(Woff2, boff2, boff1);
    // 3) bilinear sample -> split planes
    samp_kernel<<<dim3(4, 8, 16), 256>>>(kv_map);
    // 4) fused K+V projections (scale rides on K via Wk)
    gemm_kv<<<dim3(8, 4, 8), 256>>>();
    // 5) attention -> split planes
    attn_mma<<<dim3(8, 64), 256>>>();
    // 6) out = Wout @ attn_out + bout
    gemm_mma<1, 1><<<dim3(8, 2, 8), 256>>>(
        pwoh, pwol, nullptr, poh, pol, bout,
        out, nullptr, nullptr, 1.0f, 256);
}

// round 11
// speedup vs baseline: 1.1270x; 1.1270x over previous
#include <cuda_runtime.h>
#include <cuda_bf16.h>
#include <cstdint>

#define Bn 8
#define Cn 256
#define Pn 1024
#define HEADS 8
#define HD 32

// ---- fp32 scratch ----
__device__ float g_h1a[Bn*128*Pn];  // conv partial sums (splitK halves)
__device__ float g_h1b[Bn*128*Pn];
__device__ float g_off[Bn*2*Pn];

// ---- split-bf16 interchange planes (hi/lo) ----
__device__ __nv_bfloat16 g_qh[Bn*Cn*Pn], g_ql[Bn*Cn*Pn];   // unscaled q
__device__ __nv_bfloat16 g_kh[Bn*Cn*Pn], g_kl[Bn*Cn*Pn];   // scale folded via Wk
__device__ __nv_bfloat16 g_vh[Bn*Cn*Pn], g_vl[Bn*Cn*Pn];
__device__ __nv_bfloat16 g_sh[Bn*Cn*Pn], g_sl[Bn*Cn*Pn];   // sampled kv
__device__ __nv_bfloat16 g_oh[Bn*Cn*Pn], g_ol[Bn*Cn*Pn];   // attn out

// ---- pre-split weights ----
__device__ __nv_bfloat16 w_qh[Cn*Cn], w_ql[Cn*Cn];
__device__ __nv_bfloat16 w_kh[Cn*Cn], w_kl[Cn*Cn];         // pre-scaled by qscale
__device__ __nv_bfloat16 w_vh[Cn*Cn], w_vl[Cn*Cn];
__device__ __nv_bfloat16 w_oh[Cn*Cn], w_ol[Cn*Cn];
__device__ __nv_bfloat16 w_ch[128*2304], w_cl[128*2304];   // [o][t*256+c]

// ---- helpers ----
__device__ __forceinline__ uint32_t smem_u32(const void* p) {
    uint32_t a;
    asm("{ .reg .u64 t; cvta.to.shared.u64 t, %1; cvt.u32.u64 %0, t; }"
        : "=r"(a) : "l"(p));
    return a;
}
__device__ __forceinline__ void ldsm_x4(uint32_t r[4], uint32_t addr) {
    asm volatile("ldmatrix.sync.aligned.m8n8.x4.shared.b16 {%0,%1,%2,%3}, [%4];"
        : "=r"(r[0]), "=r"(r[1]), "=r"(r[2]), "=r"(r[3]) : "r"(addr));
}
__device__ __forceinline__ void ldsm_x4_t(uint32_t r[4], uint32_t addr) {
    asm volatile("ldmatrix.sync.aligned.m8n8.x4.trans.shared.b16 {%0,%1,%2,%3}, [%4];"
        : "=r"(r[0]), "=r"(r[1]), "=r"(r[2]), "=r"(r[3]) : "r"(addr));
}
__device__ __forceinline__ void mma_bf16(float d[4], const uint32_t a[4],
                                         const uint32_t b[2]) {
    asm volatile(
        "mma.sync.aligned.m16n8k16.row.col.f32.bf16.bf16.f32 "
        "{%0,%1,%2,%3}, {%4,%5,%6,%7}, {%8,%9}, {%0,%1,%2,%3};"
        : "+f"(d[0]), "+f"(d[1]), "+f"(d[2]), "+f"(d[3])
        : "r"(a[0]), "r"(a[1]), "r"(a[2]), "r"(a[3]), "r"(b[0]), "r"(b[1]));
}
__device__ __forceinline__ void split_bf16(float x, __nv_bfloat16& hi,
                                           __nv_bfloat16& lo) {
    hi = __float2bfloat16_rn(x);
    lo = __float2bfloat16_rn(x - __bfloat162float(hi));
}
__device__ __forceinline__ uint32_t pack_bf2(__nv_bfloat16 a, __nv_bfloat16 b) {
    __nv_bfloat162 t = __halves2bfloat162(a, b);
    return *reinterpret_cast<uint32_t*>(&t);
}
__device__ __forceinline__ void split2(float a, float b, uint32_t& hi, uint32_t& lo) {
    __nv_bfloat16 ha, la, hb, lb;
    split_bf16(a, ha, la);
    split_bf16(b, hb, lb);
    hi = pack_bf2(ha, hb);
    lo = pack_bf2(la, lb);
}
__device__ __forceinline__ float ex2f(float x) {
    float y; asm("ex2.approx.ftz.f32 %0, %1;" : "=f"(y) : "f"(x)); return y;
}

#define SA_STRIDE 40
#define SB_STRIDE 136
#define SC_STRIDE 72

// =====================================================================
// One-shot weight prep: split all weights; Wk scaled by kscale;
// conv W reordered [o][c*9+t] -> [o][t*256+c]. grid 2176 x 256.
// =====================================================================
__global__ void __launch_bounds__(256) split_all(
    const float* __restrict__ Wq, const float* __restrict__ Wk,
    const float* __restrict__ Wv, const float* __restrict__ Wout,
    const float* __restrict__ Woff1, float kscale)
{
    int idx = blockIdx.x * 256 + threadIdx.x;
    if (idx < 4 * 65536) {
        int w = idx >> 16, i = idx & 65535;
        const float* srcs[4] = {Wq, Wk, Wv, Wout};
        __nv_bfloat16* dh[4] = {w_qh, w_kh, w_vh, w_oh};
        __nv_bfloat16* dl[4] = {w_ql, w_kl, w_vl, w_ol};
        float v = srcs[w][i] * (w == 1 ? kscale : 1.0f);
        split_bf16(v, dh[w][i], dl[w][i]);
    } else {
        int i = idx - 4 * 65536;            // [0, 294912)
        int o = i / 2304;
        int r = i - o * 2304;
        int c = r / 9;
        int t = r - c * 9;
        int dst = o * 2304 + t * 256 + c;
        split_bf16(Woff1[i], w_ch[dst], w_cl[dst]);
    }
}

// =====================================================================
// GEMM via mma.sync bf16-split, software-pipelined k-loop.
// BMODE: 0 = fp32 B (split at store), 1 = split-plane B.
// OMODE bit0: fp32 out (+bias); bit1: split planes out (scaled).
// CTA tile 128x128, grid (8, O/128, 8), 256 threads.
// =====================================================================
template<int BMODE, int OMODE>
__global__ void __launch_bounds__(256) gemm_mma(
    const __nv_bfloat16* __restrict__ Ah, const __nv_bfloat16* __restrict__ Al,
    const float* __restrict__ Bf,
    const __nv_bfloat16* __restrict__ Bh, const __nv_bfloat16* __restrict__ Bl,
    const float* __restrict__ bias,
    float* __restrict__ Yf,
    __nv_bfloat16* __restrict__ Yh, __nv_bfloat16* __restrict__ Yl,
    float yscale, int Cin)
{
    __shared__ __align__(16) __nv_bfloat16 sA[2][128][SA_STRIDE];
    __shared__ __align__(16) __nv_bfloat16 sB[2][32][SB_STRIDE];
    const int b  = blockIdx.z;
    const int o0 = blockIdx.y * 128;
    const int p0 = blockIdx.x * 128;
    const int O  = gridDim.y * 128;
    const size_t bB = (size_t)b * Cin * Pn;
    const size_t bY = (size_t)b * O * Pn;
    const int tid  = threadIdx.x;
    const int lane = tid & 31;
    const int wid  = tid >> 5;
    const int wm   = wid & 3;
    const int wn   = wid >> 2;

    float d[2][8][4];
    #pragma unroll
    for (int mf = 0; mf < 2; mf++)
        #pragma unroll
        for (int nf = 0; nf < 8; nf++)
            #pragma unroll
            for (int i = 0; i < 4; i++) d[mf][nf][i] = 0.0f;

    const int a_row  = (lane & 7) + ((lane >> 3) & 1) * 8;
    const int a_colk = ((lane >> 4) & 1) * 8;
    const int b_rowk = (lane & 7) + ((lane >> 3) & 1) * 8;
    const int b_ncol = ((lane >> 4) & 1) * 8;

    uint4  ra[2][2];
    float4 rbf[4];
    uint4  rb[2][2];

    auto loadA = [&](int c0) {
        #pragma unroll
        for (int t = 0; t < 2; t++) {
            const __nv_bfloat16* Ap = t ? Al : Ah;
            #pragma unroll
            for (int i = 0; i < 2; i++) {
                int e = tid + i * 256;
                int o = e >> 2, c8 = (e & 3) * 8;
                ra[t][i] = *reinterpret_cast<const uint4*>(
                    Ap + (size_t)(o0 + o) * Cin + c0 + c8);
            }
        }
    };
    auto storeA = [&]() {
        #pragma unroll
        for (int t = 0; t < 2; t++)
            #pragma unroll
            for (int i = 0; i < 2; i++) {
                int e = tid + i * 256;
                int o = e >> 2, c8 = (e & 3) * 8;
                *reinterpret_cast<uint4*>(&sA[t][o][c8]) = ra[t][i];
            }
    };
    auto loadB = [&](int c0) {
        if (BMODE == 0) {
            #pragma unroll
            for (int i = 0; i < 4; i++) {
                int e = tid + i * 256;
                int k = e >> 5, p4 = (e & 31) * 4;
                rbf[i] = *reinterpret_cast<const float4*>(
                    Bf + bB + (size_t)(c0 + k) * Pn + p0 + p4);
            }
        } else {
            #pragma unroll
            for (int t = 0; t < 2; t++) {
                const __nv_bfloat16* Bp = t ? Bl : Bh;
                #pragma unroll
                for (int i = 0; i < 2; i++) {
                    int e = tid + i * 256;
                    int k = e >> 4, p8 = (e & 15) * 8;
                    rb[t][i] = *reinterpret_cast<const uint4*>(
                        Bp + bB + (size_t)(c0 + k) * Pn + p0 + p8);
                }
            }
        }
    };
    auto storeB = [&]() {
        if (BMODE == 0) {
            #pragma unroll
            for (int i = 0; i < 4; i++) {
                int e = tid + i * 256;
                int k = e >> 5, p4 = (e & 31) * 4;
                float4 x = rbf[i];
                __nv_bfloat16 h0, l0, h1, l1, h2, l2, h3, l3;
                split_bf16(x.x, h0, l0); split_bf16(x.y, h1, l1);
                split_bf16(x.z, h2, l2); split_bf16(x.w, h3, l3);
                *reinterpret_cast<__nv_bfloat162*>(&sB[0][k][p4])     = __halves2bfloat162(h0, h1);
                *reinterpret_cast<__nv_bfloat162*>(&sB[0][k][p4 + 2]) = __halves2bfloat162(h2, h3);
                *reinterpret_cast<__nv_bfloat162*>(&sB[1][k][p4])     = __halves2bfloat162(l0, l1);
                *reinterpret_cast<__nv_bfloat162*>(&sB[1][k][p4 + 2]) = __halves2bfloat162(l2, l3);
            }
        } else {
            #pragma unroll
            for (int t = 0; t < 2; t++)
                #pragma unroll
                for (int i = 0; i < 2; i++) {
                    int e = tid + i * 256;
                    int k = e >> 4, p8 = (e & 15) * 8;
                    *reinterpret_cast<uint4*>(&sB[t][k][p8]) = rb[t][i];
                }
        }
    };

    loadA(0); loadB(0);
    storeA(); storeB();
    __syncthreads();

    for (int c0 = 0; c0 < Cin; c0 += 32) {
        bool more = (c0 + 32 < Cin);
        if (more) { loadA(c0 + 32); loadB(c0 + 32); }

        #pragma unroll
        for (int kk = 0; kk < 32; kk += 16) {
            uint32_t afr[2][2][4];
            #pragma unroll
            for (int t2 = 0; t2 < 2; t2++)
                #pragma unroll
                for (int mf = 0; mf < 2; mf++)
                    ldsm_x4(afr[t2][mf],
                        smem_u32(&sA[t2][wm * 32 + mf * 16 + a_row][kk + a_colk]));
            uint32_t bfr[2][8][2];
            #pragma unroll
            for (int t2 = 0; t2 < 2; t2++)
                #pragma unroll
                for (int nf2 = 0; nf2 < 4; nf2++) {
                    uint32_t r[4];
                    ldsm_x4_t(r, smem_u32(
                        &sB[t2][kk + b_rowk][wn * 64 + nf2 * 16 + b_ncol]));
                    bfr[t2][2 * nf2][0] = r[0]; bfr[t2][2 * nf2][1] = r[1];
                    bfr[t2][2 * nf2 + 1][0] = r[2]; bfr[t2][2 * nf2 + 1][1] = r[3];
                }
            #pragma unroll
            for (int mf = 0; mf < 2; mf++)
                #pragma unroll
                for (int nf = 0; nf < 8; nf++) {
                    mma_bf16(d[mf][nf], afr[0][mf], bfr[0][nf]);
                    mma_bf16(d[mf][nf], afr[0][mf], bfr[1][nf]);
                    mma_bf16(d[mf][nf], afr[1][mf], bfr[0][nf]);
                }
        }
        __syncthreads();
        if (more) { storeA(); storeB(); __syncthreads(); }
    }

    #pragma unroll
    for (int mf = 0; mf < 2; mf++) {
        int r = o0 + wm * 32 + mf * 16 + (lane >> 2);
        float b0v = bias ? bias[r] : 0.0f;
        float b1v = bias ? bias[r + 8] : 0.0f;
        #pragma unroll
        for (int nf = 0; nf < 8; nf++) {
            int cb = p0 + wn * 64 + nf * 8 + (lane & 3) * 2;
            float v00 = d[mf][nf][0] + b0v, v01 = d[mf][nf][1] + b0v;
            float v10 = d[mf][nf][2] + b1v, v11 = d[mf][nf][3] + b1v;
            if (OMODE & 1) {
                *reinterpret_cast<float2*>(Yf + bY + (size_t)r * Pn + cb) =
                    make_float2(v00, v01);
                *reinterpret_cast<float2*>(Yf + bY + (size_t)(r + 8) * Pn + cb) =
                    make_float2(v10, v11);
            }
            if (OMODE & 2) {
                uint32_t h0, l0, h1, l1;
                split2(v00 * yscale, v01 * yscale, h0, l0);
                split2(v10 * yscale, v11 * yscale, h1, l1);
                *reinterpret_cast<uint32_t*>(Yh + bY + (size_t)r * Pn + cb)       = h0;
                *reinterpret_cast<uint32_t*>(Yl + bY + (size_t)r * Pn + cb)       = l0;
                *reinterpret_cast<uint32_t*>(Yh + bY + (size_t)(r + 8) * Pn + cb) = h1;
                *reinterpret_cast<uint32_t*>(Yl + bY + (size_t)(r + 8) * Pn + cb) = l1;
            }
        }
    }
}

// =====================================================================
// Fused K+V projection. grid (8, 4, 8), 256 threads.
// =====================================================================
__global__ void __launch_bounds__(256) gemm_kv()
{
    __shared__ __align__(16) __nv_bfloat16 sAk[2][64][SA_STRIDE];
    __shared__ __align__(16) __nv_bfloat16 sAv[2][64][SA_STRIDE];
    __shared__ __align__(16) __nv_bfloat16 sB[2][32][SB_STRIDE];
    const int b  = blockIdx.z;
    const int o0 = blockIdx.y * 64;
    const int p0 = blockIdx.x * 128;
    const size_t bB = (size_t)b * Cn * Pn;
    const int tid  = threadIdx.x;
    const int lane = tid & 31;
    const int wid  = tid >> 5;
    const int half = wid >> 2;
    const int w2   = wid & 3;
    const int wm   = w2 & 1;
    const int wn   = w2 >> 1;

    float d[2][8][4];
    #pragma unroll
    for (int mf = 0; mf < 2; mf++)
        #pragma unroll
        for (int nf = 0; nf < 8; nf++)
            #pragma unroll
            for (int i = 0; i < 4; i++) d[mf][nf][i] = 0.0f;

    const int a_row  = (lane & 7) + ((lane >> 3) & 1) * 8;
    const int a_colk = ((lane >> 4) & 1) * 8;
    const int b_rowk = (lane & 7) + ((lane >> 3) & 1) * 8;
    const int b_ncol = ((lane >> 4) & 1) * 8;

    const int ao = tid >> 2, ac8 = (tid & 3) * 8;
    uint4 ra[4];
    uint4 rb[2][2];
    auto loadA = [&](int c0) {
        size_t off = (size_t)(o0 + ao) * Cn + c0 + ac8;
        ra[0] = *reinterpret_cast<const uint4*>(w_kh + off);
        ra[1] = *reinterpret_cast<const uint4*>(w_kl + off);
        ra[2] = *reinterpret_cast<const uint4*>(w_vh + off);
        ra[3] = *reinterpret_cast<const uint4*>(w_vl + off);
    };
    auto storeA = [&]() {
        *reinterpret_cast<uint4*>(&sAk[0][ao][ac8]) = ra[0];
        *reinterpret_cast<uint4*>(&sAk[1][ao][ac8]) = ra[1];
        *reinterpret_cast<uint4*>(&sAv[0][ao][ac8]) = ra[2];
        *reinterpret_cast<uint4*>(&sAv[1][ao][ac8]) = ra[3];
    };
    auto loadB = [&](int c0) {
        #pragma unroll
        for (int t = 0; t < 2; t++) {
            const __nv_bfloat16* Bp = t ? g_sl : g_sh;
            #pragma unroll
            for (int i = 0; i < 2; i++) {
                int e = tid + i * 256;
                int k = e >> 4, p8 = (e & 15) * 8;
                rb[t][i] = *reinterpret_cast<const uint4*>(
                    Bp + bB + (size_t)(c0 + k) * Pn + p0 + p8);
            }
        }
    };
    auto storeB = [&]() {
        #pragma unroll
        for (int t = 0; t < 2; t++)
            #pragma unroll
            for (int i = 0; i < 2; i++) {
                int e = tid + i * 256;
                int k = e >> 4, p8 = (e & 15) * 8;
                *reinterpret_cast<uint4*>(&sB[t][k][p8]) = rb[t][i];
            }
    };

    loadA(0); loadB(0);
    storeA(); storeB();
    __syncthreads();

    for (int c0 = 0; c0 < Cn; c0 += 32) {
        bool more = (c0 + 32 < Cn);
        if (more) { loadA(c0 + 32); loadB(c0 + 32); }

        #pragma unroll
        for (int kk = 0; kk < 32; kk += 16) {
            uint32_t afr[2][2][4];
            #pragma unroll
            for (int t2 = 0; t2 < 2; t2++)
                #pragma unroll
                for (int mf = 0; mf < 2; mf++) {
                    const __nv_bfloat16* base = half
                        ? &sAv[t2][wm * 32 + mf * 16 + a_row][kk + a_colk]
                        : &sAk[t2][wm * 32 + mf * 16 + a_row][kk + a_colk];
                    ldsm_x4(afr[t2][mf], smem_u32(base));
                }
            uint32_t bfr[2][8][2];
            #pragma unroll
            for (int t2 = 0; t2 < 2; t2++)
                #pragma unroll
                for (int nf2 = 0; nf2 < 4; nf2++) {
                    uint32_t r[4];
                    ldsm_x4_t(r, smem_u32(
                        &sB[t2][kk + b_rowk][wn * 64 + nf2 * 16 + b_ncol]));
                    bfr[t2][2 * nf2][0] = r[0]; bfr[t2][2 * nf2][1] = r[1];
                    bfr[t2][2 * nf2 + 1][0] = r[2]; bfr[t2][2 * nf2 + 1][1] = r[3];
                }
            #pragma unroll
            for (int mf = 0; mf < 2; mf++)
                #pragma unroll
                for (int nf = 0; nf < 8; nf++) {
                    mma_bf16(d[mf][nf], afr[0][mf], bfr[0][nf]);
                    mma_bf16(d[mf][nf], afr[0][mf], bfr[1][nf]);
                    mma_bf16(d[mf][nf], afr[1][mf], bfr[0][nf]);
                }
        }
        __syncthreads();
        if (more) { storeA(); storeB(); __syncthreads(); }
    }

    __nv_bfloat16* Yh = (half ? g_vh : g_kh) + bB;
    __nv_bfloat16* Yl = (half ? g_vl : g_kl) + bB;
    #pragma unroll
    for (int mf = 0; mf < 2; mf++) {
        int r = o0 + wm * 32 + mf * 16 + (lane >> 2);
        #pragma unroll
        for (int nf = 0; nf < 8; nf++) {
            int cb = p0 + wn * 64 + nf * 8 + (lane & 3) * 2;
            uint32_t h0, l0, h1, l1;
            split2(d[mf][nf][0], d[mf][nf][1], h0, l0);
            split2(d[mf][nf][2], d[mf][nf][3], h1, l1);
            *reinterpret_cast<uint32_t*>(Yh + (size_t)r * Pn + cb)       = h0;
            *reinterpret_cast<uint32_t*>(Yl + (size_t)r * Pn + cb)       = l0;
            *reinterpret_cast<uint32_t*>(Yh + (size_t)(r + 8) * Pn + cb) = h1;
            *reinterpret_cast<uint32_t*>(Yl + (size_t)(r + 8) * Pn + cb) = l1;
        }
    }
}

// =====================================================================
// Conv as GEMM with FUSED shift (round-8/9 version).
// CTA tile 128(o) x 64(p), splitK=2. grid (16, 2, 8), 256 threads.
// =====================================================================
__global__ void __launch_bounds__(256) conv_mma3()
{
    __shared__ __align__(16) __nv_bfloat16 sA[2][128][SA_STRIDE];
    __shared__ __align__(16) __nv_bfloat16 sB[2][32][SC_STRIDE];
    const int b  = blockIdx.z;
    const int ks = blockIdx.y;
    const int p0 = blockIdx.x * 64;
    float* Yb = (ks ? g_h1b : g_h1a) + (size_t)b * 128 * Pn;
    const size_t bQ = (size_t)b * Cn * Pn;
    const int tid  = threadIdx.x;
    const int lane = tid & 31;
    const int wid  = tid >> 5;
    const int wm   = wid & 3;
    const int wn   = wid >> 2;

    float d[2][4][4];
    #pragma unroll
    for (int mf = 0; mf < 2; mf++)
        #pragma unroll
        for (int nf = 0; nf < 4; nf++)
            #pragma unroll
            for (int i = 0; i < 4; i++) d[mf][nf][i] = 0.0f;

    const int a_row  = (lane & 7) + ((lane >> 3) & 1) * 8;
    const int a_colk = ((lane >> 4) & 1) * 8;
    const int b_rowk = (lane & 7) + ((lane >> 3) & 1) * 8;
    const int b_ncol = ((lane >> 4) & 1) * 8;

    uint4 ra[2][2], rb[2];
    auto loadA = [&](int c0) {
        #pragma unroll
        for (int t = 0; t < 2; t++) {
            const __nv_bfloat16* Ap = t ? w_cl : w_ch;
            #pragma unroll
            for (int i = 0; i < 2; i++) {
                int e = tid + i * 256;
                int o = e >> 2, c8 = (e & 3) * 8;
                ra[t][i] = *reinterpret_cast<const uint4*>(
                    Ap + (size_t)o * 2304 + c0 + c8);
            }
        }
    };
    auto storeA = [&]() {
        #pragma unroll
        for (int t = 0; t < 2; t++)
            #pragma unroll
            for (int i = 0; i < 2; i++) {
                int e = tid + i * 256;
                int o = e >> 2, c8 = (e & 3) * 8;
                *reinterpret_cast<uint4*>(&sA[t][o][c8]) = ra[t][i];
            }
    };
    const int bk = tid >> 3, bp8 = (tid & 7) * 8;
    const int P  = p0 + bp8;
    const int x0 = P & 31;
    const int yb = P >> 5;
    auto loadB = [&](int c0) {
        int t  = c0 >> 8;
        int cc = (c0 & 255) + bk;
        int ty = t / 3;
        int dy = ty - 1;
        int dx = t - ty * 3 - 1;
        int ys = yb + dy;
        bool yok = (unsigned)ys < 32u;
        size_t rowoff = bQ + (size_t)cc * Pn + ys * 32;
        #pragma unroll
        for (int pl = 0; pl < 2; pl++) {
            const __nv_bfloat16* Qp = pl ? g_ql : g_qh;
            uint4 v = make_uint4(0u, 0u, 0u, 0u);
            if (yok) {
                uint4 w = *reinterpret_cast<const uint4*>(Qp + rowoff + x0);
                if (dx == 0) {
                    v = w;
                } else if (dx > 0) {
                    uint32_t extra = 0;
                    if (x0 != 24)
                        extra = *reinterpret_cast<const uint16_t*>(
                            Qp + rowoff + x0 + 8);
                    v.x = __funnelshift_r(w.x, w.y, 16);
                    v.y = __funnelshift_r(w.y, w.z, 16);
                    v.z = __funnelshift_r(w.z, w.w, 16);
                    v.w = (w.w >> 16) | (extra << 16);
                } else {
                    uint32_t extra = 0;
                    if (x0 != 0)
                        extra = *reinterpret_cast<const uint16_t*>(
                            Qp + rowoff + x0 - 1);
                    v.x = (w.x << 16) | extra;
                    v.y = __funnelshift_l(w.x, w.y, 16);
                    v.z = __funnelshift_l(w.y, w.z, 16);
                    v.w = __funnelshift_l(w.z, w.w, 16);
                }
            }
            rb[pl] = v;
        }
    };
    auto storeB = [&]() {
        *reinterpret_cast<uint4*>(&sB[0][bk][bp8]) = rb[0];
        *reinterpret_cast<uint4*>(&sB[1][bk][bp8]) = rb[1];
    };

    const int cbeg = ks * 1152, cend = cbeg + 1152;
    loadA(cbeg); loadB(cbeg);
    storeA(); storeB();
    __syncthreads();

    for (int c0 = cbeg; c0 < cend; c0 += 32) {
        bool more = (c0 + 32 < cend);
        if (more) { loadA(c0 + 32); loadB(c0 + 32); }

        #pragma unroll
        for (int kk = 0; kk < 32; kk += 16) {
            uint32_t afr[2][2][4];
            #pragma unroll
            for (int t2 = 0; t2 < 2; t2++)
                #pragma unroll
                for (int mf = 0; mf < 2; mf++)
                    ldsm_x4(afr[t2][mf],
                        smem_u32(&sA[t2][wm * 32 + mf * 16 + a_row][kk + a_colk]));
            uint32_t bfr[2][4][2];
            #pragma unroll
            for (int t2 = 0; t2 < 2; t2++)
                #pragma unroll
                for (int nf2 = 0; nf2 < 2; nf2++) {
                    uint32_t r[4];
                    ldsm_x4_t(r, smem_u32(
                        &sB[t2][kk + b_rowk][wn * 32 + nf2 * 16 + b_ncol]));
                    bfr[t2][2 * nf2][0] = r[0]; bfr[t2][2 * nf2][1] = r[1];
                    bfr[t2][2 * nf2 + 1][0] = r[2]; bfr[t2][2 * nf2 + 1][1] = r[3];
                }
            #pragma unroll
            for (int mf = 0; mf < 2; mf++)
                #pragma unroll
                for (int nf = 0; nf < 4; nf++) {
                    mma_bf16(d[mf][nf], afr[0][mf], bfr[0][nf]);
                    mma_bf16(d[mf][nf], afr[0][mf], bfr[1][nf]);
                    mma_bf16(d[mf][nf], afr[1][mf], bfr[0][nf]);
                }
        }
        __syncthreads();
        if (more) { storeA(); storeB(); __syncthreads(); }
    }
    #pragma unroll
    for (int mf = 0; mf < 2; mf++) {
        int r = wm * 32 + mf * 16 + (lane >> 2);
        #pragma unroll
        for (int nf = 0; nf < 4; nf++) {
            int cb = p0 + wn * 32 + nf * 8 + (lane & 3) * 2;
            *reinterpret_cast<float2*>(Yb + (size_t)r * Pn + cb) =
                make_float2(d[mf][nf][0], d[mf][nf][1]);
            *reinterpret_cast<float2*>(Yb + (size_t)(r + 8) * Pn + cb) =
                make_float2(d[mf][nf][2], d[mf][nf][3]);
        }
    }
}

// =====================================================================
// Offsets, parallelized (round-9 version). grid (16, 8), 256 threads.
// =====================================================================
__global__ void __launch_bounds__(256) offs_kernel2(
    const float* __restrict__ Woff2, const float* __restrict__ boff2,
    const float* __restrict__ boff1)
{
    __shared__ float red[2][4][64];
    const int b   = blockIdx.y;
    const int px  = threadIdx.x & 63;
    const int seg = threadIdx.x >> 6;
    const int p   = blockIdx.x * 64 + px;
    const float* h1a = g_h1a + (size_t)b * 128 * Pn;
    const float* h1b = g_h1b + (size_t)b * 128 * Pn;
    const int c0 = seg * 32;
    float ox0 = 0.0f, oy0 = 0.0f, ox1 = 0.0f, oy1 = 0.0f;
    #pragma unroll 8
    for (int c = c0; c < c0 + 32; c += 2) {
        size_t i0 = (size_t)c * Pn + p;
        size_t i1 = (size_t)(c + 1) * Pn + p;
        float ha0 = h1a[i0], hb0 = h1b[i0];
        float ha1 = h1a[i1], hb1 = h1b[i1];
        float h0 = fmaxf(ha0 + hb0 + boff1[c], 0.0f);
        float h1 = fmaxf(ha1 + hb1 + boff1[c + 1], 0.0f);
        ox0 += Woff2[c] * h0;       oy0 += Woff2[128 + c] * h0;
        ox1 += Woff2[c + 1] * h1;   oy1 += Woff2[128 + c + 1] * h1;
    }
    red[0][seg][px] = ox0 + ox1;
    red[1][seg][px] = oy0 + oy1;
    __syncthreads();
    if (seg == 0) {
        float ox = boff2[0] + red[0][0][px] + red[0][1][px]
                 + red[0][2][px] + red[0][3][px];
        float oy = boff2[1] + red[1][0][px] + red[1][1][px]
                 + red[1][2][px] + red[1][3][px];
        g_off[((size_t)b * 2 + 0) * Pn + p] = ox * 0.1f;
        g_off[((size_t)b * 2 + 1) * Pn + p] = oy * 0.1f;
    }
}

// =====================================================================
// Bilinear grid sample -> split planes. grid (4, 8, 16).
// =====================================================================
__global__ void __launch_bounds__(256) samp_kernel(const float* __restrict__ kv)
{
    const int b  = blockIdx.y;
    const int p  = blockIdx.x * 256 + threadIdx.x;
    const int c0 = blockIdx.z * 16;
    float ox = g_off[((size_t)b * 2 + 0) * Pn + p];
    float oy = g_off[((size_t)b * 2 + 1) * Pn + p];
    int px = p & 31, py = p >> 5;
    float gx = -1.0f + px * (2.0f / 31.0f);
    float gy = -1.0f + py * (2.0f / 31.0f);
    float x = (gx + ox + 1.0f) * 0.5f * 31.0f;
    float y = (gy + oy + 1.0f) * 0.5f * 31.0f;
    x = fminf(fmaxf(x, 0.0f), 31.0f);
    y = fminf(fmaxf(y, 0.0f), 31.0f);
    float x0f = floorf(x), y0f = floorf(y);
    float wx = x - x0f, wy = y - y0f;
    int x0 = (int)x0f, y0 = (int)y0f;
    int x1 = min(x0 + 1, 31), y1 = min(y0 + 1, 31);
    float w00 = (1.0f - wx) * (1.0f - wy);
    float w01 = wx * (1.0f - wy);
    float w10 = (1.0f - wx) * wy;
    float w11 = wx * wy;
    int i00 = (y0 << 5) + x0, i01 = (y0 << 5) + x1;
    int i10 = (y1 << 5) + x0, i11 = (y1 << 5) + x1;
    const float* kvb = kv + (size_t)b * Cn * Pn;
    const size_t ob = (size_t)b * Cn * Pn;
    #pragma unroll 4
    for (int c = c0; c < c0 + 16; c++) {
        const float* pl = kvb + (size_t)c * Pn;
        float v = w00 * pl[i00] + w01 * pl[i01] + w10 * pl[i10] + w11 * pl[i11];
        __nv_bfloat16 h, l;
        split_bf16(v, h, l);
        g_sh[ob + (size_t)c * Pn + p] = h;
        g_sl[ob + (size_t)c * Pn + p] = l;
    }
}

// =====================================================================
// Flash attention on tensor cores, software-pipelined KV loads:
// prefetch tile kt+1 into registers during compute of kt.
// grid (8, 64), 256 threads.
// =====================================================================
__global__ void __launch_bounds__(256) attn_mma()
{
    __shared__ __align__(16) __nv_bfloat16 sK[2][32][SB_STRIDE];
    __shared__ __align__(16) __nv_bfloat16 sV[2][32][SB_STRIDE];

    const int bh = blockIdx.y;
    const int b  = bh >> 3, h = bh & 7;
    const int p0 = blockIdx.x * 128;
    const int tid  = threadIdx.x;
    const int lane = tid & 31;
    const int wm   = tid >> 5;
    const size_t base = ((size_t)b * Cn + h * HD) * Pn;

    const int krow = (lane & 7) + ((lane >> 3) & 1) * 8;
    const int ncol = ((lane >> 4) & 1) * 8;

    // ---- stage Q planes into sK, extract A-frags ----
    #pragma unroll
    for (int t = 0; t < 2; t++) {
        const __nv_bfloat16* Qp = (t ? g_ql : g_qh) + base;
        #pragma unroll
        for (int i = 0; i < 2; i++) {
            int e = tid + i * 256;
            int d = e >> 4, p8 = (e & 15) * 8;
            uint4 v = *reinterpret_cast<const uint4*>(Qp + (size_t)d * Pn + p0 + p8);
            *reinterpret_cast<uint4*>(&sK[t][d][p8]) = v;
        }
    }
    __syncthreads();
    uint32_t aQ[2][2][4];
    #pragma unroll
    for (int t = 0; t < 2; t++)
        #pragma unroll
        for (int ks = 0; ks < 2; ks++) {
            uint32_t r[4];
            ldsm_x4_t(r, smem_u32(&sK[t][ks * 16 + krow][wm * 16 + ncol]));
            aQ[t][ks][0] = r[0]; aQ[t][ks][1] = r[2];
            aQ[t][ks][2] = r[1]; aQ[t][ks][3] = r[3];
        }

    float O[4][4];
    #pragma unroll
    for (int nf = 0; nf < 4; nf++)
        #pragma unroll
        for (int i = 0; i < 4; i++) O[nf][i] = 0.0f;
    float lsum0 = 0.0f, lsum1 = 0.0f;

    const int vrow = (lane & 7) + ((lane >> 3) & 1) * 8;
    const int vcol = ((lane >> 4) & 1) * 8;

    // pipeline registers: per-thread 2 rows (d, d+16), K and V, 2 planes
    const int ld_d  = tid >> 4;            // 0..15
    const int ld_p8 = (tid & 15) * 8;
    uint4 rk[2][2], rv[2][2];
    auto loadKV = [&](int kv0) {
        #pragma unroll
        for (int t = 0; t < 2; t++) {
            const __nv_bfloat16* Kp = (t ? g_kl : g_kh) + base;
            const __nv_bfloat16* Vp = (t ? g_vl : g_vh) + base;
            #pragma unroll
            for (int i = 0; i < 2; i++) {
                int d = ld_d + i * 16;
                rk[t][i] = *reinterpret_cast<const uint4*>(
                    Kp + (size_t)d * Pn + kv0 + ld_p8);
                rv[t][i] = *reinterpret_cast<const uint4*>(
                    Vp + (size_t)d * Pn + kv0 + ld_p8);
            }
        }
    };
    auto storeKV = [&]() {
        #pragma unroll
        for (int t = 0; t < 2; t++)
            #pragma unroll
            for (int i = 0; i < 2; i++) {
                int d = ld_d + i * 16;
                *reinterpret_cast<uint4*>(&sK[t][d][ld_p8]) = rk[t][i];
                *reinterpret_cast<uint4*>(&sV[t][d][ld_p8]) = rv[t][i];
            }
    };

    loadKV(0);

    for (int kt = 0; kt < 8; kt++) {
        __syncthreads();            // Q-frag extraction / prior compute done
        storeKV();
        __syncthreads();
        if (kt + 1 < 8) loadKV((kt + 1) * 128);

        float S[16][4];
        #pragma unroll
        for (int f = 0; f < 16; f++)
            #pragma unroll
            for (int i = 0; i < 4; i++) S[f][i] = 0.0f;

        #pragma unroll
        for (int nb = 0; nb < 8; nb++) {
            uint32_t bk[2][2][4];
            #pragma unroll
            for (int t = 0; t < 2; t++)
                #pragma unroll
                for (int ks = 0; ks < 2; ks++)
                    ldsm_x4_t(bk[t][ks],
                        smem_u32(&sK[t][ks * 16 + krow][nb * 16 + ncol]));
            #pragma unroll
            for (int half = 0; half < 2; half++) {
                float* s = S[nb * 2 + half];
                #pragma unroll
                for (int ks = 0; ks < 2; ks++) {
                    uint32_t bhi[2] = {bk[0][ks][2 * half], bk[0][ks][2 * half + 1]};
                    uint32_t blo[2] = {bk[1][ks][2 * half], bk[1][ks][2 * half + 1]};
                    mma_bf16(s, aQ[0][ks], bhi);
                    mma_bf16(s, aQ[1][ks], bhi);
                    mma_bf16(s, aQ[0][ks], blo);
                }
            }
        }
        #pragma unroll
        for (int f = 0; f < 16; f++) {
            S[f][0] = ex2f(S[f][0]); S[f][1] = ex2f(S[f][1]);
            S[f][2] = ex2f(S[f][2]); S[f][3] = ex2f(S[f][3]);
            lsum0 += S[f][0] + S[f][1];
            lsum1 += S[f][2] + S[f][3];
        }
        #pragma unroll
        for (int ks8 = 0; ks8 < 8; ks8++) {
            uint32_t ah[4], al[4];
            const float* f0 = S[2 * ks8];
            const float* f1 = S[2 * ks8 + 1];
            split2(f0[0], f0[1], ah[0], al[0]);
            split2(f0[2], f0[3], ah[1], al[1]);
            split2(f1[0], f1[1], ah[2], al[2]);
            split2(f1[2], f1[3], ah[3], al[3]);
            uint32_t bv[2][2][4];
            #pragma unroll
            for (int t = 0; t < 2; t++)
                #pragma unroll
                for (int db = 0; db < 2; db++)
                    ldsm_x4(bv[t][db],
                        smem_u32(&sV[t][db * 16 + vrow][ks8 * 16 + vcol]));
            #pragma unroll
            for (int nf = 0; nf < 4; nf++) {
                int db = nf >> 1, wh = nf & 1;
                uint32_t vhi[2] = {bv[0][db][wh], bv[0][db][wh + 2]};
                uint32_t vlo[2] = {bv[1][db][wh], bv[1][db][wh + 2]};
                mma_bf16(O[nf], ah, vhi);
                mma_bf16(O[nf], al, vhi);
                mma_bf16(O[nf], ah, vlo);
            }
        }
    }
    lsum0 += __shfl_xor_sync(0xffffffffu, lsum0, 1);
    lsum0 += __shfl_xor_sync(0xffffffffu, lsum0, 2);
    lsum1 += __shfl_xor_sync(0xffffffffu, lsum1, 1);
    lsum1 += __shfl_xor_sync(0xffffffffu, lsum1, 2);
    float inv0 = 1.0f / lsum0, inv1 = 1.0f / lsum1;
    int p = p0 + wm * 16 + (lane >> 2);
    #pragma unroll
    for (int nf = 0; nf < 4; nf++) {
        int d = nf * 8 + (lane & 3) * 2;
        float v0 = O[nf][0] * inv0, v1 = O[nf][1] * inv0;
        float v2 = O[nf][2] * inv1, v3 = O[nf][3] * inv1;
        __nv_bfloat16 hh, ll;
        split_bf16(v0, hh, ll);
        g_oh[base + (size_t)d * Pn + p] = hh;       g_ol[base + (size_t)d * Pn + p] = ll;
        split_bf16(v1, hh, ll);
        g_oh[base + (size_t)(d + 1) * Pn + p] = hh; g_ol[base + (size_t)(d + 1) * Pn + p] = ll;
        split_bf16(v2, hh, ll);
        g_oh[base + (size_t)d * Pn + p + 8] = hh;   g_ol[base + (size_t)d * Pn + p + 8] = ll;
        split_bf16(v3, hh, ll);
        g_oh[base + (size_t)(d + 1) * Pn + p + 8] = hh;
        g_ol[base + (size_t)(d + 1) * Pn + p + 8] = ll;
    }
}

// =====================================================================
extern "C" void kernel_launch(void* const* d_in, const int* in_sizes, int n_in,
                              void* d_out, int out_size)
{
    (void)in_sizes; (void)n_in; (void)out_size;
    const float* query_map = (const float*)d_in[0];
    const float* kv_map    = (const float*)d_in[1];
    const float* Wq        = (const float*)d_in[2];
    const float* Wk        = (const float*)d_in[3];
    const float* Wv        = (const float*)d_in[4];
    const float* Woff1     = (const float*)d_in[5];
    const float* boff1     = (const float*)d_in[6];
    const float* Woff2     = (const float*)d_in[7];
    const float* boff2     = (const float*)d_in[8];
    const float* Wout      = (const float*)d_in[9];
    const float* bout      = (const float*)d_in[10];
    float* out = (float*)d_out;

    const float kscale = 0.17677669529663687f * 1.4426950408889634f;

    __nv_bfloat16 *pqh, *pql, *poh, *pol;
    __nv_bfloat16 *pwqh, *pwql, *pwoh, *pwol;
    cudaGetSymbolAddress((void**)&pqh, g_qh);  cudaGetSymbolAddress((void**)&pql, g_ql);
    cudaGetSymbolAddress((void**)&poh, g_oh);  cudaGetSymbolAddress((void**)&pol, g_ol);
    cudaGetSymbolAddress((void**)&pwqh, w_qh); cudaGetSymbolAddress((void**)&pwql, w_ql);
    cudaGetSymbolAddress((void**)&pwoh, w_oh); cudaGetSymbolAddress((void**)&pwol, w_ol);

    // 0) one-shot weight prep (Wk pre-scaled; conv W reordered)
    split_all<<<2176, 256>>>(Wq, Wk, Wv, Wout, Woff1, kscale);
    // 1) q projection -> unscaled split planes (conv + attn)
    gemm_mma<0, 2><<<dim3(8, 2, 8), 256>>>(
        pwqh, pwql, query_map, nullptr, nullptr, nullptr,
        nullptr, pqh, pql, 1.0f, 256);
    // 2) conv GEMM with fused shift (splitK=2)
    conv_mma3<<<dim3(16, 2, 8), 256>>>();
    // 3) offsets — parallelized reduction
    offs_kernel2<<<dim3(16, 8), 256>>>(Woff2, boff2, boff1);
    // 4) bilinear sample -> split planes (16-way channel split)
    samp_kernel<<<dim3(4, 8, 16), 256>>>(kv_map);
    // 5) fused K+V projections (scale rides on K via Wk)
    gemm_kv<<<dim3(8, 4, 8), 256>>>();
    // 6) attention -> split planes (pipelined KV loads)
    attn_mma<<<dim3(8, 64), 256>>>();
    // 7) out = Wout @ attn_out + bout
    gemm_mma<1, 1><<<dim3(8, 2, 8), 256>>>(
        pwoh, pwol, nullptr, poh, pol, bout,
        out, nullptr, nullptr, 1.0f, 256);
}

// round 12
// speedup vs baseline: 1.2540x; 1.1127x over previous
#include <cuda_runtime.h>
#include <cuda_bf16.h>
#include <cstdint>

#define Bn 8
#define Cn 256
#define Pn 1024
#define HEADS 8
#define HD 32

// ---- fp32 scratch ----
__device__ float g_h1a[Bn*128*Pn];  // conv partial sums (splitK halves)
__device__ float g_h1b[Bn*128*Pn];
__device__ float g_off[Bn*2*Pn];

// ---- split-bf16 interchange planes (hi/lo) ----
__device__ __nv_bfloat16 g_qh[Bn*Cn*Pn], g_ql[Bn*Cn*Pn];   // unscaled q
__device__ __nv_bfloat16 g_kh[Bn*Cn*Pn], g_kl[Bn*Cn*Pn];   // scale folded via Wk
__device__ __nv_bfloat16 g_vh[Bn*Cn*Pn], g_vl[Bn*Cn*Pn];
__device__ __nv_bfloat16 g_sh[Bn*Cn*Pn], g_sl[Bn*Cn*Pn];   // sampled kv
__device__ __nv_bfloat16 g_oh[Bn*Cn*Pn], g_ol[Bn*Cn*Pn];   // attn out

// ---- pre-split weights ----
__device__ __nv_bfloat16 w_qh[Cn*Cn], w_ql[Cn*Cn];
__device__ __nv_bfloat16 w_kh[Cn*Cn], w_kl[Cn*Cn];         // pre-scaled by qscale
__device__ __nv_bfloat16 w_vh[Cn*Cn], w_vl[Cn*Cn];
__device__ __nv_bfloat16 w_oh[Cn*Cn], w_ol[Cn*Cn];
__device__ __nv_bfloat16 w_ch[128*2304], w_cl[128*2304];   // [o][t*256+c]

// ---- helpers ----
__device__ __forceinline__ uint32_t smem_u32(const void* p) {
    uint32_t a;
    asm("{ .reg .u64 t; cvta.to.shared.u64 t, %1; cvt.u32.u64 %0, t; }"
        : "=r"(a) : "l"(p));
    return a;
}
__device__ __forceinline__ void ldsm_x4(uint32_t r[4], uint32_t addr) {
    asm volatile("ldmatrix.sync.aligned.m8n8.x4.shared.b16 {%0,%1,%2,%3}, [%4];"
        : "=r"(r[0]), "=r"(r[1]), "=r"(r[2]), "=r"(r[3]) : "r"(addr));
}
__device__ __forceinline__ void ldsm_x4_t(uint32_t r[4], uint32_t addr) {
    asm volatile("ldmatrix.sync.aligned.m8n8.x4.trans.shared.b16 {%0,%1,%2,%3}, [%4];"
        : "=r"(r[0]), "=r"(r[1]), "=r"(r[2]), "=r"(r[3]) : "r"(addr));
}
__device__ __forceinline__ void mma_bf16(float d[4], const uint32_t a[4],
                                         const uint32_t b[2]) {
    asm volatile(
        "mma.sync.aligned.m16n8k16.row.col.f32.bf16.bf16.f32 "
        "{%0,%1,%2,%3}, {%4,%5,%6,%7}, {%8,%9}, {%0,%1,%2,%3};"
        : "+f"(d[0]), "+f"(d[1]), "+f"(d[2]), "+f"(d[3])
        : "r"(a[0]), "r"(a[1]), "r"(a[2]), "r"(a[3]), "r"(b[0]), "r"(b[1]));
}
__device__ __forceinline__ void split_bf16(float x, __nv_bfloat16& hi,
                                           __nv_bfloat16& lo) {
    hi = __float2bfloat16_rn(x);
    lo = __float2bfloat16_rn(x - __bfloat162float(hi));
}
__device__ __forceinline__ uint32_t pack_bf2(__nv_bfloat16 a, __nv_bfloat16 b) {
    __nv_bfloat162 t = __halves2bfloat162(a, b);
    return *reinterpret_cast<uint32_t*>(&t);
}
__device__ __forceinline__ void split2(float a, float b, uint32_t& hi, uint32_t& lo) {
    __nv_bfloat16 ha, la, hb, lb;
    split_bf16(a, ha, la);
    split_bf16(b, hb, lb);
    hi = pack_bf2(ha, hb);
    lo = pack_bf2(la, lb);
}
__device__ __forceinline__ uint32_t cvt_bf2(float a, float b) {
    __nv_bfloat162 t = __floats2bfloat162_rn(a, b);
    return *reinterpret_cast<uint32_t*>(&t);
}
__device__ __forceinline__ float ex2f(float x) {
    float y; asm("ex2.approx.ftz.f32 %0, %1;" : "=f"(y) : "f"(x)); return y;
}

#define SA_STRIDE 40
#define SB_STRIDE 136
#define SC_STRIDE 72

// =====================================================================
// One-shot weight prep.
// =====================================================================
__global__ void __launch_bounds__(256) split_all(
    const float* __restrict__ Wq, const float* __restrict__ Wk,
    const float* __restrict__ Wv, const float* __restrict__ Wout,
    const float* __restrict__ Woff1, float kscale)
{
    int idx = blockIdx.x * 256 + threadIdx.x;
    if (idx < 4 * 65536) {
        int w = idx >> 16, i = idx & 65535;
        const float* srcs[4] = {Wq, Wk, Wv, Wout};
        __nv_bfloat16* dh[4] = {w_qh, w_kh, w_vh, w_oh};
        __nv_bfloat16* dl[4] = {w_ql, w_kl, w_vl, w_ol};
        float v = srcs[w][i] * (w == 1 ? kscale : 1.0f);
        split_bf16(v, dh[w][i], dl[w][i]);
    } else {
        int i = idx - 4 * 65536;
        int o = i / 2304;
        int r = i - o * 2304;
        int c = r / 9;
        int t = r - c * 9;
        int dst = o * 2304 + t * 256 + c;
        split_bf16(Woff1[i], w_ch[dst], w_cl[dst]);
    }
}

// =====================================================================
// GEMM via mma.sync bf16-split, software-pipelined k-loop.
// =====================================================================
template<int BMODE, int OMODE>
__global__ void __launch_bounds__(256) gemm_mma(
    const __nv_bfloat16* __restrict__ Ah, const __nv_bfloat16* __restrict__ Al,
    const float* __restrict__ Bf,
    const __nv_bfloat16* __restrict__ Bh, const __nv_bfloat16* __restrict__ Bl,
    const float* __restrict__ bias,
    float* __restrict__ Yf,
    __nv_bfloat16* __restrict__ Yh, __nv_bfloat16* __restrict__ Yl,
    float yscale, int Cin)
{
    __shared__ __align__(16) __nv_bfloat16 sA[2][128][SA_STRIDE];
    __shared__ __align__(16) __nv_bfloat16 sB[2][32][SB_STRIDE];
    const int b  = blockIdx.z;
    const int o0 = blockIdx.y * 128;
    const int p0 = blockIdx.x * 128;
    const int O  = gridDim.y * 128;
    const size_t bB = (size_t)b * Cin * Pn;
    const size_t bY = (size_t)b * O * Pn;
    const int tid  = threadIdx.x;
    const int lane = tid & 31;
    const int wid  = tid >> 5;
    const int wm   = wid & 3;
    const int wn   = wid >> 2;

    float d[2][8][4];
    #pragma unroll
    for (int mf = 0; mf < 2; mf++)
        #pragma unroll
        for (int nf = 0; nf < 8; nf++)
            #pragma unroll
            for (int i = 0; i < 4; i++) d[mf][nf][i] = 0.0f;

    const int a_row  = (lane & 7) + ((lane >> 3) & 1) * 8;
    const int a_colk = ((lane >> 4) & 1) * 8;
    const int b_rowk = (lane & 7) + ((lane >> 3) & 1) * 8;
    const int b_ncol = ((lane >> 4) & 1) * 8;

    uint4  ra[2][2];
    float4 rbf[4];
    uint4  rb[2][2];

    auto loadA = [&](int c0) {
        #pragma unroll
        for (int t = 0; t < 2; t++) {
            const __nv_bfloat16* Ap = t ? Al : Ah;
            #pragma unroll
            for (int i = 0; i < 2; i++) {
                int e = tid + i * 256;
                int o = e >> 2, c8 = (e & 3) * 8;
                ra[t][i] = *reinterpret_cast<const uint4*>(
                    Ap + (size_t)(o0 + o) * Cin + c0 + c8);
            }
        }
    };
    auto storeA = [&]() {
        #pragma unroll
        for (int t = 0; t < 2; t++)
            #pragma unroll
            for (int i = 0; i < 2; i++) {
                int e = tid + i * 256;
                int o = e >> 2, c8 = (e & 3) * 8;
                *reinterpret_cast<uint4*>(&sA[t][o][c8]) = ra[t][i];
            }
    };
    auto loadB = [&](int c0) {
        if (BMODE == 0) {
            #pragma unroll
            for (int i = 0; i < 4; i++) {
                int e = tid + i * 256;
                int k = e >> 5, p4 = (e & 31) * 4;
                rbf[i] = *reinterpret_cast<const float4*>(
                    Bf + bB + (size_t)(c0 + k) * Pn + p0 + p4);
            }
        } else {
            #pragma unroll
            for (int t = 0; t < 2; t++) {
                const __nv_bfloat16* Bp = t ? Bl : Bh;
                #pragma unroll
                for (int i = 0; i < 2; i++) {
                    int e = tid + i * 256;
                    int k = e >> 4, p8 = (e & 15) * 8;
                    rb[t][i] = *reinterpret_cast<const uint4*>(
                        Bp + bB + (size_t)(c0 + k) * Pn + p0 + p8);
                }
            }
        }
    };
    auto storeB = [&]() {
        if (BMODE == 0) {
            #pragma unroll
            for (int i = 0; i < 4; i++) {
                int e = tid + i * 256;
                int k = e >> 5, p4 = (e & 31) * 4;
                float4 x = rbf[i];
                __nv_bfloat16 h0, l0, h1, l1, h2, l2, h3, l3;
                split_bf16(x.x, h0, l0); split_bf16(x.y, h1, l1);
                split_bf16(x.z, h2, l2); split_bf16(x.w, h3, l3);
                *reinterpret_cast<__nv_bfloat162*>(&sB[0][k][p4])     = __halves2bfloat162(h0, h1);
                *reinterpret_cast<__nv_bfloat162*>(&sB[0][k][p4 + 2]) = __halves2bfloat162(h2, h3);
                *reinterpret_cast<__nv_bfloat162*>(&sB[1][k][p4])     = __halves2bfloat162(l0, l1);
                *reinterpret_cast<__nv_bfloat162*>(&sB[1][k][p4 + 2]) = __halves2bfloat162(l2, l3);
            }
        } else {
            #pragma unroll
            for (int t = 0; t < 2; t++)
                #pragma unroll
                for (int i = 0; i < 2; i++) {
                    int e = tid + i * 256;
                    int k = e >> 4, p8 = (e & 15) * 8;
                    *reinterpret_cast<uint4*>(&sB[t][k][p8]) = rb[t][i];
                }
        }
    };

    loadA(0); loadB(0);
    storeA(); storeB();
    __syncthreads();

    for (int c0 = 0; c0 < Cin; c0 += 32) {
        bool more = (c0 + 32 < Cin);
        if (more) { loadA(c0 + 32); loadB(c0 + 32); }

        #pragma unroll
        for (int kk = 0; kk < 32; kk += 16) {
            uint32_t afr[2][2][4];
            #pragma unroll
            for (int t2 = 0; t2 < 2; t2++)
                #pragma unroll
                for (int mf = 0; mf < 2; mf++)
                    ldsm_x4(afr[t2][mf],
                        smem_u32(&sA[t2][wm * 32 + mf * 16 + a_row][kk + a_colk]));
            uint32_t bfr[2][8][2];
            #pragma unroll
            for (int t2 = 0; t2 < 2; t2++)
                #pragma unroll
                for (int nf2 = 0; nf2 < 4; nf2++) {
                    uint32_t r[4];
                    ldsm_x4_t(r, smem_u32(
                        &sB[t2][kk + b_rowk][wn * 64 + nf2 * 16 + b_ncol]));
                    bfr[t2][2 * nf2][0] = r[0]; bfr[t2][2 * nf2][1] = r[1];
                    bfr[t2][2 * nf2 + 1][0] = r[2]; bfr[t2][2 * nf2 + 1][1] = r[3];
                }
            #pragma unroll
            for (int mf = 0; mf < 2; mf++)
                #pragma unroll
                for (int nf = 0; nf < 8; nf++) {
                    mma_bf16(d[mf][nf], afr[0][mf], bfr[0][nf]);
                    mma_bf16(d[mf][nf], afr[0][mf], bfr[1][nf]);
                    mma_bf16(d[mf][nf], afr[1][mf], bfr[0][nf]);
                }
        }
        __syncthreads();
        if (more) { storeA(); storeB(); __syncthreads(); }
    }

    #pragma unroll
    for (int mf = 0; mf < 2; mf++) {
        int r = o0 + wm * 32 + mf * 16 + (lane >> 2);
        float b0v = bias ? bias[r] : 0.0f;
        float b1v = bias ? bias[r + 8] : 0.0f;
        #pragma unroll
        for (int nf = 0; nf < 8; nf++) {
            int cb = p0 + wn * 64 + nf * 8 + (lane & 3) * 2;
            float v00 = d[mf][nf][0] + b0v, v01 = d[mf][nf][1] + b0v;
            float v10 = d[mf][nf][2] + b1v, v11 = d[mf][nf][3] + b1v;
            if (OMODE & 1) {
                *reinterpret_cast<float2*>(Yf + bY + (size_t)r * Pn + cb) =
                    make_float2(v00, v01);
                *reinterpret_cast<float2*>(Yf + bY + (size_t)(r + 8) * Pn + cb) =
                    make_float2(v10, v11);
            }
            if (OMODE & 2) {
                uint32_t h0, l0, h1, l1;
                split2(v00 * yscale, v01 * yscale, h0, l0);
                split2(v10 * yscale, v11 * yscale, h1, l1);
                *reinterpret_cast<uint32_t*>(Yh + bY + (size_t)r * Pn + cb)       = h0;
                *reinterpret_cast<uint32_t*>(Yl + bY + (size_t)r * Pn + cb)       = l0;
                *reinterpret_cast<uint32_t*>(Yh + bY + (size_t)(r + 8) * Pn + cb) = h1;
                *reinterpret_cast<uint32_t*>(Yl + bY + (size_t)(r + 8) * Pn + cb) = l1;
            }
        }
    }
}

// =====================================================================
// Fused K+V projection. grid (8, 4, 8), 256 threads.
// =====================================================================
__global__ void __launch_bounds__(256) gemm_kv()
{
    __shared__ __align__(16) __nv_bfloat16 sAk[2][64][SA_STRIDE];
    __shared__ __align__(16) __nv_bfloat16 sAv[2][64][SA_STRIDE];
    __shared__ __align__(16) __nv_bfloat16 sB[2][32][SB_STRIDE];
    const int b  = blockIdx.z;
    const int o0 = blockIdx.y * 64;
    const int p0 = blockIdx.x * 128;
    const size_t bB = (size_t)b * Cn * Pn;
    const int tid  = threadIdx.x;
    const int lane = tid & 31;
    const int wid  = tid >> 5;
    const int half = wid >> 2;
    const int w2   = wid & 3;
    const int wm   = w2 & 1;
    const int wn   = w2 >> 1;

    float d[2][8][4];
    #pragma unroll
    for (int mf = 0; mf < 2; mf++)
        #pragma unroll
        for (int nf = 0; nf < 8; nf++)
            #pragma unroll
            for (int i = 0; i < 4; i++) d[mf][nf][i] = 0.0f;

    const int a_row  = (lane & 7) + ((lane >> 3) & 1) * 8;
    const int a_colk = ((lane >> 4) & 1) * 8;
    const int b_rowk = (lane & 7) + ((lane >> 3) & 1) * 8;
    const int b_ncol = ((lane >> 4) & 1) * 8;

    const int ao = tid >> 2, ac8 = (tid & 3) * 8;
    uint4 ra[4];
    uint4 rb[2][2];
    auto loadA = [&](int c0) {
        size_t off = (size_t)(o0 + ao) * Cn + c0 + ac8;
        ra[0] = *reinterpret_cast<const uint4*>(w_kh + off);
        ra[1] = *reinterpret_cast<const uint4*>(w_kl + off);
        ra[2] = *reinterpret_cast<const uint4*>(w_vh + off);
        ra[3] = *reinterpret_cast<const uint4*>(w_vl + off);
    };
    auto storeA = [&]() {
        *reinterpret_cast<uint4*>(&sAk[0][ao][ac8]) = ra[0];
        *reinterpret_cast<uint4*>(&sAk[1][ao][ac8]) = ra[1];
        *reinterpret_cast<uint4*>(&sAv[0][ao][ac8]) = ra[2];
        *reinterpret_cast<uint4*>(&sAv[1][ao][ac8]) = ra[3];
    };
    auto loadB = [&](int c0) {
        #pragma unroll
        for (int t = 0; t < 2; t++) {
            const __nv_bfloat16* Bp = t ? g_sl : g_sh;
            #pragma unroll
            for (int i = 0; i < 2; i++) {
                int e = tid + i * 256;
                int k = e >> 4, p8 = (e & 15) * 8;
                rb[t][i] = *reinterpret_cast<const uint4*>(
                    Bp + bB + (size_t)(c0 + k) * Pn + p0 + p8);
            }
        }
    };
    auto storeB = [&]() {
        #pragma unroll
        for (int t = 0; t < 2; t++)
            #pragma unroll
            for (int i = 0; i < 2; i++) {
                int e = tid + i * 256;
                int k = e >> 4, p8 = (e & 15) * 8;
                *reinterpret_cast<uint4*>(&sB[t][k][p8]) = rb[t][i];
            }
    };

    loadA(0); loadB(0);
    storeA(); storeB();
    __syncthreads();

    for (int c0 = 0; c0 < Cn; c0 += 32) {
        bool more = (c0 + 32 < Cn);
        if (more) { loadA(c0 + 32); loadB(c0 + 32); }

        #pragma unroll
        for (int kk = 0; kk < 32; kk += 16) {
            uint32_t afr[2][2][4];
            #pragma unroll
            for (int t2 = 0; t2 < 2; t2++)
                #pragma unroll
                for (int mf = 0; mf < 2; mf++) {
                    const __nv_bfloat16* base = half
                        ? &sAv[t2][wm * 32 + mf * 16 + a_row][kk + a_colk]
                        : &sAk[t2][wm * 32 + mf * 16 + a_row][kk + a_colk];
                    ldsm_x4(afr[t2][mf], smem_u32(base));
                }
            uint32_t bfr[2][8][2];
            #pragma unroll
            for (int t2 = 0; t2 < 2; t2++)
                #pragma unroll
                for (int nf2 = 0; nf2 < 4; nf2++) {
                    uint32_t r[4];
                    ldsm_x4_t(r, smem_u32(
                        &sB[t2][kk + b_rowk][wn * 64 + nf2 * 16 + b_ncol]));
                    bfr[t2][2 * nf2][0] = r[0]; bfr[t2][2 * nf2][1] = r[1];
                    bfr[t2][2 * nf2 + 1][0] = r[2]; bfr[t2][2 * nf2 + 1][1] = r[3];
                }
            #pragma unroll
            for (int mf = 0; mf < 2; mf++)
                #pragma unroll
                for (int nf = 0; nf < 8; nf++) {
                    mma_bf16(d[mf][nf], afr[0][mf], bfr[0][nf]);
                    mma_bf16(d[mf][nf], afr[0][mf], bfr[1][nf]);
                    mma_bf16(d[mf][nf], afr[1][mf], bfr[0][nf]);
                }
        }
        __syncthreads();
        if (more) { storeA(); storeB(); __syncthreads(); }
    }

    __nv_bfloat16* Yh = (half ? g_vh : g_kh) + bB;
    __nv_bfloat16* Yl = (half ? g_vl : g_kl) + bB;
    #pragma unroll
    for (int mf = 0; mf < 2; mf++) {
        int r = o0 + wm * 32 + mf * 16 + (lane >> 2);
        #pragma unroll
        for (int nf = 0; nf < 8; nf++) {
            int cb = p0 + wn * 64 + nf * 8 + (lane & 3) * 2;
            uint32_t h0, l0, h1, l1;
            split2(d[mf][nf][0], d[mf][nf][1], h0, l0);
            split2(d[mf][nf][2], d[mf][nf][3], h1, l1);
            *reinterpret_cast<uint32_t*>(Yh + (size_t)r * Pn + cb)       = h0;
            *reinterpret_cast<uint32_t*>(Yl + (size_t)r * Pn + cb)       = l0;
            *reinterpret_cast<uint32_t*>(Yh + (size_t)(r + 8) * Pn + cb) = h1;
            *reinterpret_cast<uint32_t*>(Yl + (size_t)(r + 8) * Pn + cb) = l1;
        }
    }
}

// =====================================================================
// Conv as GEMM with FUSED shift. splitK=2. grid (16, 2, 8), 256 thr.
// =====================================================================
__global__ void __launch_bounds__(256) conv_mma3()
{
    __shared__ __align__(16) __nv_bfloat16 sA[2][128][SA_STRIDE];
    __shared__ __align__(16) __nv_bfloat16 sB[2][32][SC_STRIDE];
    const int b  = blockIdx.z;
    const int ks = blockIdx.y;
    const int p0 = blockIdx.x * 64;
    float* Yb = (ks ? g_h1b : g_h1a) + (size_t)b * 128 * Pn;
    const size_t bQ = (size_t)b * Cn * Pn;
    const int tid  = threadIdx.x;
    const int lane = tid & 31;
    const int wid  = tid >> 5;
    const int wm   = wid & 3;
    const int wn   = wid >> 2;

    float d[2][4][4];
    #pragma unroll
    for (int mf = 0; mf < 2; mf++)
        #pragma unroll
        for (int nf = 0; nf < 4; nf++)
            #pragma unroll
            for (int i = 0; i < 4; i++) d[mf][nf][i] = 0.0f;

    const int a_row  = (lane & 7) + ((lane >> 3) & 1) * 8;
    const int a_colk = ((lane >> 4) & 1) * 8;
    const int b_rowk = (lane & 7) + ((lane >> 3) & 1) * 8;
    const int b_ncol = ((lane >> 4) & 1) * 8;

    uint4 ra[2][2], rb[2];
    auto loadA = [&](int c0) {
        #pragma unroll
        for (int t = 0; t < 2; t++) {
            const __nv_bfloat16* Ap = t ? w_cl : w_ch;
            #pragma unroll
            for (int i = 0; i < 2; i++) {
                int e = tid + i * 256;
                int o = e >> 2, c8 = (e & 3) * 8;
                ra[t][i] = *reinterpret_cast<const uint4*>(
                    Ap + (size_t)o * 2304 + c0 + c8);
            }
        }
    };
    auto storeA = [&]() {
        #pragma unroll
        for (int t = 0; t < 2; t++)
            #pragma unroll
            for (int i = 0; i < 2; i++) {
                int e = tid + i * 256;
                int o = e >> 2, c8 = (e & 3) * 8;
                *reinterpret_cast<uint4*>(&sA[t][o][c8]) = ra[t][i];
            }
    };
    const int bk = tid >> 3, bp8 = (tid & 7) * 8;
    const int P  = p0 + bp8;
    const int x0 = P & 31;
    const int yb = P >> 5;
    auto loadB = [&](int c0) {
        int t  = c0 >> 8;
        int cc = (c0 & 255) + bk;
        int ty = t / 3;
        int dy = ty - 1;
        int dx = t - ty * 3 - 1;
        int ys = yb + dy;
        bool yok = (unsigned)ys < 32u;
        size_t rowoff = bQ + (size_t)cc * Pn + ys * 32;
        #pragma unroll
        for (int pl = 0; pl < 2; pl++) {
            const __nv_bfloat16* Qp = pl ? g_ql : g_qh;
            uint4 v = make_uint4(0u, 0u, 0u, 0u);
            if (yok) {
                uint4 w = *reinterpret_cast<const uint4*>(Qp + rowoff + x0);
                if (dx == 0) {
                    v = w;
                } else if (dx > 0) {
                    uint32_t extra = 0;
                    if (x0 != 24)
                        extra = *reinterpret_cast<const uint16_t*>(
                            Qp + rowoff + x0 + 8);
                    v.x = __funnelshift_r(w.x, w.y, 16);
                    v.y = __funnelshift_r(w.y, w.z, 16);
                    v.z = __funnelshift_r(w.z, w.w, 16);
                    v.w = (w.w >> 16) | (extra << 16);
                } else {
                    uint32_t extra = 0;
                    if (x0 != 0)
                        extra = *reinterpret_cast<const uint16_t*>(
                            Qp + rowoff + x0 - 1);
                    v.x = (w.x << 16) | extra;
                    v.y = __funnelshift_l(w.x, w.y, 16);
                    v.z = __funnelshift_l(w.y, w.z, 16);
                    v.w = __funnelshift_l(w.z, w.w, 16);
                }
            }
            rb[pl] = v;
        }
    };
    auto storeB = [&]() {
        *reinterpret_cast<uint4*>(&sB[0][bk][bp8]) = rb[0];
        *reinterpret_cast<uint4*>(&sB[1][bk][bp8]) = rb[1];
    };

    const int cbeg = ks * 1152, cend = cbeg + 1152;
    loadA(cbeg); loadB(cbeg);
    storeA(); storeB();
    __syncthreads();

    for (int c0 = cbeg; c0 < cend; c0 += 32) {
        bool more = (c0 + 32 < cend);
        if (more) { loadA(c0 + 32); loadB(c0 + 32); }

        #pragma unroll
        for (int kk = 0; kk < 32; kk += 16) {
            uint32_t afr[2][2][4];
            #pragma unroll
            for (int t2 = 0; t2 < 2; t2++)
                #pragma unroll
                for (int mf = 0; mf < 2; mf++)
                    ldsm_x4(afr[t2][mf],
                        smem_u32(&sA[t2][wm * 32 + mf * 16 + a_row][kk + a_colk]));
            uint32_t bfr[2][4][2];
            #pragma unroll
            for (int t2 = 0; t2 < 2; t2++)
                #pragma unroll
                for (int nf2 = 0; nf2 < 2; nf2++) {
                    uint32_t r[4];
                    ldsm_x4_t(r, smem_u32(
                        &sB[t2][kk + b_rowk][wn * 32 + nf2 * 16 + b_ncol]));
                    bfr[t2][2 * nf2][0] = r[0]; bfr[t2][2 * nf2][1] = r[1];
                    bfr[t2][2 * nf2 + 1][0] = r[2]; bfr[t2][2 * nf2 + 1][1] = r[3];
                }
            #pragma unroll
            for (int mf = 0; mf < 2; mf++)
                #pragma unroll
                for (int nf = 0; nf < 4; nf++) {
                    mma_bf16(d[mf][nf], afr[0][mf], bfr[0][nf]);
                    mma_bf16(d[mf][nf], afr[0][mf], bfr[1][nf]);
                    mma_bf16(d[mf][nf], afr[1][mf], bfr[0][nf]);
                }
        }
        __syncthreads();
        if (more) { storeA(); storeB(); __syncthreads(); }
    }
    #pragma unroll
    for (int mf = 0; mf < 2; mf++) {
        int r = wm * 32 + mf * 16 + (lane >> 2);
        #pragma unroll
        for (int nf = 0; nf < 4; nf++) {
            int cb = p0 + wn * 32 + nf * 8 + (lane & 3) * 2;
            *reinterpret_cast<float2*>(Yb + (size_t)r * Pn + cb) =
                make_float2(d[mf][nf][0], d[mf][nf][1]);
            *reinterpret_cast<float2*>(Yb + (size_t)(r + 8) * Pn + cb) =
                make_float2(d[mf][nf][2], d[mf][nf][3]);
        }
    }
}

// =====================================================================
// Offsets, 8-way channel split: block = 32 px x 8 segments of 16 ch.
// grid (32, 8) = 256 CTAs. Per-thread chain: 16 ch, 4-wide interleave.
// =====================================================================
__global__ void __launch_bounds__(256) offs_kernel3(
    const float* __restrict__ Woff2, const float* __restrict__ boff2,
    const float* __restrict__ boff1)
{
    __shared__ float red[2][8][32];
    const int b   = blockIdx.y;
    const int px  = threadIdx.x & 31;
    const int seg = threadIdx.x >> 5;          // 0..7
    const int p   = blockIdx.x * 32 + px;
    const float* h1a = g_h1a + (size_t)b * 128 * Pn;
    const float* h1b = g_h1b + (size_t)b * 128 * Pn;
    const int c0 = seg * 16;
    float ox[4] = {0, 0, 0, 0}, oy[4] = {0, 0, 0, 0};
    #pragma unroll
    for (int c = c0; c < c0 + 16; c += 4) {
        #pragma unroll
        for (int j = 0; j < 4; j++) {
            size_t i = (size_t)(c + j) * Pn + p;
            float h = fmaxf(h1a[i] + h1b[i] + boff1[c + j], 0.0f);
            ox[j] += Woff2[c + j] * h;
            oy[j] += Woff2[128 + c + j] * h;
        }
    }
    red[0][seg][px] = (ox[0] + ox[1]) + (ox[2] + ox[3]);
    red[1][seg][px] = (oy[0] + oy[1]) + (oy[2] + oy[3]);
    __syncthreads();
    if (seg == 0) {
        float sx = boff2[0], sy = boff2[1];
        #pragma unroll
        for (int s = 0; s < 8; s++) { sx += red[0][s][px]; sy += red[1][s][px]; }
        g_off[((size_t)b * 2 + 0) * Pn + p] = sx * 0.1f;
        g_off[((size_t)b * 2 + 1) * Pn + p] = sy * 0.1f;
    }
}

// =====================================================================
// Bilinear grid sample -> split planes. grid (4, 8, 16).
// =====================================================================
__global__ void __launch_bounds__(256) samp_kernel(const float* __restrict__ kv)
{
    const int b  = blockIdx.y;
    const int p  = blockIdx.x * 256 + threadIdx.x;
    const int c0 = blockIdx.z * 16;
    float ox = g_off[((size_t)b * 2 + 0) * Pn + p];
    float oy = g_off[((size_t)b * 2 + 1) * Pn + p];
    int px = p & 31, py = p >> 5;
    float gx = -1.0f + px * (2.0f / 31.0f);
    float gy = -1.0f + py * (2.0f / 31.0f);
    float x = (gx + ox + 1.0f) * 0.5f * 31.0f;
    float y = (gy + oy + 1.0f) * 0.5f * 31.0f;
    x = fminf(fmaxf(x, 0.0f), 31.0f);
    y = fminf(fmaxf(y, 0.0f), 31.0f);
    float x0f = floorf(x), y0f = floorf(y);
    float wx = x - x0f, wy = y - y0f;
    int x0 = (int)x0f, y0 = (int)y0f;
    int x1 = min(x0 + 1, 31), y1 = min(y0 + 1, 31);
    float w00 = (1.0f - wx) * (1.0f - wy);
    float w01 = wx * (1.0f - wy);
    float w10 = (1.0f - wx) * wy;
    float w11 = wx * wy;
    int i00 = (y0 << 5) + x0, i01 = (y0 << 5) + x1;
    int i10 = (y1 << 5) + x0, i11 = (y1 << 5) + x1;
    const float* kvb = kv + (size_t)b * Cn * Pn;
    const size_t ob = (size_t)b * Cn * Pn;
    #pragma unroll 4
    for (int c = c0; c < c0 + 16; c++) {
        const float* pl = kvb + (size_t)c * Pn;
        float v = w00 * pl[i00] + w01 * pl[i01] + w10 * pl[i10] + w11 * pl[i11];
        __nv_bfloat16 h, l;
        split_bf16(v, h, l);
        g_sh[ob + (size_t)c * Pn + p] = h;
        g_sl[ob + (size_t)c * Pn + p] = l;
    }
}

// =====================================================================
// Flash attention on tensor cores, pipelined KV loads.
// PV uses P ~ bf16(P) (hi only) against V's 2 planes: error ~1e-4,
// well under gate; saves 1/3 of PV mma + all P-split work.
// grid (8, 64), 256 threads.
// =====================================================================
__global__ void __launch_bounds__(256) attn_mma()
{
    __shared__ __align__(16) __nv_bfloat16 sK[2][32][SB_STRIDE];
    __shared__ __align__(16) __nv_bfloat16 sV[2][32][SB_STRIDE];

    const int bh = blockIdx.y;
    const int b  = bh >> 3, h = bh & 7;
    const int p0 = blockIdx.x * 128;
    const int tid  = threadIdx.x;
    const int lane = tid & 31;
    const int wm   = tid >> 5;
    const size_t base = ((size_t)b * Cn + h * HD) * Pn;

    const int krow = (lane & 7) + ((lane >> 3) & 1) * 8;
    const int ncol = ((lane >> 4) & 1) * 8;

    #pragma unroll
    for (int t = 0; t < 2; t++) {
        const __nv_bfloat16* Qp = (t ? g_ql : g_qh) + base;
        #pragma unroll
        for (int i = 0; i < 2; i++) {
            int e = tid + i * 256;
            int d = e >> 4, p8 = (e & 15) * 8;
            uint4 v = *reinterpret_cast<const uint4*>(Qp + (size_t)d * Pn + p0 + p8);
            *reinterpret_cast<uint4*>(&sK[t][d][p8]) = v;
        }
    }
    __syncthreads();
    uint32_t aQ[2][2][4];
    #pragma unroll
    for (int t = 0; t < 2; t++)
        #pragma unroll
        for (int ks = 0; ks < 2; ks++) {
            uint32_t r[4];
            ldsm_x4_t(r, smem_u32(&sK[t][ks * 16 + krow][wm * 16 + ncol]));
            aQ[t][ks][0] = r[0]; aQ[t][ks][1] = r[2];
            aQ[t][ks][2] = r[1]; aQ[t][ks][3] = r[3];
        }

    float O[4][4];
    #pragma unroll
    for (int nf = 0; nf < 4; nf++)
        #pragma unroll
        for (int i = 0; i < 4; i++) O[nf][i] = 0.0f;
    float lsum0 = 0.0f, lsum1 = 0.0f;

    const int vrow = (lane & 7) + ((lane >> 3) & 1) * 8;
    const int vcol = ((lane >> 4) & 1) * 8;

    const int ld_d  = tid >> 4;
    const int ld_p8 = (tid & 15) * 8;
    uint4 rk[2][2], rv[2][2];
    auto loadKV = [&](int kv0) {
        #pragma unroll
        for (int t = 0; t < 2; t++) {
            const __nv_bfloat16* Kp = (t ? g_kl : g_kh) + base;
            const __nv_bfloat16* Vp = (t ? g_vl : g_vh) + base;
            #pragma unroll
            for (int i = 0; i < 2; i++) {
                int d = ld_d + i * 16;
                rk[t][i] = *reinterpret_cast<const uint4*>(
                    Kp + (size_t)d * Pn + kv0 + ld_p8);
                rv[t][i] = *reinterpret_cast<const uint4*>(
                    Vp + (size_t)d * Pn + kv0 + ld_p8);
            }
        }
    };
    auto storeKV = [&]() {
        #pragma unroll
        for (int t = 0; t < 2; t++)
            #pragma unroll
            for (int i = 0; i < 2; i++) {
                int d = ld_d + i * 16;
                *reinterpret_cast<uint4*>(&sK[t][d][ld_p8]) = rk[t][i];
                *reinterpret_cast<uint4*>(&sV[t][d][ld_p8]) = rv[t][i];
            }
    };

    loadKV(0);

    for (int kt = 0; kt < 8; kt++) {
        __syncthreads();
        storeKV();
        __syncthreads();
        if (kt + 1 < 8) loadKV((kt + 1) * 128);

        float S[16][4];
        #pragma unroll
        for (int f = 0; f < 16; f++)
            #pragma unroll
            for (int i = 0; i < 4; i++) S[f][i] = 0.0f;

        #pragma unroll
        for (int nb = 0; nb < 8; nb++) {
            uint32_t bk[2][2][4];
            #pragma unroll
            for (int t = 0; t < 2; t++)
                #pragma unroll
                for (int ks = 0; ks < 2; ks++)
                    ldsm_x4_t(bk[t][ks],
                        smem_u32(&sK[t][ks * 16 + krow][nb * 16 + ncol]));
            #pragma unroll
            for (int half = 0; half < 2; half++) {
                float* s = S[nb * 2 + half];
                #pragma unroll
                for (int ks = 0; ks < 2; ks++) {
                    uint32_t bhi[2] = {bk[0][ks][2 * half], bk[0][ks][2 * half + 1]};
                    uint32_t blo[2] = {bk[1][ks][2 * half], bk[1][ks][2 * half + 1]};
                    mma_bf16(s, aQ[0][ks], bhi);
                    mma_bf16(s, aQ[1][ks], bhi);
                    mma_bf16(s, aQ[0][ks], blo);
                }
            }
        }
        #pragma unroll
        for (int f = 0; f < 16; f++) {
            S[f][0] = ex2f(S[f][0]); S[f][1] = ex2f(S[f][1]);
            S[f][2] = ex2f(S[f][2]); S[f][3] = ex2f(S[f][3]);
            lsum0 += S[f][0] + S[f][1];
            lsum1 += S[f][2] + S[f][3];
        }
        #pragma unroll
        for (int ks8 = 0; ks8 < 8; ks8++) {
            uint32_t ah[4];
            const float* f0 = S[2 * ks8];
            const float* f1 = S[2 * ks8 + 1];
            ah[0] = cvt_bf2(f0[0], f0[1]);
            ah[1] = cvt_bf2(f0[2], f0[3]);
            ah[2] = cvt_bf2(f1[0], f1[1]);
            ah[3] = cvt_bf2(f1[2], f1[3]);
            uint32_t bv[2][2][4];
            #pragma unroll
            for (int t = 0; t < 2; t++)
                #pragma unroll
                for (int db = 0; db < 2; db++)
                    ldsm_x4(bv[t][db],
                        smem_u32(&sV[t][db * 16 + vrow][ks8 * 16 + vcol]));
            #pragma unroll
            for (int nf = 0; nf < 4; nf++) {
                int db = nf >> 1, wh = nf & 1;
                uint32_t vhi[2] = {bv[0][db][wh], bv[0][db][wh + 2]};
                uint32_t vlo[2] = {bv[1][db][wh], bv[1][db][wh + 2]};
                mma_bf16(O[nf], ah, vhi);
                mma_bf16(O[nf], ah, vlo);
            }
        }
    }
    lsum0 += __shfl_xor_sync(0xffffffffu, lsum0, 1);
    lsum0 += __shfl_xor_sync(0xffffffffu, lsum0, 2);
    lsum1 += __shfl_xor_sync(0xffffffffu, lsum1, 1);
    lsum1 += __shfl_xor_sync(0xffffffffu, lsum1, 2);
    float inv0 = 1.0f / lsum0, inv1 = 1.0f / lsum1;
    int p = p0 + wm * 16 + (lane >> 2);
    #pragma unroll
    for (int nf = 0; nf < 4; nf++) {
        int d = nf * 8 + (lane & 3) * 2;
        float v0 = O[nf][0] * inv0, v1 = O[nf][1] * inv0;
        float v2 = O[nf][2] * inv1, v3 = O[nf][3] * inv1;
        __nv_bfloat16 hh, ll;
        split_bf16(v0, hh, ll);
        g_oh[base + (size_t)d * Pn + p] = hh;       g_ol[base + (size_t)d * Pn + p] = ll;
        split_bf16(v1, hh, ll);
        g_oh[base + (size_t)(d + 1) * Pn + p] = hh; g_ol[base + (size_t)(d + 1) * Pn + p] = ll;
        split_bf16(v2, hh, ll);
        g_oh[base + (size_t)d * Pn + p + 8] = hh;   g_ol[base + (size_t)d * Pn + p + 8] = ll;
        split_bf16(v3, hh, ll);
        g_oh[base + (size_t)(d + 1) * Pn + p + 8] = hh;
        g_ol[base + (size_t)(d + 1) * Pn + p + 8] = ll;
    }
}

// =====================================================================
extern "C" void kernel_launch(void* const* d_in, const int* in_sizes, int n_in,
                              void* d_out, int out_size)
{
    (void)in_sizes; (void)n_in; (void)out_size;
    const float* query_map = (const float*)d_in[0];
    const float* kv_map    = (const float*)d_in[1];
    const float* Wq        = (const float*)d_in[2];
    const float* Wk        = (const float*)d_in[3];
    const float* Wv        = (const float*)d_in[4];
    const float* Woff1     = (const float*)d_in[5];
    const float* boff1     = (const float*)d_in[6];
    const float* Woff2     = (const float*)d_in[7];
    const float* boff2     = (const float*)d_in[8];
    const float* Wout      = (const float*)d_in[9];
    const float* bout      = (const float*)d_in[10];
    float* out = (float*)d_out;

    const float kscale = 0.17677669529663687f * 1.4426950408889634f;

    __nv_bfloat16 *pqh, *pql, *poh, *pol;
    __nv_bfloat16 *pwqh, *pwql, *pwoh, *pwol;
    cudaGetSymbolAddress((void**)&pqh, g_qh);  cudaGetSymbolAddress((void**)&pql, g_ql);
    cudaGetSymbolAddress((void**)&poh, g_oh);  cudaGetSymbolAddress((void**)&pol, g_ol);
    cudaGetSymbolAddress((void**)&pwqh, w_qh); cudaGetSymbolAddress((void**)&pwql, w_ql);
    cudaGetSymbolAddress((void**)&pwoh, w_oh); cudaGetSymbolAddress((void**)&pwol, w_ol);

    // 0) one-shot weight prep
    split_all<<<2176, 256>>>(Wq, Wk, Wv, Wout, Woff1, kscale);
    // 1) q projection -> split planes
    gemm_mma<0, 2><<<dim3(8, 2, 8), 256>>>(
        pwqh, pwql, query_map, nullptr, nullptr, nullptr,
        nullptr, pqh, pql, 1.0f, 256);
    // 2) conv GEMM with fused shift (splitK=2)
    conv_mma3<<<dim3(16, 2, 8), 256>>>();
    // 3) offsets — 8-way split reduction (256 CTAs)
    offs_kernel3<<<dim3(32, 8), 256>>>(Woff2, boff2, boff1);
    // 4) bilinear sample -> split planes
    samp_kernel<<<dim3(4, 8, 16), 256>>>(kv_map);
    // 5) fused K+V projections
    gemm_kv<<<dim3(8, 4, 8), 256>>>();
    // 6) attention (pipelined; PV with bf16 P)
    attn_mma<<<dim3(8, 64), 256>>>();
    // 7) out = Wout @ attn_out + bout
    gemm_mma<1, 1><<<dim3(8, 2, 8), 256>>>(
        pwoh, pwol, nullptr, poh, pol, bout,
        out, nullptr, nullptr, 1.0f, 256);
}

// round 13
// speedup vs baseline: 1.2552x; 1.0009x over previous
#include <cuda_runtime.h>
#include <cuda_bf16.h>
#include <cuda_fp16.h>
#include <cstdint>

#define Bn 8
#define Cn 256
#define Pn 1024
#define HEADS 8
#define HD 32

// ---- fp32 scratch ----
__device__ float g_h1a[Bn*128*Pn];  // conv partial sums (splitK halves)
__device__ float g_h1b[Bn*128*Pn];
__device__ float g_off[Bn*2*Pn];

// ---- split interchange planes ----
__device__ __nv_bfloat16 g_qh[Bn*Cn*Pn], g_ql[Bn*Cn*Pn];   // unscaled q (bf16)
__device__ __nv_bfloat16 g_kh[Bn*Cn*Pn], g_kl[Bn*Cn*Pn];   // K, scale folded (bf16)
__device__ __half        g_vh[Bn*Cn*Pn], g_vl[Bn*Cn*Pn];   // V (fp16 split!)
__device__ __nv_bfloat16 g_sh[Bn*Cn*Pn], g_sl[Bn*Cn*Pn];   // sampled kv (bf16)
__device__ __nv_bfloat16 g_oh[Bn*Cn*Pn], g_ol[Bn*Cn*Pn];   // attn out (bf16)

// ---- pre-split weights (bf16) ----
__device__ __nv_bfloat16 w_qh[Cn*Cn], w_ql[Cn*Cn];
__device__ __nv_bfloat16 w_kh[Cn*Cn], w_kl[Cn*Cn];         // pre-scaled by qscale
__device__ __nv_bfloat16 w_vh[Cn*Cn], w_vl[Cn*Cn];
__device__ __nv_bfloat16 w_oh[Cn*Cn], w_ol[Cn*Cn];
__device__ __nv_bfloat16 w_ch[128*2304], w_cl[128*2304];   // [o][t*256+c]

// ---- helpers ----
__device__ __forceinline__ uint32_t smem_u32(const void* p) {
    uint32_t a;
    asm("{ .reg .u64 t; cvta.to.shared.u64 t, %1; cvt.u32.u64 %0, t; }"
        : "=r"(a) : "l"(p));
    return a;
}
__device__ __forceinline__ void ldsm_x4(uint32_t r[4], uint32_t addr) {
    asm volatile("ldmatrix.sync.aligned.m8n8.x4.shared.b16 {%0,%1,%2,%3}, [%4];"
        : "=r"(r[0]), "=r"(r[1]), "=r"(r[2]), "=r"(r[3]) : "r"(addr));
}
__device__ __forceinline__ void ldsm_x4_t(uint32_t r[4], uint32_t addr) {
    asm volatile("ldmatrix.sync.aligned.m8n8.x4.trans.shared.b16 {%0,%1,%2,%3}, [%4];"
        : "=r"(r[0]), "=r"(r[1]), "=r"(r[2]), "=r"(r[3]) : "r"(addr));
}
__device__ __forceinline__ void mma_bf16(float d[4], const uint32_t a[4],
                                         const uint32_t b[2]) {
    asm volatile(
        "mma.sync.aligned.m16n8k16.row.col.f32.bf16.bf16.f32 "
        "{%0,%1,%2,%3}, {%4,%5,%6,%7}, {%8,%9}, {%0,%1,%2,%3};"
        : "+f"(d[0]), "+f"(d[1]), "+f"(d[2]), "+f"(d[3])
        : "r"(a[0]), "r"(a[1]), "r"(a[2]), "r"(a[3]), "r"(b[0]), "r"(b[1]));
}
__device__ __forceinline__ void mma_f16(float d[4], const uint32_t a[4],
                                        const uint32_t b[2]) {
    asm volatile(
        "mma.sync.aligned.m16n8k16.row.col.f32.f16.f16.f32 "
        "{%0,%1,%2,%3}, {%4,%5,%6,%7}, {%8,%9}, {%0,%1,%2,%3};"
        : "+f"(d[0]), "+f"(d[1]), "+f"(d[2]), "+f"(d[3])
        : "r"(a[0]), "r"(a[1]), "r"(a[2]), "r"(a[3]), "r"(b[0]), "r"(b[1]));
}
__device__ __forceinline__ void split_bf16(float x, __nv_bfloat16& hi,
                                           __nv_bfloat16& lo) {
    hi = __float2bfloat16_rn(x);
    lo = __float2bfloat16_rn(x - __bfloat162float(hi));
}
__device__ __forceinline__ uint32_t pack_bf2(__nv_bfloat16 a, __nv_bfloat16 b) {
    __nv_bfloat162 t = __halves2bfloat162(a, b);
    return *reinterpret_cast<uint32_t*>(&t);
}
__device__ __forceinline__ void split2(float a, float b, uint32_t& hi, uint32_t& lo) {
    __nv_bfloat16 ha, la, hb, lb;
    split_bf16(a, ha, la);
    split_bf16(b, hb, lb);
    hi = pack_bf2(ha, hb);
    lo = pack_bf2(la, lb);
}
// fp16 split (for V planes)
__device__ __forceinline__ void split2h(float a, float b, uint32_t& hi, uint32_t& lo) {
    __half ha = __float2half_rn(a);
    __half la = __float2half_rn(a - __half2float(ha));
    __half hb = __float2half_rn(b);
    __half lb = __float2half_rn(b - __half2float(hb));
    __half2 th = __halves2half2(ha, hb);
    __half2 tl = __halves2half2(la, lb);
    hi = *reinterpret_cast<uint32_t*>(&th);
    lo = *reinterpret_cast<uint32_t*>(&tl);
}
__device__ __forceinline__ uint32_t cvt_h2(float a, float b) {
    __half2 t = __floats2half2_rn(a, b);
    return *reinterpret_cast<uint32_t*>(&t);
}
__device__ __forceinline__ float ex2f(float x) {
    float y; asm("ex2.approx.ftz.f32 %0, %1;" : "=f"(y) : "f"(x)); return y;
}

#define SA_STRIDE 40
#define SB_STRIDE 136
#define SC_STRIDE 72

// =====================================================================
// One-shot weight prep.
// =====================================================================
__global__ void __launch_bounds__(256) split_all(
    const float* __restrict__ Wq, const float* __restrict__ Wk,
    const float* __restrict__ Wv, const float* __restrict__ Wout,
    const float* __restrict__ Woff1, float kscale)
{
    int idx = blockIdx.x * 256 + threadIdx.x;
    if (idx < 4 * 65536) {
        int w = idx >> 16, i = idx & 65535;
        const float* srcs[4] = {Wq, Wk, Wv, Wout};
        __nv_bfloat16* dh[4] = {w_qh, w_kh, w_vh, w_oh};
        __nv_bfloat16* dl[4] = {w_ql, w_kl, w_vl, w_ol};
        float v = srcs[w][i] * (w == 1 ? kscale : 1.0f);
        split_bf16(v, dh[w][i], dl[w][i]);
    } else {
        int i = idx - 4 * 65536;
        int o = i / 2304;
        int r = i - o * 2304;
        int c = r / 9;
        int t = r - c * 9;
        int dst = o * 2304 + t * 256 + c;
        split_bf16(Woff1[i], w_ch[dst], w_cl[dst]);
    }
}

// =====================================================================
// GEMM via mma.sync bf16-split, software-pipelined k-loop.
// =====================================================================
template<int BMODE, int OMODE>
__global__ void __launch_bounds__(256) gemm_mma(
    const __nv_bfloat16* __restrict__ Ah, const __nv_bfloat16* __restrict__ Al,
    const float* __restrict__ Bf,
    const __nv_bfloat16* __restrict__ Bh, const __nv_bfloat16* __restrict__ Bl,
    const float* __restrict__ bias,
    float* __restrict__ Yf,
    __nv_bfloat16* __restrict__ Yh, __nv_bfloat16* __restrict__ Yl,
    float yscale, int Cin)
{
    __shared__ __align__(16) __nv_bfloat16 sA[2][128][SA_STRIDE];
    __shared__ __align__(16) __nv_bfloat16 sB[2][32][SB_STRIDE];
    const int b  = blockIdx.z;
    const int o0 = blockIdx.y * 128;
    const int p0 = blockIdx.x * 128;
    const int O  = gridDim.y * 128;
    const size_t bB = (size_t)b * Cin * Pn;
    const size_t bY = (size_t)b * O * Pn;
    const int tid  = threadIdx.x;
    const int lane = tid & 31;
    const int wid  = tid >> 5;
    const int wm   = wid & 3;
    const int wn   = wid >> 2;

    float d[2][8][4];
    #pragma unroll
    for (int mf = 0; mf < 2; mf++)
        #pragma unroll
        for (int nf = 0; nf < 8; nf++)
            #pragma unroll
            for (int i = 0; i < 4; i++) d[mf][nf][i] = 0.0f;

    const int a_row  = (lane & 7) + ((lane >> 3) & 1) * 8;
    const int a_colk = ((lane >> 4) & 1) * 8;
    const int b_rowk = (lane & 7) + ((lane >> 3) & 1) * 8;
    const int b_ncol = ((lane >> 4) & 1) * 8;

    uint4  ra[2][2];
    float4 rbf[4];
    uint4  rb[2][2];

    auto loadA = [&](int c0) {
        #pragma unroll
        for (int t = 0; t < 2; t++) {
            const __nv_bfloat16* Ap = t ? Al : Ah;
            #pragma unroll
            for (int i = 0; i < 2; i++) {
                int e = tid + i * 256;
                int o = e >> 2, c8 = (e & 3) * 8;
                ra[t][i] = *reinterpret_cast<const uint4*>(
                    Ap + (size_t)(o0 + o) * Cin + c0 + c8);
            }
        }
    };
    auto storeA = [&]() {
        #pragma unroll
        for (int t = 0; t < 2; t++)
            #pragma unroll
            for (int i = 0; i < 2; i++) {
                int e = tid + i * 256;
                int o = e >> 2, c8 = (e & 3) * 8;
                *reinterpret_cast<uint4*>(&sA[t][o][c8]) = ra[t][i];
            }
    };
    auto loadB = [&](int c0) {
        if (BMODE == 0) {
            #pragma unroll
            for (int i = 0; i < 4; i++) {
                int e = tid + i * 256;
                int k = e >> 5, p4 = (e & 31) * 4;
                rbf[i] = *reinterpret_cast<const float4*>(
                    Bf + bB + (size_t)(c0 + k) * Pn + p0 + p4);
            }
        } else {
            #pragma unroll
            for (int t = 0; t < 2; t++) {
                const __nv_bfloat16* Bp = t ? Bl : Bh;
                #pragma unroll
                for (int i = 0; i < 2; i++) {
                    int e = tid + i * 256;
                    int k = e >> 4, p8 = (e & 15) * 8;
                    rb[t][i] = *reinterpret_cast<const uint4*>(
                        Bp + bB + (size_t)(c0 + k) * Pn + p0 + p8);
                }
            }
        }
    };
    auto storeB = [&]() {
        if (BMODE == 0) {
            #pragma unroll
            for (int i = 0; i < 4; i++) {
                int e = tid + i * 256;
                int k = e >> 5, p4 = (e & 31) * 4;
                float4 x = rbf[i];
                __nv_bfloat16 h0, l0, h1, l1, h2, l2, h3, l3;
                split_bf16(x.x, h0, l0); split_bf16(x.y, h1, l1);
                split_bf16(x.z, h2, l2); split_bf16(x.w, h3, l3);
                *reinterpret_cast<__nv_bfloat162*>(&sB[0][k][p4])     = __halves2bfloat162(h0, h1);
                *reinterpret_cast<__nv_bfloat162*>(&sB[0][k][p4 + 2]) = __halves2bfloat162(h2, h3);
                *reinterpret_cast<__nv_bfloat162*>(&sB[1][k][p4])     = __halves2bfloat162(l0, l1);
                *reinterpret_cast<__nv_bfloat162*>(&sB[1][k][p4 + 2]) = __halves2bfloat162(l2, l3);
            }
        } else {
            #pragma unroll
            for (int t = 0; t < 2; t++)
                #pragma unroll
                for (int i = 0; i < 2; i++) {
                    int e = tid + i * 256;
                    int k = e >> 4, p8 = (e & 15) * 8;
                    *reinterpret_cast<uint4*>(&sB[t][k][p8]) = rb[t][i];
                }
        }
    };

    loadA(0); loadB(0);
    storeA(); storeB();
    __syncthreads();

    for (int c0 = 0; c0 < Cin; c0 += 32) {
        bool more = (c0 + 32 < Cin);
        if (more) { loadA(c0 + 32); loadB(c0 + 32); }

        #pragma unroll
        for (int kk = 0; kk < 32; kk += 16) {
            uint32_t afr[2][2][4];
            #pragma unroll
            for (int t2 = 0; t2 < 2; t2++)
                #pragma unroll
                for (int mf = 0; mf < 2; mf++)
                    ldsm_x4(afr[t2][mf],
                        smem_u32(&sA[t2][wm * 32 + mf * 16 + a_row][kk + a_colk]));
            uint32_t bfr[2][8][2];
            #pragma unroll
            for (int t2 = 0; t2 < 2; t2++)
                #pragma unroll
                for (int nf2 = 0; nf2 < 4; nf2++) {
                    uint32_t r[4];
                    ldsm_x4_t(r, smem_u32(
                        &sB[t2][kk + b_rowk][wn * 64 + nf2 * 16 + b_ncol]));
                    bfr[t2][2 * nf2][0] = r[0]; bfr[t2][2 * nf2][1] = r[1];
                    bfr[t2][2 * nf2 + 1][0] = r[2]; bfr[t2][2 * nf2 + 1][1] = r[3];
                }
            #pragma unroll
            for (int mf = 0; mf < 2; mf++)
                #pragma unroll
                for (int nf = 0; nf < 8; nf++) {
                    mma_bf16(d[mf][nf], afr[0][mf], bfr[0][nf]);
                    mma_bf16(d[mf][nf], afr[0][mf], bfr[1][nf]);
                    mma_bf16(d[mf][nf], afr[1][mf], bfr[0][nf]);
                }
        }
        __syncthreads();
        if (more) { storeA(); storeB(); __syncthreads(); }
    }

    #pragma unroll
    for (int mf = 0; mf < 2; mf++) {
        int r = o0 + wm * 32 + mf * 16 + (lane >> 2);
        float b0v = bias ? bias[r] : 0.0f;
        float b1v = bias ? bias[r + 8] : 0.0f;
        #pragma unroll
        for (int nf = 0; nf < 8; nf++) {
            int cb = p0 + wn * 64 + nf * 8 + (lane & 3) * 2;
            float v00 = d[mf][nf][0] + b0v, v01 = d[mf][nf][1] + b0v;
            float v10 = d[mf][nf][2] + b1v, v11 = d[mf][nf][3] + b1v;
            if (OMODE & 1) {
                *reinterpret_cast<float2*>(Yf + bY + (size_t)r * Pn + cb) =
                    make_float2(v00, v01);
                *reinterpret_cast<float2*>(Yf + bY + (size_t)(r + 8) * Pn + cb) =
                    make_float2(v10, v11);
            }
            if (OMODE & 2) {
                uint32_t h0, l0, h1, l1;
                split2(v00 * yscale, v01 * yscale, h0, l0);
                split2(v10 * yscale, v11 * yscale, h1, l1);
                *reinterpret_cast<uint32_t*>(Yh + bY + (size_t)r * Pn + cb)       = h0;
                *reinterpret_cast<uint32_t*>(Yl + bY + (size_t)r * Pn + cb)       = l0;
                *reinterpret_cast<uint32_t*>(Yh + bY + (size_t)(r + 8) * Pn + cb) = h1;
                *reinterpret_cast<uint32_t*>(Yl + bY + (size_t)(r + 8) * Pn + cb) = l1;
            }
        }
    }
}

// =====================================================================
// Fused K+V projection. K -> bf16 planes; V -> fp16 planes.
// grid (8, 4, 8), 256 threads: warps 0-3 -> K, warps 4-7 -> V.
// =====================================================================
__global__ void __launch_bounds__(256) gemm_kv()
{
    __shared__ __align__(16) __nv_bfloat16 sAk[2][64][SA_STRIDE];
    __shared__ __align__(16) __nv_bfloat16 sAv[2][64][SA_STRIDE];
    __shared__ __align__(16) __nv_bfloat16 sB[2][32][SB_STRIDE];
    const int b  = blockIdx.z;
    const int o0 = blockIdx.y * 64;
    const int p0 = blockIdx.x * 128;
    const size_t bB = (size_t)b * Cn * Pn;
    const int tid  = threadIdx.x;
    const int lane = tid & 31;
    const int wid  = tid >> 5;
    const int half = wid >> 2;
    const int w2   = wid & 3;
    const int wm   = w2 & 1;
    const int wn   = w2 >> 1;

    float d[2][8][4];
    #pragma unroll
    for (int mf = 0; mf < 2; mf++)
        #pragma unroll
        for (int nf = 0; nf < 8; nf++)
            #pragma unroll
            for (int i = 0; i < 4; i++) d[mf][nf][i] = 0.0f;

    const int a_row  = (lane & 7) + ((lane >> 3) & 1) * 8;
    const int a_colk = ((lane >> 4) & 1) * 8;
    const int b_rowk = (lane & 7) + ((lane >> 3) & 1) * 8;
    const int b_ncol = ((lane >> 4) & 1) * 8;

    const int ao = tid >> 2, ac8 = (tid & 3) * 8;
    uint4 ra[4];
    uint4 rb[2][2];
    auto loadA = [&](int c0) {
        size_t off = (size_t)(o0 + ao) * Cn + c0 + ac8;
        ra[0] = *reinterpret_cast<const uint4*>(w_kh + off);
        ra[1] = *reinterpret_cast<const uint4*>(w_kl + off);
        ra[2] = *reinterpret_cast<const uint4*>(w_vh + off);
        ra[3] = *reinterpret_cast<const uint4*>(w_vl + off);
    };
    auto storeA = [&]() {
        *reinterpret_cast<uint4*>(&sAk[0][ao][ac8]) = ra[0];
        *reinterpret_cast<uint4*>(&sAk[1][ao][ac8]) = ra[1];
        *reinterpret_cast<uint4*>(&sAv[0][ao][ac8]) = ra[2];
        *reinterpret_cast<uint4*>(&sAv[1][ao][ac8]) = ra[3];
    };
    auto loadB = [&](int c0) {
        #pragma unroll
        for (int t = 0; t < 2; t++) {
            const __nv_bfloat16* Bp = t ? g_sl : g_sh;
            #pragma unroll
            for (int i = 0; i < 2; i++) {
                int e = tid + i * 256;
                int k = e >> 4, p8 = (e & 15) * 8;
                rb[t][i] = *reinterpret_cast<const uint4*>(
                    Bp + bB + (size_t)(c0 + k) * Pn + p0 + p8);
            }
        }
    };
    auto storeB = [&]() {
        #pragma unroll
        for (int t = 0; t < 2; t++)
            #pragma unroll
            for (int i = 0; i < 2; i++) {
                int e = tid + i * 256;
                int k = e >> 4, p8 = (e & 15) * 8;
                *reinterpret_cast<uint4*>(&sB[t][k][p8]) = rb[t][i];
            }
    };

    loadA(0); loadB(0);
    storeA(); storeB();
    __syncthreads();

    for (int c0 = 0; c0 < Cn; c0 += 32) {
        bool more = (c0 + 32 < Cn);
        if (more) { loadA(c0 + 32); loadB(c0 + 32); }

        #pragma unroll
        for (int kk = 0; kk < 32; kk += 16) {
            uint32_t afr[2][2][4];
            #pragma unroll
            for (int t2 = 0; t2 < 2; t2++)
                #pragma unroll
                for (int mf = 0; mf < 2; mf++) {
                    const __nv_bfloat16* base = half
                        ? &sAv[t2][wm * 32 + mf * 16 + a_row][kk + a_colk]
                        : &sAk[t2][wm * 32 + mf * 16 + a_row][kk + a_colk];
                    ldsm_x4(afr[t2][mf], smem_u32(base));
                }
            uint32_t bfr[2][8][2];
            #pragma unroll
            for (int t2 = 0; t2 < 2; t2++)
                #pragma unroll
                for (int nf2 = 0; nf2 < 4; nf2++) {
                    uint32_t r[4];
                    ldsm_x4_t(r, smem_u32(
                        &sB[t2][kk + b_rowk][wn * 64 + nf2 * 16 + b_ncol]));
                    bfr[t2][2 * nf2][0] = r[0]; bfr[t2][2 * nf2][1] = r[1];
                    bfr[t2][2 * nf2 + 1][0] = r[2]; bfr[t2][2 * nf2 + 1][1] = r[3];
                }
            #pragma unroll
            for (int mf = 0; mf < 2; mf++)
                #pragma unroll
                for (int nf = 0; nf < 8; nf++) {
                    mma_bf16(d[mf][nf], afr[0][mf], bfr[0][nf]);
                    mma_bf16(d[mf][nf], afr[0][mf], bfr[1][nf]);
                    mma_bf16(d[mf][nf], afr[1][mf], bfr[0][nf]);
                }
        }
        __syncthreads();
        if (more) { storeA(); storeB(); __syncthreads(); }
    }

    #pragma unroll
    for (int mf = 0; mf < 2; mf++) {
        int r = o0 + wm * 32 + mf * 16 + (lane >> 2);
        #pragma unroll
        for (int nf = 0; nf < 8; nf++) {
            int cb = p0 + wn * 64 + nf * 8 + (lane & 3) * 2;
            uint32_t h0, l0, h1, l1;
            if (half == 0) {
                split2(d[mf][nf][0], d[mf][nf][1], h0, l0);
                split2(d[mf][nf][2], d[mf][nf][3], h1, l1);
                *reinterpret_cast<uint32_t*>(g_kh + bB + (size_t)r * Pn + cb)       = h0;
                *reinterpret_cast<uint32_t*>(g_kl + bB + (size_t)r * Pn + cb)       = l0;
                *reinterpret_cast<uint32_t*>(g_kh + bB + (size_t)(r + 8) * Pn + cb) = h1;
                *reinterpret_cast<uint32_t*>(g_kl + bB + (size_t)(r + 8) * Pn + cb) = l1;
            } else {
                split2h(d[mf][nf][0], d[mf][nf][1], h0, l0);
                split2h(d[mf][nf][2], d[mf][nf][3], h1, l1);
                *reinterpret_cast<uint32_t*>(g_vh + bB + (size_t)r * Pn + cb)       = h0;
                *reinterpret_cast<uint32_t*>(g_vl + bB + (size_t)r * Pn + cb)       = l0;
                *reinterpret_cast<uint32_t*>(g_vh + bB + (size_t)(r + 8) * Pn + cb) = h1;
                *reinterpret_cast<uint32_t*>(g_vl + bB + (size_t)(r + 8) * Pn + cb) = l1;
            }
        }
    }
}

// =====================================================================
// Conv as GEMM with FUSED shift. splitK=2. grid (16, 2, 8), 256 thr.
// =====================================================================
__global__ void __launch_bounds__(256) conv_mma3()
{
    __shared__ __align__(16) __nv_bfloat16 sA[2][128][SA_STRIDE];
    __shared__ __align__(16) __nv_bfloat16 sB[2][32][SC_STRIDE];
    const int b  = blockIdx.z;
    const int ks = blockIdx.y;
    const int p0 = blockIdx.x * 64;
    float* Yb = (ks ? g_h1b : g_h1a) + (size_t)b * 128 * Pn;
    const size_t bQ = (size_t)b * Cn * Pn;
    const int tid  = threadIdx.x;
    const int lane = tid & 31;
    const int wid  = tid >> 5;
    const int wm   = wid & 3;
    const int wn   = wid >> 2;

    float d[2][4][4];
    #pragma unroll
    for (int mf = 0; mf < 2; mf++)
        #pragma unroll
        for (int nf = 0; nf < 4; nf++)
            #pragma unroll
            for (int i = 0; i < 4; i++) d[mf][nf][i] = 0.0f;

    const int a_row  = (lane & 7) + ((lane >> 3) & 1) * 8;
    const int a_colk = ((lane >> 4) & 1) * 8;
    const int b_rowk = (lane & 7) + ((lane >> 3) & 1) * 8;
    const int b_ncol = ((lane >> 4) & 1) * 8;

    uint4 ra[2][2], rb[2];
    auto loadA = [&](int c0) {
        #pragma unroll
        for (int t = 0; t < 2; t++) {
            const __nv_bfloat16* Ap = t ? w_cl : w_ch;
            #pragma unroll
            for (int i = 0; i < 2; i++) {
                int e = tid + i * 256;
                int o = e >> 2, c8 = (e & 3) * 8;
                ra[t][i] = *reinterpret_cast<const uint4*>(
                    Ap + (size_t)o * 2304 + c0 + c8);
            }
        }
    };
    auto storeA = [&]() {
        #pragma unroll
        for (int t = 0; t < 2; t++)
            #pragma unroll
            for (int i = 0; i < 2; i++) {
                int e = tid + i * 256;
                int o = e >> 2, c8 = (e & 3) * 8;
                *reinterpret_cast<uint4*>(&sA[t][o][c8]) = ra[t][i];
            }
    };
    const int bk = tid >> 3, bp8 = (tid & 7) * 8;
    const int P  = p0 + bp8;
    const int x0 = P & 31;
    const int yb = P >> 5;
    auto loadB = [&](int c0) {
        int t  = c0 >> 8;
        int cc = (c0 & 255) + bk;
        int ty = t / 3;
        int dy = ty - 1;
        int dx = t - ty * 3 - 1;
        int ys = yb + dy;
        bool yok = (unsigned)ys < 32u;
        size_t rowoff = bQ + (size_t)cc * Pn + ys * 32;
        #pragma unroll
        for (int pl = 0; pl < 2; pl++) {
            const __nv_bfloat16* Qp = pl ? g_ql : g_qh;
            uint4 v = make_uint4(0u, 0u, 0u, 0u);
            if (yok) {
                uint4 w = *reinterpret_cast<const uint4*>(Qp + rowoff + x0);
                if (dx == 0) {
                    v = w;
                } else if (dx > 0) {
                    uint32_t extra = 0;
                    if (x0 != 24)
                        extra = *reinterpret_cast<const uint16_t*>(
                            Qp + rowoff + x0 + 8);
                    v.x = __funnelshift_r(w.x, w.y, 16);
                    v.y = __funnelshift_r(w.y, w.z, 16);
                    v.z = __funnelshift_r(w.z, w.w, 16);
                    v.w = (w.w >> 16) | (extra << 16);
                } else {
                    uint32_t extra = 0;
                    if (x0 != 0)
                        extra = *reinterpret_cast<const uint16_t*>(
                            Qp + rowoff + x0 - 1);
                    v.x = (w.x << 16) | extra;
                    v.y = __funnelshift_l(w.x, w.y, 16);
                    v.z = __funnelshift_l(w.y, w.z, 16);
                    v.w = __funnelshift_l(w.z, w.w, 16);
                }
            }
            rb[pl] = v;
        }
    };
    auto storeB = [&]() {
        *reinterpret_cast<uint4*>(&sB[0][bk][bp8]) = rb[0];
        *reinterpret_cast<uint4*>(&sB[1][bk][bp8]) = rb[1];
    };

    const int cbeg = ks * 1152, cend = cbeg + 1152;
    loadA(cbeg); loadB(cbeg);
    storeA(); storeB();
    __syncthreads();

    for (int c0 = cbeg; c0 < cend; c0 += 32) {
        bool more = (c0 + 32 < cend);
        if (more) { loadA(c0 + 32); loadB(c0 + 32); }

        #pragma unroll
        for (int kk = 0; kk < 32; kk += 16) {
            uint32_t afr[2][2][4];
            #pragma unroll
            for (int t2 = 0; t2 < 2; t2++)
                #pragma unroll
                for (int mf = 0; mf < 2; mf++)
                    ldsm_x4(afr[t2][mf],
                        smem_u32(&sA[t2][wm * 32 + mf * 16 + a_row][kk + a_colk]));
            uint32_t bfr[2][4][2];
            #pragma unroll
            for (int t2 = 0; t2 < 2; t2++)
                #pragma unroll
                for (int nf2 = 0; nf2 < 2; nf2++) {
                    uint32_t r[4];
                    ldsm_x4_t(r, smem_u32(
                        &sB[t2][kk + b_rowk][wn * 32 + nf2 * 16 + b_ncol]));
                    bfr[t2][2 * nf2][0] = r[0]; bfr[t2][2 * nf2][1] = r[1];
                    bfr[t2][2 * nf2 + 1][0] = r[2]; bfr[t2][2 * nf2 + 1][1] = r[3];
                }
            #pragma unroll
            for (int mf = 0; mf < 2; mf++)
                #pragma unroll
                for (int nf = 0; nf < 4; nf++) {
                    mma_bf16(d[mf][nf], afr[0][mf], bfr[0][nf]);
                    mma_bf16(d[mf][nf], afr[0][mf], bfr[1][nf]);
                    mma_bf16(d[mf][nf], afr[1][mf], bfr[0][nf]);
                }
        }
        __syncthreads();
        if (more) { storeA(); storeB(); __syncthreads(); }
    }
    #pragma unroll
    for (int mf = 0; mf < 2; mf++) {
        int r = wm * 32 + mf * 16 + (lane >> 2);
        #pragma unroll
        for (int nf = 0; nf < 4; nf++) {
            int cb = p0 + wn * 32 + nf * 8 + (lane & 3) * 2;
            *reinterpret_cast<float2*>(Yb + (size_t)r * Pn + cb) =
                make_float2(d[mf][nf][0], d[mf][nf][1]);
            *reinterpret_cast<float2*>(Yb + (size_t)(r + 8) * Pn + cb) =
                make_float2(d[mf][nf][2], d[mf][nf][3]);
        }
    }
}

// =====================================================================
// Offsets, 8-way channel split. grid (32, 8), 256 threads.
// =====================================================================
__global__ void __launch_bounds__(256) offs_kernel3(
    const float* __restrict__ Woff2, const float* __restrict__ boff2,
    const float* __restrict__ boff1)
{
    __shared__ float red[2][8][32];
    const int b   = blockIdx.y;
    const int px  = threadIdx.x & 31;
    const int seg = threadIdx.x >> 5;
    const int p   = blockIdx.x * 32 + px;
    const float* h1a = g_h1a + (size_t)b * 128 * Pn;
    const float* h1b = g_h1b + (size_t)b * 128 * Pn;
    const int c0 = seg * 16;
    float ox[4] = {0, 0, 0, 0}, oy[4] = {0, 0, 0, 0};
    #pragma unroll
    for (int c = c0; c < c0 + 16; c += 4) {
        #pragma unroll
        for (int j = 0; j < 4; j++) {
            size_t i = (size_t)(c + j) * Pn + p;
            float h = fmaxf(h1a[i] + h1b[i] + boff1[c + j], 0.0f);
            ox[j] += Woff2[c + j] * h;
            oy[j] += Woff2[128 + c + j] * h;
        }
    }
    red[0][seg][px] = (ox[0] + ox[1]) + (ox[2] + ox[3]);
    red[1][seg][px] = (oy[0] + oy[1]) + (oy[2] + oy[3]);
    __syncthreads();
    if (seg == 0) {
        float sx = boff2[0], sy = boff2[1];
        #pragma unroll
        for (int s = 0; s < 8; s++) { sx += red[0][s][px]; sy += red[1][s][px]; }
        g_off[((size_t)b * 2 + 0) * Pn + p] = sx * 0.1f;
        g_off[((size_t)b * 2 + 1) * Pn + p] = sy * 0.1f;
    }
}

// =====================================================================
// Bilinear grid sample -> split planes. grid (4, 8, 16).
// =====================================================================
__global__ void __launch_bounds__(256) samp_kernel(const float* __restrict__ kv)
{
    const int b  = blockIdx.y;
    const int p  = blockIdx.x * 256 + threadIdx.x;
    const int c0 = blockIdx.z * 16;
    float ox = g_off[((size_t)b * 2 + 0) * Pn + p];
    float oy = g_off[((size_t)b * 2 + 1) * Pn + p];
    int px = p & 31, py = p >> 5;
    float gx = -1.0f + px * (2.0f / 31.0f);
    float gy = -1.0f + py * (2.0f / 31.0f);
    float x = (gx + ox + 1.0f) * 0.5f * 31.0f;
    float y = (gy + oy + 1.0f) * 0.5f * 31.0f;
    x = fminf(fmaxf(x, 0.0f), 31.0f);
    y = fminf(fmaxf(y, 0.0f), 31.0f);
    float x0f = floorf(x), y0f = floorf(y);
    float wx = x - x0f, wy = y - y0f;
    int x0 = (int)x0f, y0 = (int)y0f;
    int x1 = min(x0 + 1, 31), y1 = min(y0 + 1, 31);
    float w00 = (1.0f - wx) * (1.0f - wy);
    float w01 = wx * (1.0f - wy);
    float w10 = (1.0f - wx) * wy;
    float w11 = wx * wy;
    int i00 = (y0 << 5) + x0, i01 = (y0 << 5) + x1;
    int i10 = (y1 << 5) + x0, i11 = (y1 << 5) + x1;
    const float* kvb = kv + (size_t)b * Cn * Pn;
    const size_t ob = (size_t)b * Cn * Pn;
    #pragma unroll 4
    for (int c = c0; c < c0 + 16; c++) {
        const float* pl = kvb + (size_t)c * Pn;
        float v = w00 * pl[i00] + w01 * pl[i01] + w10 * pl[i10] + w11 * pl[i11];
        __nv_bfloat16 h, l;
        split_bf16(v, h, l);
        g_sh[ob + (size_t)c * Pn + p] = h;
        g_sl[ob + (size_t)c * Pn + p] = l;
    }
}

// =====================================================================
// Flash attention on tensor cores, pipelined KV loads.
// QK: bf16-split (3 mma). PV: fp16 P (single plane, 2^-12 rounding)
// x fp16 V hi/lo planes -> 2 mma, error ~1e-4. grid (8, 64), 256 thr.
// =====================================================================
__global__ void __launch_bounds__(256) attn_mma()
{
    __shared__ __align__(16) __nv_bfloat16 sK[2][32][SB_STRIDE];
    __shared__ __align__(16) __half        sV[2][32][SB_STRIDE];

    const int bh = blockIdx.y;
    const int b  = bh >> 3, h = bh & 7;
    const int p0 = blockIdx.x * 128;
    const int tid  = threadIdx.x;
    const int lane = tid & 31;
    const int wm   = tid >> 5;
    const size_t base = ((size_t)b * Cn + h * HD) * Pn;

    const int krow = (lane & 7) + ((lane >> 3) & 1) * 8;
    const int ncol = ((lane >> 4) & 1) * 8;

    #pragma unroll
    for (int t = 0; t < 2; t++) {
        const __nv_bfloat16* Qp = (t ? g_ql : g_qh) + base;
        #pragma unroll
        for (int i = 0; i < 2; i++) {
            int e = tid + i * 256;
            int d = e >> 4, p8 = (e & 15) * 8;
            uint4 v = *reinterpret_cast<const uint4*>(Qp + (size_t)d * Pn + p0 + p8);
            *reinterpret_cast<uint4*>(&sK[t][d][p8]) = v;
        }
    }
    __syncthreads();
    uint32_t aQ[2][2][4];
    #pragma unroll
    for (int t = 0; t < 2; t++)
        #pragma unroll
        for (int ks = 0; ks < 2; ks++) {
            uint32_t r[4];
            ldsm_x4_t(r, smem_u32(&sK[t][ks * 16 + krow][wm * 16 + ncol]));
            aQ[t][ks][0] = r[0]; aQ[t][ks][1] = r[2];
            aQ[t][ks][2] = r[1]; aQ[t][ks][3] = r[3];
        }

    float O[4][4];
    #pragma unroll
    for (int nf = 0; nf < 4; nf++)
        #pragma unroll
        for (int i = 0; i < 4; i++) O[nf][i] = 0.0f;
    float lsum0 = 0.0f, lsum1 = 0.0f;

    const int vrow = (lane & 7) + ((lane >> 3) & 1) * 8;
    const int vcol = ((lane >> 4) & 1) * 8;

    const int ld_d  = tid >> 4;
    const int ld_p8 = (tid & 15) * 8;
    uint4 rk[2][2], rv[2][2];
    auto loadKV = [&](int kv0) {
        #pragma unroll
        for (int t = 0; t < 2; t++) {
            const __nv_bfloat16* Kp = (t ? g_kl : g_kh) + base;
            const __half*        Vp = (t ? g_vl : g_vh) + base;
            #pragma unroll
            for (int i = 0; i < 2; i++) {
                int d = ld_d + i * 16;
                rk[t][i] = *reinterpret_cast<const uint4*>(
                    Kp + (size_t)d * Pn + kv0 + ld_p8);
                rv[t][i] = *reinterpret_cast<const uint4*>(
                    Vp + (size_t)d * Pn + kv0 + ld_p8);
            }
        }
    };
    auto storeKV = [&]() {
        #pragma unroll
        for (int t = 0; t < 2; t++)
            #pragma unroll
            for (int i = 0; i < 2; i++) {
                int d = ld_d + i * 16;
                *reinterpret_cast<uint4*>(&sK[t][d][ld_p8]) = rk[t][i];
                *reinterpret_cast<uint4*>(&sV[t][d][ld_p8]) = rv[t][i];
            }
    };

    loadKV(0);

    for (int kt = 0; kt < 8; kt++) {
        __syncthreads();
        storeKV();
        __syncthreads();
        if (kt + 1 < 8) loadKV((kt + 1) * 128);

        float S[16][4];
        #pragma unroll
        for (int f = 0; f < 16; f++)
            #pragma unroll
            for (int i = 0; i < 4; i++) S[f][i] = 0.0f;

        #pragma unroll
        for (int nb = 0; nb < 8; nb++) {
            uint32_t bk[2][2][4];
            #pragma unroll
            for (int t = 0; t < 2; t++)
                #pragma unroll
                for (int ks = 0; ks < 2; ks++)
                    ldsm_x4_t(bk[t][ks],
                        smem_u32(&sK[t][ks * 16 + krow][nb * 16 + ncol]));
            #pragma unroll
            for (int half = 0; half < 2; half++) {
                float* s = S[nb * 2 + half];
                #pragma unroll
                for (int ks = 0; ks < 2; ks++) {
                    uint32_t bhi[2] = {bk[0][ks][2 * half], bk[0][ks][2 * half + 1]};
                    uint32_t blo[2] = {bk[1][ks][2 * half], bk[1][ks][2 * half + 1]};
                    mma_bf16(s, aQ[0][ks], bhi);
                    mma_bf16(s, aQ[1][ks], bhi);
                    mma_bf16(s, aQ[0][ks], blo);
                }
            }
        }
        #pragma unroll
        for (int f = 0; f < 16; f++) {
            S[f][0] = ex2f(S[f][0]); S[f][1] = ex2f(S[f][1]);
            S[f][2] = ex2f(S[f][2]); S[f][3] = ex2f(S[f][3]);
            lsum0 += S[f][0] + S[f][1];
            lsum1 += S[f][2] + S[f][3];
        }
        #pragma unroll
        for (int ks8 = 0; ks8 < 8; ks8++) {
            uint32_t ah[4];
            const float* f0 = S[2 * ks8];
            const float* f1 = S[2 * ks8 + 1];
            ah[0] = cvt_h2(f0[0], f0[1]);
            ah[1] = cvt_h2(f0[2], f0[3]);
            ah[2] = cvt_h2(f1[0], f1[1]);
            ah[3] = cvt_h2(f1[2], f1[3]);
            uint32_t bv[2][2][4];
            #pragma unroll
            for (int t = 0; t < 2; t++)
                #pragma unroll
                for (int db = 0; db < 2; db++)
                    ldsm_x4(bv[t][db],
                        smem_u32(&sV[t][db * 16 + vrow][ks8 * 16 + vcol]));
            #pragma unroll
            for (int nf = 0; nf < 4; nf++) {
                int db = nf >> 1, wh = nf & 1;
                uint32_t vhi[2] = {bv[0][db][wh], bv[0][db][wh + 2]};
                uint32_t vlo[2] = {bv[1][db][wh], bv[1][db][wh + 2]};
                mma_f16(O[nf], ah, vhi);
                mma_f16(O[nf], ah, vlo);
            }
        }
    }
    lsum0 += __shfl_xor_sync(0xffffffffu, lsum0, 1);
    lsum0 += __shfl_xor_sync(0xffffffffu, lsum0, 2);
    lsum1 += __shfl_xor_sync(0xffffffffu, lsum1, 1);
    lsum1 += __shfl_xor_sync(0xffffffffu, lsum1, 2);
    float inv0 = 1.0f / lsum0, inv1 = 1.0f / lsum1;
    int p = p0 + wm * 16 + (lane >> 2);
    #pragma unroll
    for (int nf = 0; nf < 4; nf++) {
        int d = nf * 8 + (lane & 3) * 2;
        float v0 = O[nf][0] * inv0, v1 = O[nf][1] * inv0;
        float v2 = O[nf][2] * inv1, v3 = O[nf][3] * inv1;
        __nv_bfloat16 hh, ll;
        split_bf16(v0, hh, ll);
        g_oh[base + (size_t)d * Pn + p] = hh;       g_ol[base + (size_t)d * Pn + p] = ll;
        split_bf16(v1, hh, ll);
        g_oh[base + (size_t)(d + 1) * Pn + p] = hh; g_ol[base + (size_t)(d + 1) * Pn + p] = ll;
        split_bf16(v2, hh, ll);
        g_oh[base + (size_t)d * Pn + p + 8] = hh;   g_ol[base + (size_t)d * Pn + p + 8] = ll;
        split_bf16(v3, hh, ll);
        g_oh[base + (size_t)(d + 1) * Pn + p + 8] = hh;
        g_ol[base + (size_t)(d + 1) * Pn + p + 8] = ll;
    }
}

// =====================================================================
extern "C" void kernel_launch(void* const* d_in, const int* in_sizes, int n_in,
                              void* d_out, int out_size)
{
    (void)in_sizes; (void)n_in; (void)out_size;
    const float* query_map = (const float*)d_in[0];
    const float* kv_map    = (const float*)d_in[1];
    const float* Wq        = (const float*)d_in[2];
    const float* Wk        = (const float*)d_in[3];
    const float* Wv        = (const float*)d_in[4];
    const float* Woff1     = (const float*)d_in[5];
    const float* boff1     = (const float*)d_in[6];
    const float* Woff2     = (const float*)d_in[7];
    const float* boff2     = (const float*)d_in[8];
    const float* Wout      = (const float*)d_in[9];
    const float* bout      = (const float*)d_in[10];
    float* out = (float*)d_out;

    const float kscale = 0.17677669529663687f * 1.4426950408889634f;

    __nv_bfloat16 *pqh, *pql, *poh, *pol;
    __nv_bfloat16 *pwqh, *pwql, *pwoh, *pwol;
    cudaGetSymbolAddress((void**)&pqh, g_qh);  cudaGetSymbolAddress((void**)&pql, g_ql);
    cudaGetSymbolAddress((void**)&poh, g_oh);  cudaGetSymbolAddress((void**)&pol, g_ol);
    cudaGetSymbolAddress((void**)&pwqh, w_qh); cudaGetSymbolAddress((void**)&pwql, w_ql);
    cudaGetSymbolAddress((void**)&pwoh, w_oh); cudaGetSymbolAddress((void**)&pwol, w_ol);

    // 0) one-shot weight prep
    split_all<<<2176, 256>>>(Wq, Wk, Wv, Wout, Woff1, kscale);
    // 1) q projection -> split planes
    gemm_mma<0, 2><<<dim3(8, 2, 8), 256>>>(
        pwqh, pwql, query_map, nullptr, nullptr, nullptr,
        nullptr, pqh, pql, 1.0f, 256);
    // 2) conv GEMM with fused shift (splitK=2)
    conv_mma3<<<dim3(16, 2, 8), 256>>>();
    // 3) offsets — 8-way split reduction
    offs_kernel3<<<dim3(32, 8), 256>>>(Woff2, boff2, boff1);
    // 4) bilinear sample -> split planes
    samp_kernel<<<dim3(4, 8, 16), 256>>>(kv_map);
    // 5) fused K+V projections (V -> fp16 planes)
    gemm_kv<<<dim3(8, 4, 8), 256>>>();
    // 6) attention (pipelined; fp16 PV, restored precision margin)
    attn_mma<<<dim3(8, 64), 256>>>();
    // 7) out = Wout @ attn_out + bout
    gemm_mma<1, 1><<<dim3(8, 2, 8), 256>>>(
        pwoh, pwol, nullptr, poh, pol, bout,
        out, nullptr, nullptr, 1.0f, 256);
}

// round 15
// speedup vs baseline: 1.3573x; 1.0814x over previous
#include <cuda_runtime.h>
#include <cuda_bf16.h>
#include <cuda_fp16.h>
#include <cstdint>

#define Bn 8
#define Cn 256
#define Pn 1024
#define HEADS 8
#define HD 32

// ---- fp32 scratch ----
__device__ float g_h1a[Bn*128*Pn];  // conv partial sums (splitK halves)
__device__ float g_h1b[Bn*128*Pn];
__device__ float g_off[Bn*2*Pn];

// ---- interchange planes ----
__device__ __nv_bfloat16 g_qh[Bn*Cn*Pn], g_ql[Bn*Cn*Pn];   // unscaled q (bf16)
__device__ __half        g_kf[Bn*Cn*Pn];                   // K fp16 single plane (scale folded)
__device__ __half        g_vh[Bn*Cn*Pn], g_vl[Bn*Cn*Pn];   // V fp16 split
__device__ __nv_bfloat16 g_sh[Bn*Cn*Pn], g_sl[Bn*Cn*Pn];   // sampled kv (bf16)
__device__ __nv_bfloat16 g_oh[Bn*Cn*Pn], g_ol[Bn*Cn*Pn];   // attn out (bf16)

// ---- pre-split weights (bf16) ----
__device__ __nv_bfloat16 w_qh[Cn*Cn], w_ql[Cn*Cn];
__device__ __nv_bfloat16 w_kh[Cn*Cn], w_kl[Cn*Cn];         // pre-scaled by qscale
__device__ __nv_bfloat16 w_vh[Cn*Cn], w_vl[Cn*Cn];
__device__ __nv_bfloat16 w_oh[Cn*Cn], w_ol[Cn*Cn];
__device__ __nv_bfloat16 w_ch[128*2304], w_cl[128*2304];   // [o][t*256+c]

// ---- helpers ----
__device__ __forceinline__ uint32_t smem_u32(const void* p) {
    uint32_t a;
    asm("{ .reg .u64 t; cvta.to.shared.u64 t, %1; cvt.u32.u64 %0, t; }"
        : "=r"(a) : "l"(p));
    return a;
}
__device__ __forceinline__ void ldsm_x4(uint32_t r[4], uint32_t addr) {
    asm volatile("ldmatrix.sync.aligned.m8n8.x4.shared.b16 {%0,%1,%2,%3}, [%4];"
        : "=r"(r[0]), "=r"(r[1]), "=r"(r[2]), "=r"(r[3]) : "r"(addr));
}
__device__ __forceinline__ void ldsm_x4_t(uint32_t r[4], uint32_t addr) {
    asm volatile("ldmatrix.sync.aligned.m8n8.x4.trans.shared.b16 {%0,%1,%2,%3}, [%4];"
        : "=r"(r[0]), "=r"(r[1]), "=r"(r[2]), "=r"(r[3]) : "r"(addr));
}
__device__ __forceinline__ void mma_bf16(float d[4], const uint32_t a[4],
                                         const uint32_t b[2]) {
    asm volatile(
        "mma.sync.aligned.m16n8k16.row.col.f32.bf16.bf16.f32 "
        "{%0,%1,%2,%3}, {%4,%5,%6,%7}, {%8,%9}, {%0,%1,%2,%3};"
        : "+f"(d[0]), "+f"(d[1]), "+f"(d[2]), "+f"(d[3])
        : "r"(a[0]), "r"(a[1]), "r"(a[2]), "r"(a[3]), "r"(b[0]), "r"(b[1]));
}
__device__ __forceinline__ void mma_f16(float d[4], const uint32_t a[4],
                                        const uint32_t b[2]) {
    asm volatile(
        "mma.sync.aligned.m16n8k16.row.col.f32.f16.f16.f32 "
        "{%0,%1,%2,%3}, {%4,%5,%6,%7}, {%8,%9}, {%0,%1,%2,%3};"
        : "+f"(d[0]), "+f"(d[1]), "+f"(d[2]), "+f"(d[3])
        : "r"(a[0]), "r"(a[1]), "r"(a[2]), "r"(a[3]), "r"(b[0]), "r"(b[1]));
}
__device__ __forceinline__ void split_bf16(float x, __nv_bfloat16& hi,
                                           __nv_bfloat16& lo) {
    hi = __float2bfloat16_rn(x);
    lo = __float2bfloat16_rn(x - __bfloat162float(hi));
}
__device__ __forceinline__ uint32_t pack_bf2(__nv_bfloat16 a, __nv_bfloat16 b) {
    __nv_bfloat162 t = __halves2bfloat162(a, b);
    return *reinterpret_cast<uint32_t*>(&t);
}
__device__ __forceinline__ void split2(float a, float b, uint32_t& hi, uint32_t& lo) {
    __nv_bfloat16 ha, la, hb, lb;
    split_bf16(a, ha, la);
    split_bf16(b, hb, lb);
    hi = pack_bf2(ha, hb);
    lo = pack_bf2(la, lb);
}
// fp16 split (for V planes)
__device__ __forceinline__ void split2h(float a, float b, uint32_t& hi, uint32_t& lo) {
    __half ha = __float2half_rn(a);
    __half la = __float2half_rn(a - __half2float(ha));
    __half hb = __float2half_rn(b);
    __half lb = __float2half_rn(b - __half2float(hb));
    __half2 th = __halves2half2(ha, hb);
    __half2 tl = __halves2half2(la, lb);
    hi = *reinterpret_cast<uint32_t*>(&th);
    lo = *reinterpret_cast<uint32_t*>(&tl);
}
__device__ __forceinline__ uint32_t cvt_h2(float a, float b) {
    __half2 t = __floats2half2_rn(a, b);
    return *reinterpret_cast<uint32_t*>(&t);
}
// bf16x2 bits -> fp16x2 bits (exact: bf16 values are fp16-representable here)
__device__ __forceinline__ uint32_t bf2_to_h2(uint32_t x) {
    __nv_bfloat162 b = *reinterpret_cast<__nv_bfloat162*>(&x);
    float2 f = __bfloat1622float2(b);
    __half2 h = __floats2half2_rn(f.x, f.y);
    return *reinterpret_cast<uint32_t*>(&h);
}
__device__ __forceinline__ float ex2f(float x) {
    float y; asm("ex2.approx.ftz.f32 %0, %1;" : "=f"(y) : "f"(x)); return y;
}

#define SA_STRIDE 40
#define SB_STRIDE 136
#define SC_STRIDE 72

// =====================================================================
// One-shot weight prep.
// =====================================================================
__global__ void __launch_bounds__(256) split_all(
    const float* __restrict__ Wq, const float* __restrict__ Wk,
    const float* __restrict__ Wv, const float* __restrict__ Wout,
    const float* __restrict__ Woff1, float kscale)
{
    int idx = blockIdx.x * 256 + threadIdx.x;
    if (idx < 4 * 65536) {
        int w = idx >> 16, i = idx & 65535;
        const float* srcs[4] = {Wq, Wk, Wv, Wout};
        __nv_bfloat16* dh[4] = {w_qh, w_kh, w_vh, w_oh};
        __nv_bfloat16* dl[4] = {w_ql, w_kl, w_vl, w_ol};
        float v = srcs[w][i] * (w == 1 ? kscale : 1.0f);
        split_bf16(v, dh[w][i], dl[w][i]);
    } else {
        int i = idx - 4 * 65536;
        int o = i / 2304;
        int r = i - o * 2304;
        int c = r / 9;
        int t = r - c * 9;
        int dst = o * 2304 + t * 256 + c;
        split_bf16(Woff1[i], w_ch[dst], w_cl[dst]);
    }
}

// =====================================================================
// GEMM via mma.sync bf16-split, software-pipelined k-loop.
// =====================================================================
template<int BMODE, int OMODE>
__global__ void __launch_bounds__(256) gemm_mma(
    const __nv_bfloat16* __restrict__ Ah, const __nv_bfloat16* __restrict__ Al,
    const float* __restrict__ Bf,
    const __nv_bfloat16* __restrict__ Bh, const __nv_bfloat16* __restrict__ Bl,
    const float* __restrict__ bias,
    float* __restrict__ Yf,
    __nv_bfloat16* __restrict__ Yh, __nv_bfloat16* __restrict__ Yl,
    float yscale, int Cin)
{
    __shared__ __align__(16) __nv_bfloat16 sA[2][128][SA_STRIDE];
    __shared__ __align__(16) __nv_bfloat16 sB[2][32][SB_STRIDE];
    const int b  = blockIdx.z;
    const int o0 = blockIdx.y * 128;
    const int p0 = blockIdx.x * 128;
    const int O  = gridDim.y * 128;
    const size_t bB = (size_t)b * Cin * Pn;
    const size_t bY = (size_t)b * O * Pn;
    const int tid  = threadIdx.x;
    const int lane = tid & 31;
    const int wid  = tid >> 5;
    const int wm   = wid & 3;
    const int wn   = wid >> 2;

    float d[2][8][4];
    #pragma unroll
    for (int mf = 0; mf < 2; mf++)
        #pragma unroll
        for (int nf = 0; nf < 8; nf++)
            #pragma unroll
            for (int i = 0; i < 4; i++) d[mf][nf][i] = 0.0f;

    const int a_row  = (lane & 7) + ((lane >> 3) & 1) * 8;
    const int a_colk = ((lane >> 4) & 1) * 8;
    const int b_rowk = (lane & 7) + ((lane >> 3) & 1) * 8;
    const int b_ncol = ((lane >> 4) & 1) * 8;

    uint4  ra[2][2];
    float4 rbf[4];
    uint4  rb[2][2];

    auto loadA = [&](int c0) {
        #pragma unroll
        for (int t = 0; t < 2; t++) {
            const __nv_bfloat16* Ap = t ? Al : Ah;
            #pragma unroll
            for (int i = 0; i < 2; i++) {
                int e = tid + i * 256;
                int o = e >> 2, c8 = (e & 3) * 8;
                ra[t][i] = *reinterpret_cast<const uint4*>(
                    Ap + (size_t)(o0 + o) * Cin + c0 + c8);
            }
        }
    };
    auto storeA = [&]() {
        #pragma unroll
        for (int t = 0; t < 2; t++)
            #pragma unroll
            for (int i = 0; i < 2; i++) {
                int e = tid + i * 256;
                int o = e >> 2, c8 = (e & 3) * 8;
                *reinterpret_cast<uint4*>(&sA[t][o][c8]) = ra[t][i];
            }
    };
    auto loadB = [&](int c0) {
        if (BMODE == 0) {
            #pragma unroll
            for (int i = 0; i < 4; i++) {
                int e = tid + i * 256;
                int k = e >> 5, p4 = (e & 31) * 4;
                rbf[i] = *reinterpret_cast<const float4*>(
                    Bf + bB + (size_t)(c0 + k) * Pn + p0 + p4);
            }
        } else {
            #pragma unroll
            for (int t = 0; t < 2; t++) {
                const __nv_bfloat16* Bp = t ? Bl : Bh;
                #pragma unroll
                for (int i = 0; i < 2; i++) {
                    int e = tid + i * 256;
                    int k = e >> 4, p8 = (e & 15) * 8;
                    rb[t][i] = *reinterpret_cast<const uint4*>(
                        Bp + bB + (size_t)(c0 + k) * Pn + p0 + p8);
                }
            }
        }
    };
    auto storeB = [&]() {
        if (BMODE == 0) {
            #pragma unroll
            for (int i = 0; i < 4; i++) {
                int e = tid + i * 256;
                int k = e >> 5, p4 = (e & 31) * 4;
                float4 x = rbf[i];
                __nv_bfloat16 h0, l0, h1, l1, h2, l2, h3, l3;
                split_bf16(x.x, h0, l0); split_bf16(x.y, h1, l1);
                split_bf16(x.z, h2, l2); split_bf16(x.w, h3, l3);
                *reinterpret_cast<__nv_bfloat162*>(&sB[0][k][p4])     = __halves2bfloat162(h0, h1);
                *reinterpret_cast<__nv_bfloat162*>(&sB[0][k][p4 + 2]) = __halves2bfloat162(h2, h3);
                *reinterpret_cast<__nv_bfloat162*>(&sB[1][k][p4])     = __halves2bfloat162(l0, l1);
                *reinterpret_cast<__nv_bfloat162*>(&sB[1][k][p4 + 2]) = __halves2bfloat162(l2, l3);
            }
        } else {
            #pragma unroll
            for (int t = 0; t < 2; t++)
                #pragma unroll
                for (int i = 0; i < 2; i++) {
                    int e = tid + i * 256;
                    int k = e >> 4, p8 = (e & 15) * 8;
                    *reinterpret_cast<uint4*>(&sB[t][k][p8]) = rb[t][i];
                }
        }
    };

    loadA(0); loadB(0);
    storeA(); storeB();
    __syncthreads();

    for (int c0 = 0; c0 < Cin; c0 += 32) {
        bool more = (c0 + 32 < Cin);
        if (more) { loadA(c0 + 32); loadB(c0 + 32); }

        #pragma unroll
        for (int kk = 0; kk < 32; kk += 16) {
            uint32_t afr[2][2][4];
            #pragma unroll
            for (int t2 = 0; t2 < 2; t2++)
                #pragma unroll
                for (int mf = 0; mf < 2; mf++)
                    ldsm_x4(afr[t2][mf],
                        smem_u32(&sA[t2][wm * 32 + mf * 16 + a_row][kk + a_colk]));
            uint32_t bfr[2][8][2];
            #pragma unroll
            for (int t2 = 0; t2 < 2; t2++)
                #pragma unroll
                for (int nf2 = 0; nf2 < 4; nf2++) {
                    uint32_t r[4];
                    ldsm_x4_t(r, smem_u32(
                        &sB[t2][kk + b_rowk][wn * 64 + nf2 * 16 + b_ncol]));
                    bfr[t2][2 * nf2][0] = r[0]; bfr[t2][2 * nf2][1] = r[1];
                    bfr[t2][2 * nf2 + 1][0] = r[2]; bfr[t2][2 * nf2 + 1][1] = r[3];
                }
            #pragma unroll
            for (int mf = 0; mf < 2; mf++)
                #pragma unroll
                for (int nf = 0; nf < 8; nf++) {
                    mma_bf16(d[mf][nf], afr[0][mf], bfr[0][nf]);
                    mma_bf16(d[mf][nf], afr[0][mf], bfr[1][nf]);
                    mma_bf16(d[mf][nf], afr[1][mf], bfr[0][nf]);
                }
        }
        __syncthreads();
        if (more) { storeA(); storeB(); __syncthreads(); }
    }

    #pragma unroll
    for (int mf = 0; mf < 2; mf++) {
        int r = o0 + wm * 32 + mf * 16 + (lane >> 2);
        float b0v = bias ? bias[r] : 0.0f;
        float b1v = bias ? bias[r + 8] : 0.0f;
        #pragma unroll
        for (int nf = 0; nf < 8; nf++) {
            int cb = p0 + wn * 64 + nf * 8 + (lane & 3) * 2;
            float v00 = d[mf][nf][0] + b0v, v01 = d[mf][nf][1] + b0v;
            float v10 = d[mf][nf][2] + b1v, v11 = d[mf][nf][3] + b1v;
            if (OMODE & 1) {
                *reinterpret_cast<float2*>(Yf + bY + (size_t)r * Pn + cb) =
                    make_float2(v00, v01);
                *reinterpret_cast<float2*>(Yf + bY + (size_t)(r + 8) * Pn + cb) =
                    make_float2(v10, v11);
            }
            if (OMODE & 2) {
                uint32_t h0, l0, h1, l1;
                split2(v00 * yscale, v01 * yscale, h0, l0);
                split2(v10 * yscale, v11 * yscale, h1, l1);
                *reinterpret_cast<uint32_t*>(Yh + bY + (size_t)r * Pn + cb)       = h0;
                *reinterpret_cast<uint32_t*>(Yl + bY + (size_t)r * Pn + cb)       = l0;
                *reinterpret_cast<uint32_t*>(Yh + bY + (size_t)(r + 8) * Pn + cb) = h1;
                *reinterpret_cast<uint32_t*>(Yl + bY + (size_t)(r + 8) * Pn + cb) = l1;
            }
        }
    }
}

// =====================================================================
// Fused K+V projection. K -> fp16 single plane; V -> fp16 split planes.
// grid (8, 4, 8), 256 threads: warps 0-3 -> K, warps 4-7 -> V.
// =====================================================================
__global__ void __launch_bounds__(256) gemm_kv()
{
    __shared__ __align__(16) __nv_bfloat16 sAk[2][64][SA_STRIDE];
    __shared__ __align__(16) __nv_bfloat16 sAv[2][64][SA_STRIDE];
    __shared__ __align__(16) __nv_bfloat16 sB[2][32][SB_STRIDE];
    const int b  = blockIdx.z;
    const int o0 = blockIdx.y * 64;
    const int p0 = blockIdx.x * 128;
    const size_t bB = (size_t)b * Cn * Pn;
    const int tid  = threadIdx.x;
    const int lane = tid & 31;
    const int wid  = tid >> 5;
    const int half = wid >> 2;
    const int w2   = wid & 3;
    const int wm   = w2 & 1;
    const int wn   = w2 >> 1;

    float d[2][8][4];
    #pragma unroll
    for (int mf = 0; mf < 2; mf++)
        #pragma unroll
        for (int nf = 0; nf < 8; nf++)
            #pragma unroll
            for (int i = 0; i < 4; i++) d[mf][nf][i] = 0.0f;

    const int a_row  = (lane & 7) + ((lane >> 3) & 1) * 8;
    const int a_colk = ((lane >> 4) & 1) * 8;
    const int b_rowk = (lane & 7) + ((lane >> 3) & 1) * 8;
    const int b_ncol = ((lane >> 4) & 1) * 8;

    const int ao = tid >> 2, ac8 = (tid & 3) * 8;
    uint4 ra[4];
    uint4 rb[2][2];
    auto loadA = [&](int c0) {
        size_t off = (size_t)(o0 + ao) * Cn + c0 + ac8;
        ra[0] = *reinterpret_cast<const uint4*>(w_kh + off);
        ra[1] = *reinterpret_cast<const uint4*>(w_kl + off);
        ra[2] = *reinterpret_cast<const uint4*>(w_vh + off);
        ra[3] = *reinterpret_cast<const uint4*>(w_vl + off);
    };
    auto storeA = [&]() {
        *reinterpret_cast<uint4*>(&sAk[0][ao][ac8]) = ra[0];
        *reinterpret_cast<uint4*>(&sAk[1][ao][ac8]) = ra[1];
        *reinterpret_cast<uint4*>(&sAv[0][ao][ac8]) = ra[2];
        *reinterpret_cast<uint4*>(&sAv[1][ao][ac8]) = ra[3];
    };
    auto loadB = [&](int c0) {
        #pragma unroll
        for (int t = 0; t < 2; t++) {
            const __nv_bfloat16* Bp = t ? g_sl : g_sh;
            #pragma unroll
            for (int i = 0; i < 2; i++) {
                int e = tid + i * 256;
                int k = e >> 4, p8 = (e & 15) * 8;
                rb[t][i] = *reinterpret_cast<const uint4*>(
                    Bp + bB + (size_t)(c0 + k) * Pn + p0 + p8);
            }
        }
    };
    auto storeB = [&]() {
        #pragma unroll
        for (int t = 0; t < 2; t++)
            #pragma unroll
            for (int i = 0; i < 2; i++) {
                int e = tid + i * 256;
                int k = e >> 4, p8 = (e & 15) * 8;
                *reinterpret_cast<uint4*>(&sB[t][k][p8]) = rb[t][i];
            }
    };

    loadA(0); loadB(0);
    storeA(); storeB();
    __syncthreads();

    for (int c0 = 0; c0 < Cn; c0 += 32) {
        bool more = (c0 + 32 < Cn);
        if (more) { loadA(c0 + 32); loadB(c0 + 32); }

        #pragma unroll
        for (int kk = 0; kk < 32; kk += 16) {
            uint32_t afr[2][2][4];
            #pragma unroll
            for (int t2 = 0; t2 < 2; t2++)
                #pragma unroll
                for (int mf = 0; mf < 2; mf++) {
                    const __nv_bfloat16* base = half
                        ? &sAv[t2][wm * 32 + mf * 16 + a_row][kk + a_colk]
                        : &sAk[t2][wm * 32 + mf * 16 + a_row][kk + a_colk];
                    ldsm_x4(afr[t2][mf], smem_u32(base));
                }
            uint32_t bfr[2][8][2];
            #pragma unroll
            for (int t2 = 0; t2 < 2; t2++)
                #pragma unroll
                for (int nf2 = 0; nf2 < 4; nf2++) {
                    uint32_t r[4];
                    ldsm_x4_t(r, smem_u32(
                        &sB[t2][kk + b_rowk][wn * 64 + nf2 * 16 + b_ncol]));
                    bfr[t2][2 * nf2][0] = r[0]; bfr[t2][2 * nf2][1] = r[1];
                    bfr[t2][2 * nf2 + 1][0] = r[2]; bfr[t2][2 * nf2 + 1][1] = r[3];
                }
            #pragma unroll
            for (int mf = 0; mf < 2; mf++)
                #pragma unroll
                for (int nf = 0; nf < 8; nf++) {
                    mma_bf16(d[mf][nf], afr[0][mf], bfr[0][nf]);
                    mma_bf16(d[mf][nf], afr[0][mf], bfr[1][nf]);
                    mma_bf16(d[mf][nf], afr[1][mf], bfr[0][nf]);
                }
        }
        __syncthreads();
        if (more) { storeA(); storeB(); __syncthreads(); }
    }

    #pragma unroll
    for (int mf = 0; mf < 2; mf++) {
        int r = o0 + wm * 32 + mf * 16 + (lane >> 2);
        #pragma unroll
        for (int nf = 0; nf < 8; nf++) {
            int cb = p0 + wn * 64 + nf * 8 + (lane & 3) * 2;
            if (half == 0) {
                // K: single fp16 plane (2^-12 rounding; budgeted)
                uint32_t p0w = cvt_h2(d[mf][nf][0], d[mf][nf][1]);
                uint32_t p1w = cvt_h2(d[mf][nf][2], d[mf][nf][3]);
                *reinterpret_cast<uint32_t*>(g_kf + bB + (size_t)r * Pn + cb)       = p0w;
                *reinterpret_cast<uint32_t*>(g_kf + bB + (size_t)(r + 8) * Pn + cb) = p1w;
            } else {
                uint32_t h0, l0, h1, l1;
                split2h(d[mf][nf][0], d[mf][nf][1], h0, l0);
                split2h(d[mf][nf][2], d[mf][nf][3], h1, l1);
                *reinterpret_cast<uint32_t*>(g_vh + bB + (size_t)r * Pn + cb)       = h0;
                *reinterpret_cast<uint32_t*>(g_vl + bB + (size_t)r * Pn + cb)       = l0;
                *reinterpret_cast<uint32_t*>(g_vh + bB + (size_t)(r + 8) * Pn + cb) = h1;
                *reinterpret_cast<uint32_t*>(g_vl + bB + (size_t)(r + 8) * Pn + cb) = l1;
            }
        }
    }
}

// =====================================================================
// Conv as GEMM with FUSED shift. splitK=2. grid (16, 2, 8), 256 thr.
// =====================================================================
__global__ void __launch_bounds__(256) conv_mma3()
{
    __shared__ __align__(16) __nv_bfloat16 sA[2][128][SA_STRIDE];
    __shared__ __align__(16) __nv_bfloat16 sB[2][32][SC_STRIDE];
    const int b  = blockIdx.z;
    const int ks = blockIdx.y;
    const int p0 = blockIdx.x * 64;
    float* Yb = (ks ? g_h1b : g_h1a) + (size_t)b * 128 * Pn;
    const size_t bQ = (size_t)b * Cn * Pn;
    const int tid  = threadIdx.x;
    const int lane = tid & 31;
    const int wid  = tid >> 5;
    const int wm   = wid & 3;
    const int wn   = wid >> 2;

    float d[2][4][4];
    #pragma unroll
    for (int mf = 0; mf < 2; mf++)
        #pragma unroll
        for (int nf = 0; nf < 4; nf++)
            #pragma unroll
            for (int i = 0; i < 4; i++) d[mf][nf][i] = 0.0f;

    const int a_row  = (lane & 7) + ((lane >> 3) & 1) * 8;
    const int a_colk = ((lane >> 4) & 1) * 8;
    const int b_rowk = (lane & 7) + ((lane >> 3) & 1) * 8;
    const int b_ncol = ((lane >> 4) & 1) * 8;

    uint4 ra[2][2], rb[2];
    auto loadA = [&](int c0) {
        #pragma unroll
        for (int t = 0; t < 2; t++) {
            const __nv_bfloat16* Ap = t ? w_cl : w_ch;
            #pragma unroll
            for (int i = 0; i < 2; i++) {
                int e = tid + i * 256;
                int o = e >> 2, c8 = (e & 3) * 8;
                ra[t][i] = *reinterpret_cast<const uint4*>(
                    Ap + (size_t)o * 2304 + c0 + c8);
            }
        }
    };
    auto storeA = [&]() {
        #pragma unroll
        for (int t = 0; t < 2; t++)
            #pragma unroll
            for (int i = 0; i < 2; i++) {
                int e = tid + i * 256;
                int o = e >> 2, c8 = (e & 3) * 8;
                *reinterpret_cast<uint4*>(&sA[t][o][c8]) = ra[t][i];
            }
    };
    const int bk = tid >> 3, bp8 = (tid & 7) * 8;
    const int P  = p0 + bp8;
    const int x0 = P & 31;
    const int yb = P >> 5;
    auto loadB = [&](int c0) {
        int t  = c0 >> 8;
        int cc = (c0 & 255) + bk;
        int ty = t / 3;
        int dy = ty - 1;
        int dx = t - ty * 3 - 1;
        int ys = yb + dy;
        bool yok = (unsigned)ys < 32u;
        size_t rowoff = bQ + (size_t)cc * Pn + ys * 32;
        #pragma unroll
        for (int pl = 0; pl < 2; pl++) {
            const __nv_bfloat16* Qp = pl ? g_ql : g_qh;
            uint4 v = make_uint4(0u, 0u, 0u, 0u);
            if (yok) {
                uint4 w = *reinterpret_cast<const uint4*>(Qp + rowoff + x0);
                if (dx == 0) {
                    v = w;
                } else if (dx > 0) {
                    uint32_t extra = 0;
                    if (x0 != 24)
                        extra = *reinterpret_cast<const uint16_t*>(
                            Qp + rowoff + x0 + 8);
                    v.x = __funnelshift_r(w.x, w.y, 16);
                    v.y = __funnelshift_r(w.y, w.z, 16);
                    v.z = __funnelshift_r(w.z, w.w, 16);
                    v.w = (w.w >> 16) | (extra << 16);
                } else {
                    uint32_t extra = 0;
                    if (x0 != 0)
                        extra = *reinterpret_cast<const uint16_t*>(
                            Qp + rowoff + x0 - 1);
                    v.x = (w.x << 16) | extra;
                    v.y = __funnelshift_l(w.x, w.y, 16);
                    v.z = __funnelshift_l(w.y, w.z, 16);
                    v.w = __funnelshift_l(w.z, w.w, 16);
                }
            }
            rb[pl] = v;
        }
    };
    auto storeB = [&]() {
        *reinterpret_cast<uint4*>(&sB[0][bk][bp8]) = rb[0];
        *reinterpret_cast<uint4*>(&sB[1][bk][bp8]) = rb[1];
    };

    const int cbeg = ks * 1152, cend = cbeg + 1152;
    loadA(cbeg); loadB(cbeg);
    storeA(); storeB();
    __syncthreads();

    for (int c0 = cbeg; c0 < cend; c0 += 32) {
        bool more = (c0 + 32 < cend);
        if (more) { loadA(c0 + 32); loadB(c0 + 32); }

        #pragma unroll
        for (int kk = 0; kk < 32; kk += 16) {
            uint32_t afr[2][2][4];
            #pragma unroll
            for (int t2 = 0; t2 < 2; t2++)
                #pragma unroll
                for (int mf = 0; mf < 2; mf++)
                    ldsm_x4(afr[t2][mf],
                        smem_u32(&sA[t2][wm * 32 + mf * 16 + a_row][kk + a_colk]));
            uint32_t bfr[2][4][2];
            #pragma unroll
            for (int t2 = 0; t2 < 2; t2++)
                #pragma unroll
                for (int nf2 = 0; nf2 < 2; nf2++) {
                    uint32_t r[4];
                    ldsm_x4_t(r, smem_u32(
                        &sB[t2][kk + b_rowk][wn * 32 + nf2 * 16 + b_ncol]));
                    bfr[t2][2 * nf2][0] = r[0]; bfr[t2][2 * nf2][1] = r[1];
                    bfr[t2][2 * nf2 + 1][0] = r[2]; bfr[t2][2 * nf2 + 1][1] = r[3];
                }
            #pragma unroll
            for (int mf = 0; mf < 2; mf++)
                #pragma unroll
                for (int nf = 0; nf < 4; nf++) {
                    mma_bf16(d[mf][nf], afr[0][mf], bfr[0][nf]);
                    mma_bf16(d[mf][nf], afr[0][mf], bfr[1][nf]);
                    mma_bf16(d[mf][nf], afr[1][mf], bfr[0][nf]);
                }
        }
        __syncthreads();
        if (more) { storeA(); storeB(); __syncthreads(); }
    }
    #pragma unroll
    for (int mf = 0; mf < 2; mf++) {
        int r = wm * 32 + mf * 16 + (lane >> 2);
        #pragma unroll
        for (int nf = 0; nf < 4; nf++) {
            int cb = p0 + wn * 32 + nf * 8 + (lane & 3) * 2;
            *reinterpret_cast<float2*>(Yb + (size_t)r * Pn + cb) =
                make_float2(d[mf][nf][0], d[mf][nf][1]);
            *reinterpret_cast<float2*>(Yb + (size_t)(r + 8) * Pn + cb) =
                make_float2(d[mf][nf][2], d[mf][nf][3]);
        }
    }
}

// =====================================================================
// Offsets, 16-way channel split: block = 16 px x 16 segments of 8 ch.
// grid (64, 8) = 512 CTAs.
// =====================================================================
__global__ void __launch_bounds__(256) offs_kernel4(
    const float* __restrict__ Woff2, const float* __restrict__ boff2,
    const float* __restrict__ boff1)
{
    __shared__ float red[2][16][16];
    const int b   = blockIdx.y;
    const int px  = threadIdx.x & 15;
    const int seg = threadIdx.x >> 4;          // 0..15
    const int p   = blockIdx.x * 16 + px;
    const float* h1a = g_h1a + (size_t)b * 128 * Pn;
    const float* h1b = g_h1b + (size_t)b * 128 * Pn;
    const int c0 = seg * 8;
    float ox0 = 0.0f, oy0 = 0.0f, ox1 = 0.0f, oy1 = 0.0f;
    #pragma unroll
    for (int c = c0; c < c0 + 8; c += 2) {
        size_t i0 = (size_t)c * Pn + p;
        size_t i1 = (size_t)(c + 1) * Pn + p;
        float h0 = fmaxf(h1a[i0] + h1b[i0] + boff1[c], 0.0f);
        float h1 = fmaxf(h1a[i1] + h1b[i1] + boff1[c + 1], 0.0f);
        ox0 += Woff2[c] * h0;       oy0 += Woff2[128 + c] * h0;
        ox1 += Woff2[c + 1] * h1;   oy1 += Woff2[128 + c + 1] * h1;
    }
    red[0][seg][px] = ox0 + ox1;
    red[1][seg][px] = oy0 + oy1;
    __syncthreads();
    if (threadIdx.x < 16) {
        float sx = boff2[0], sy = boff2[1];
        #pragma unroll
        for (int s = 0; s < 16; s++) {
            sx += red[0][s][threadIdx.x];
            sy += red[1][s][threadIdx.x];
        }
        g_off[((size_t)b * 2 + 0) * Pn + blockIdx.x * 16 + threadIdx.x] = sx * 0.1f;
        g_off[((size_t)b * 2 + 1) * Pn + blockIdx.x * 16 + threadIdx.x] = sy * 0.1f;
    }
}

// =====================================================================
// Bilinear grid sample -> split planes. grid (4, 8, 16).
// =====================================================================
__global__ void __launch_bounds__(256) samp_kernel(const float* __restrict__ kv)
{
    const int b  = blockIdx.y;
    const int p  = blockIdx.x * 256 + threadIdx.x;
    const int c0 = blockIdx.z * 16;
    float ox = g_off[((size_t)b * 2 + 0) * Pn + p];
    float oy = g_off[((size_t)b * 2 + 1) * Pn + p];
    int px = p & 31, py = p >> 5;
    float gx = -1.0f + px * (2.0f / 31.0f);
    float gy = -1.0f + py * (2.0f / 31.0f);
    float x = (gx + ox + 1.0f) * 0.5f * 31.0f;
    float y = (gy + oy + 1.0f) * 0.5f * 31.0f;
    x = fminf(fmaxf(x, 0.0f), 31.0f);
    y = fminf(fmaxf(y, 0.0f), 31.0f);
    float x0f = floorf(x), y0f = floorf(y);
    float wx = x - x0f, wy = y - y0f;
    int x0 = (int)x0f, y0 = (int)y0f;
    int x1 = min(x0 + 1, 31), y1 = min(y0 + 1, 31);
    float w00 = (1.0f - wx) * (1.0f - wy);
    float w01 = wx * (1.0f - wy);
    float w10 = (1.0f - wx) * wy;
    float w11 = wx * wy;
    int i00 = (y0 << 5) + x0, i01 = (y0 << 5) + x1;
    int i10 = (y1 << 5) + x0, i11 = (y1 << 5) + x1;
    const float* kvb = kv + (size_t)b * Cn * Pn;
    const size_t ob = (size_t)b * Cn * Pn;
    #pragma unroll 4
    for (int c = c0; c < c0 + 16; c++) {
        const float* pl = kvb + (size_t)c * Pn;
        float v = w00 * pl[i00] + w01 * pl[i01] + w10 * pl[i10] + w11 * pl[i11];
        __nv_bfloat16 h, l;
        split_bf16(v, h, l);
        g_sh[ob + (size_t)c * Pn + p] = h;
        g_sl[ob + (size_t)c * Pn + p] = l;
    }
}

// =====================================================================
// Flash attention, pipelined KV loads.
// QK: Q fp16 2-term (exact convert of bf16 hi/lo) x K fp16 single
//     plane -> 2 mma (was 3).
// PV: fp16 P x fp16 V hi/lo -> 2 mma. grid (8, 64), 256 threads.
// =====================================================================
__global__ void __launch_bounds__(256) attn_mma()
{
    __shared__ __align__(16) __half sK[32][SB_STRIDE];
    __shared__ __align__(16) __half sV[2][32][SB_STRIDE];

    const int bh = blockIdx.y;
    const int b  = bh >> 3, h = bh & 7;
    const int p0 = blockIdx.x * 128;
    const int tid  = threadIdx.x;
    const int lane = tid & 31;
    const int wm   = tid >> 5;
    const size_t base = ((size_t)b * Cn + h * HD) * Pn;

    const int krow = (lane & 7) + ((lane >> 3) & 1) * 8;
    const int ncol = ((lane >> 4) & 1) * 8;

    // ---- stage Q bf16 planes into sV (bit staging), extract + convert ----
    __nv_bfloat16* stage = reinterpret_cast<__nv_bfloat16*>(&sV[0][0][0]);
    #pragma unroll
    for (int t = 0; t < 2; t++) {
        const __nv_bfloat16* Qp = (t ? g_ql : g_qh) + base;
        #pragma unroll
        for (int i = 0; i < 2; i++) {
            int e = tid + i * 256;
            int d = e >> 4, p8 = (e & 15) * 8;
            uint4 v = *reinterpret_cast<const uint4*>(Qp + (size_t)d * Pn + p0 + p8);
            *reinterpret_cast<uint4*>(stage + (size_t)(t * 32 + d) * SB_STRIDE + p8) = v;
        }
    }
    __syncthreads();
    uint32_t aQ[2][2][4];   // [plane][kstep][4], converted to fp16
    #pragma unroll
    for (int t = 0; t < 2; t++)
        #pragma unroll
        for (int ks = 0; ks < 2; ks++) {
            uint32_t r[4];
            ldsm_x4_t(r, smem_u32(
                stage + (size_t)(t * 32 + ks * 16 + krow) * SB_STRIDE + wm * 16 + ncol));
            aQ[t][ks][0] = bf2_to_h2(r[0]); aQ[t][ks][1] = bf2_to_h2(r[2]);
            aQ[t][ks][2] = bf2_to_h2(r[1]); aQ[t][ks][3] = bf2_to_h2(r[3]);
        }

    float O[4][4];
    #pragma unroll
    for (int nf = 0; nf < 4; nf++)
        #pragma unroll
        for (int i = 0; i < 4; i++) O[nf][i] = 0.0f;
    float lsum0 = 0.0f, lsum1 = 0.0f;

    const int vrow = (lane & 7) + ((lane >> 3) & 1) * 8;
    const int vcol = ((lane >> 4) & 1) * 8;

    const int ld_d  = tid >> 4;            // 0..15
    const int ld_p8 = (tid & 15) * 8;
    uint4 rk[2], rv[2][2];
    auto loadKV = [&](int kv0) {
        const __half* Kp = g_kf + base;
        #pragma unroll
        for (int i = 0; i < 2; i++) {
            int d = ld_d + i * 16;
            rk[i] = *reinterpret_cast<const uint4*>(Kp + (size_t)d * Pn + kv0 + ld_p8);
        }
        #pragma unroll
        for (int t = 0; t < 2; t++) {
            const __half* Vp = (t ? g_vl : g_vh) + base;
            #pragma unroll
            for (int i = 0; i < 2; i++) {
                int d = ld_d + i * 16;
                rv[t][i] = *reinterpret_cast<const uint4*>(
                    Vp + (size_t)d * Pn + kv0 + ld_p8);
            }
        }
    };
    auto storeKV = [&]() {
        #pragma unroll
        for (int i = 0; i < 2; i++) {
            int d = ld_d + i * 16;
            *reinterpret_cast<uint4*>(&sK[d][ld_p8]) = rk[i];
            #pragma unroll
            for (int t = 0; t < 2; t++)
                *reinterpret_cast<uint4*>(&sV[t][d][ld_p8]) = rv[t][i];
        }
    };

    loadKV(0);

    for (int kt = 0; kt < 8; kt++) {
        __syncthreads();     // staging/compute reads done before overwrite
        storeKV();
        __syncthreads();
        if (kt + 1 < 8) loadKV((kt + 1) * 128);

        float S[16][4];
        #pragma unroll
        for (int f = 0; f < 16; f++)
            #pragma unroll
            for (int i = 0; i < 4; i++) S[f][i] = 0.0f;

        // ---- S = Q K^T : 2 fp16 mma per (nb, half, ks) pair group ----
        #pragma unroll
        for (int nb = 0; nb < 8; nb++) {
            uint32_t bk[2][4];
            #pragma unroll
            for (int ks = 0; ks < 2; ks++)
                ldsm_x4_t(bk[ks],
                    smem_u32(&sK[ks * 16 + krow][nb * 16 + ncol]));
            #pragma unroll
            for (int half = 0; half < 2; half++) {
                float* s = S[nb * 2 + half];
                #pragma unroll
                for (int ks = 0; ks < 2; ks++) {
                    uint32_t bb[2] = {bk[ks][2 * half], bk[ks][2 * half + 1]};
                    mma_f16(s, aQ[0][ks], bb);   // q_hi . k
                    mma_f16(s, aQ[1][ks], bb);   // q_lo . k
                }
            }
        }
        #pragma unroll
        for (int f = 0; f < 16; f++) {
            S[f][0] = ex2f(S[f][0]); S[f][1] = ex2f(S[f][1]);
            S[f][2] = ex2f(S[f][2]); S[f][3] = ex2f(S[f][3]);
            lsum0 += S[f][0] + S[f][1];
            lsum1 += S[f][2] + S[f][3];
        }
        #pragma unroll
        for (int ks8 = 0; ks8 < 8; ks8++) {
            uint32_t ah[4];
            const float* f0 = S[2 * ks8];
            const float* f1 = S[2 * ks8 + 1];
            ah[0] = cvt_h2(f0[0], f0[1]);
            ah[1] = cvt_h2(f0[2], f0[3]);
            ah[2] = cvt_h2(f1[0], f1[1]);
            ah[3] = cvt_h2(f1[2], f1[3]);
            uint32_t bv[2][2][4];
            #pragma unroll
            for (int t = 0; t < 2; t++)
                #pragma unroll
                for (int db = 0; db < 2; db++)
                    ldsm_x4(bv[t][db],
                        smem_u32(&sV[t][db * 16 + vrow][ks8 * 16 + vcol]));
            #pragma unroll
            for (int nf = 0; nf < 4; nf++) {
                int db = nf >> 1, wh = nf & 1;
                uint32_t vhi[2] = {bv[0][db][wh], bv[0][db][wh + 2]};
                uint32_t vlo[2] = {bv[1][db][wh], bv[1][db][wh + 2]};
                mma_f16(O[nf], ah, vhi);
                mma_f16(O[nf], ah, vlo);
            }
        }
    }
    lsum0 += __shfl_xor_sync(0xffffffffu, lsum0, 1);
    lsum0 += __shfl_xor_sync(0xffffffffu, lsum0, 2);
    lsum1 += __shfl_xor_sync(0xffffffffu, lsum1, 1);
    lsum1 += __shfl_xor_sync(0xffffffffu, lsum1, 2);
    float inv0 = 1.0f / lsum0, inv1 = 1.0f / lsum1;
    int p = p0 + wm * 16 + (lane >> 2);
    #pragma unroll
    for (int nf = 0; nf < 4; nf++) {
        int d = nf * 8 + (lane & 3) * 2;
        float v0 = O[nf][0] * inv0, v1 = O[nf][1] * inv0;
        float v2 = O[nf][2] * inv1, v3 = O[nf][3] * inv1;
        __nv_bfloat16 hh, ll;
        split_bf16(v0, hh, ll);
        g_oh[base + (size_t)d * Pn + p] = hh;       g_ol[base + (size_t)d * Pn + p] = ll;
        split_bf16(v1, hh, ll);
        g_oh[base + (size_t)(d + 1) * Pn + p] = hh; g_ol[base + (size_t)(d + 1) * Pn + p] = ll;
        split_bf16(v2, hh, ll);
        g_oh[base + (size_t)d * Pn + p + 8] = hh;   g_ol[base + (size_t)d * Pn + p + 8] = ll;
        split_bf16(v3, hh, ll);
        g_oh[base + (size_t)(d + 1) * Pn + p + 8] = hh;
        g_ol[base + (size_t)(d + 1) * Pn + p + 8] = ll;
    }
}

// =====================================================================
extern "C" void kernel_launch(void* const* d_in, const int* in_sizes, int n_in,
                              void* d_out, int out_size)
{
    (void)in_sizes; (void)n_in; (void)out_size;
    const float* query_map = (const float*)d_in[0];
    const float* kv_map    = (const float*)d_in[1];
    const float* Wq        = (const float*)d_in[2];
    const float* Wk        = (const float*)d_in[3];
    const float* Wv        = (const float*)d_in[4];
    const float* Woff1     = (const float*)d_in[5];
    const float* boff1     = (const float*)d_in[6];
    const float* Woff2     = (const float*)d_in[7];
    const float* boff2     = (const float*)d_in[8];
    const float* Wout      = (const float*)d_in[9];
    const float* bout      = (const float*)d_in[10];
    float* out = (float*)d_out;

    const float kscale = 0.17677669529663687f * 1.4426950408889634f;

    __nv_bfloat16 *pqh, *pql, *poh, *pol;
    __nv_bfloat16 *pwqh, *pwql, *pwoh, *pwol;
    cudaGetSymbolAddress((void**)&pqh, g_qh);  cudaGetSymbolAddress((void**)&pql, g_ql);
    cudaGetSymbolAddress((void**)&poh, g_oh);  cudaGetSymbolAddress((void**)&pol, g_ol);
    cudaGetSymbolAddress((void**)&pwqh, w_qh); cudaGetSymbolAddress((void**)&pwql, w_ql);
    cudaGetSymbolAddress((void**)&pwoh, w_oh); cudaGetSymbolAddress((void**)&pwol, w_ol);

    // 0) one-shot weight prep
    split_all<<<2176, 256>>>(Wq, Wk, Wv, Wout, Woff1, kscale);
    // 1) q projection -> bf16 split planes (conv + attn)
    gemm_mma<0, 2><<<dim3(8, 2, 8), 256>>>(
        pwqh, pwql, query_map, nullptr, nullptr, nullptr,
        nullptr, pqh, pql, 1.0f, 256);
    // 2) conv GEMM with fused shift (splitK=2)
    conv_mma3<<<dim3(16, 2, 8), 256>>>();
    // 3) offsets — 16-way split reduction (512 CTAs)
    offs_kernel4<<<dim3(64, 8), 256>>>(Woff2, boff2, boff1);
    // 4) bilinear sample -> split planes
    samp_kernel<<<dim3(4, 8, 16), 256>>>(kv_map);
    // 5) fused K+V projections (K -> fp16 plane, V -> fp16 planes)
    gemm_kv<<<dim3(8, 4, 8), 256>>>();
    // 6) attention (pipelined; 2-mma QK, 2-mma PV)
    attn_mma<<<dim3(8, 64), 256>>>();
    // 7) out = Wout @ attn_out + bout
    gemm_mma<1, 1><<<dim3(8, 2, 8), 256>>>(
        pwoh, pwol, nullptr, poh, pol, bout,
        out, nullptr, nullptr, 1.0f, 256);
}

// round 16
// speedup vs baseline: 1.6467x; 1.2132x over previous
#include <cuda_runtime.h>
#include <cuda_bf16.h>
#include <cuda_fp16.h>
#include <cstdint>

#define Bn 8
#define Cn 256
#define Pn 1024
#define HEADS 8
#define HD 32

// ---- fp32 scratch ----
__device__ float g_h1a[Bn*128*Pn];  // conv partial sums (splitK halves)
__device__ float g_h1b[Bn*128*Pn];
__device__ float g_off[Bn*2*Pn];

// ---- fp16 interchange planes (hi/lo; lo = residual, combined ~2^-24) ----
__device__ __half g_qh[Bn*Cn*Pn], g_ql[Bn*Cn*Pn];   // unscaled q
__device__ __half g_kf[Bn*Cn*Pn];                   // K single plane (scale folded)
__device__ __half g_vh[Bn*Cn*Pn], g_vl[Bn*Cn*Pn];   // V split
__device__ __half g_sh[Bn*Cn*Pn], g_sl[Bn*Cn*Pn];   // sampled kv
__device__ __half g_oh[Bn*Cn*Pn], g_ol[Bn*Cn*Pn];   // attn out

// ---- fp16 single-plane weights (2^-12 rounding, budgeted) ----
__device__ __half w_q16[Cn*Cn];
__device__ __half w_k16[Cn*Cn];                     // pre-scaled by kscale
__device__ __half w_v16[Cn*Cn];
__device__ __half w_o16[Cn*Cn];
__device__ __half w_c16[128*2304];                  // [o][t*256+c]

// ---- helpers ----
__device__ __forceinline__ uint32_t smem_u32(const void* p) {
    uint32_t a;
    asm("{ .reg .u64 t; cvta.to.shared.u64 t, %1; cvt.u32.u64 %0, t; }"
        : "=r"(a) : "l"(p));
    return a;
}
__device__ __forceinline__ void ldsm_x4(uint32_t r[4], uint32_t addr) {
    asm volatile("ldmatrix.sync.aligned.m8n8.x4.shared.b16 {%0,%1,%2,%3}, [%4];"
        : "=r"(r[0]), "=r"(r[1]), "=r"(r[2]), "=r"(r[3]) : "r"(addr));
}
__device__ __forceinline__ void ldsm_x4_t(uint32_t r[4], uint32_t addr) {
    asm volatile("ldmatrix.sync.aligned.m8n8.x4.trans.shared.b16 {%0,%1,%2,%3}, [%4];"
        : "=r"(r[0]), "=r"(r[1]), "=r"(r[2]), "=r"(r[3]) : "r"(addr));
}
__device__ __forceinline__ void mma_f16(float d[4], const uint32_t a[4],
                                        const uint32_t b[2]) {
    asm volatile(
        "mma.sync.aligned.m16n8k16.row.col.f32.f16.f16.f32 "
        "{%0,%1,%2,%3}, {%4,%5,%6,%7}, {%8,%9}, {%0,%1,%2,%3};"
        : "+f"(d[0]), "+f"(d[1]), "+f"(d[2]), "+f"(d[3])
        : "r"(a[0]), "r"(a[1]), "r"(a[2]), "r"(a[3]), "r"(b[0]), "r"(b[1]));
}
// fp16 2-term split
__device__ __forceinline__ void split_h(float x, __half& hi, __half& lo) {
    hi = __float2half_rn(x);
    lo = __float2half_rn(x - __half2float(hi));
}
__device__ __forceinline__ void split2h(float a, float b, uint32_t& hi, uint32_t& lo) {
    __half ha, la, hb, lb;
    split_h(a, ha, la);
    split_h(b, hb, lb);
    __half2 th = __halves2half2(ha, hb);
    __half2 tl = __halves2half2(la, lb);
    hi = *reinterpret_cast<uint32_t*>(&th);
    lo = *reinterpret_cast<uint32_t*>(&tl);
}
__device__ __forceinline__ uint32_t cvt_h2(float a, float b) {
    __half2 t = __floats2half2_rn(a, b);
    return *reinterpret_cast<uint32_t*>(&t);
}
__device__ __forceinline__ float ex2f(float x) {
    float y; asm("ex2.approx.ftz.f32 %0, %1;" : "=f"(y) : "f"(x)); return y;
}

#define SA_STRIDE 40
#define SB_STRIDE 136
#define SC_STRIDE 72

// =====================================================================
// One-shot weight prep: convert all weights to fp16 single plane;
// Wk scaled by kscale; conv W reordered [o][c*9+t] -> [o][t*256+c].
// =====================================================================
__global__ void __launch_bounds__(256) split_all(
    const float* __restrict__ Wq, const float* __restrict__ Wk,
    const float* __restrict__ Wv, const float* __restrict__ Wout,
    const float* __restrict__ Woff1, float kscale)
{
    int idx = blockIdx.x * 256 + threadIdx.x;
    if (idx < 4 * 65536) {
        int w = idx >> 16, i = idx & 65535;
        const float* srcs[4] = {Wq, Wk, Wv, Wout};
        __half* dst[4] = {w_q16, w_k16, w_v16, w_o16};
        float v = srcs[w][i] * (w == 1 ? kscale : 1.0f);
        dst[w][i] = __float2half_rn(v);
    } else {
        int i = idx - 4 * 65536;
        int o = i / 2304;
        int r = i - o * 2304;
        int c = r / 9;
        int t = r - c * 9;
        w_c16[o * 2304 + t * 256 + c] = __float2half_rn(Woff1[i]);
    }
}

// =====================================================================
// GEMM via mma.sync fp16: A single plane, B 2-term fp16 -> 2 mma.
// BMODE: 0 = fp32 B (split at store), 1 = fp16 plane B.
// OMODE bit0: fp32 out (+bias); bit1: fp16 split planes out.
// CTA tile 128x128, grid (8, O/128, 8), 256 threads.
// =====================================================================
template<int BMODE, int OMODE>
__global__ void __launch_bounds__(256) gemm_mma(
    const __half* __restrict__ Af,
    const float* __restrict__ Bf,
    const __half* __restrict__ Bh, const __half* __restrict__ Bl,
    const float* __restrict__ bias,
    float* __restrict__ Yf,
    __half* __restrict__ Yh, __half* __restrict__ Yl,
    int Cin)
{
    __shared__ __align__(16) __half sA[128][SA_STRIDE];
    __shared__ __align__(16) __half sB[2][32][SB_STRIDE];
    const int b  = blockIdx.z;
    const int o0 = blockIdx.y * 128;
    const int p0 = blockIdx.x * 128;
    const int O  = gridDim.y * 128;
    const size_t bB = (size_t)b * Cin * Pn;
    const size_t bY = (size_t)b * O * Pn;
    const int tid  = threadIdx.x;
    const int lane = tid & 31;
    const int wid  = tid >> 5;
    const int wm   = wid & 3;
    const int wn   = wid >> 2;

    float d[2][8][4];
    #pragma unroll
    for (int mf = 0; mf < 2; mf++)
        #pragma unroll
        for (int nf = 0; nf < 8; nf++)
            #pragma unroll
            for (int i = 0; i < 4; i++) d[mf][nf][i] = 0.0f;

    const int a_row  = (lane & 7) + ((lane >> 3) & 1) * 8;
    const int a_colk = ((lane >> 4) & 1) * 8;
    const int b_rowk = (lane & 7) + ((lane >> 3) & 1) * 8;
    const int b_ncol = ((lane >> 4) & 1) * 8;

    uint4  ra[2];
    float4 rbf[4];
    uint4  rb[2][2];

    auto loadA = [&](int c0) {
        #pragma unroll
        for (int i = 0; i < 2; i++) {
            int e = tid + i * 256;
            int o = e >> 2, c8 = (e & 3) * 8;
            ra[i] = *reinterpret_cast<const uint4*>(
                Af + (size_t)(o0 + o) * Cin + c0 + c8);
        }
    };
    auto storeA = [&]() {
        #pragma unroll
        for (int i = 0; i < 2; i++) {
            int e = tid + i * 256;
            int o = e >> 2, c8 = (e & 3) * 8;
            *reinterpret_cast<uint4*>(&sA[o][c8]) = ra[i];
        }
    };
    auto loadB = [&](int c0) {
        if (BMODE == 0) {
            #pragma unroll
            for (int i = 0; i < 4; i++) {
                int e = tid + i * 256;
                int k = e >> 5, p4 = (e & 31) * 4;
                rbf[i] = *reinterpret_cast<const float4*>(
                    Bf + bB + (size_t)(c0 + k) * Pn + p0 + p4);
            }
        } else {
            #pragma unroll
            for (int t = 0; t < 2; t++) {
                const __half* Bp = t ? Bl : Bh;
                #pragma unroll
                for (int i = 0; i < 2; i++) {
                    int e = tid + i * 256;
                    int k = e >> 4, p8 = (e & 15) * 8;
                    rb[t][i] = *reinterpret_cast<const uint4*>(
                        Bp + bB + (size_t)(c0 + k) * Pn + p0 + p8);
                }
            }
        }
    };
    auto storeB = [&]() {
        if (BMODE == 0) {
            #pragma unroll
            for (int i = 0; i < 4; i++) {
                int e = tid + i * 256;
                int k = e >> 5, p4 = (e & 31) * 4;
                float4 x = rbf[i];
                uint32_t h0, l0, h1, l1;
                split2h(x.x, x.y, h0, l0);
                split2h(x.z, x.w, h1, l1);
                *reinterpret_cast<uint32_t*>(&sB[0][k][p4])     = h0;
                *reinterpret_cast<uint32_t*>(&sB[0][k][p4 + 2]) = h1;
                *reinterpret_cast<uint32_t*>(&sB[1][k][p4])     = l0;
                *reinterpret_cast<uint32_t*>(&sB[1][k][p4 + 2]) = l1;
            }
        } else {
            #pragma unroll
            for (int t = 0; t < 2; t++)
                #pragma unroll
                for (int i = 0; i < 2; i++) {
                    int e = tid + i * 256;
                    int k = e >> 4, p8 = (e & 15) * 8;
                    *reinterpret_cast<uint4*>(&sB[t][k][p8]) = rb[t][i];
                }
        }
    };

    loadA(0); loadB(0);
    storeA(); storeB();
    __syncthreads();

    for (int c0 = 0; c0 < Cin; c0 += 32) {
        bool more = (c0 + 32 < Cin);
        if (more) { loadA(c0 + 32); loadB(c0 + 32); }

        #pragma unroll
        for (int kk = 0; kk < 32; kk += 16) {
            uint32_t afr[2][4];
            #pragma unroll
            for (int mf = 0; mf < 2; mf++)
                ldsm_x4(afr[mf],
                    smem_u32(&sA[wm * 32 + mf * 16 + a_row][kk + a_colk]));
            uint32_t bfr[2][8][2];
            #pragma unroll
            for (int t2 = 0; t2 < 2; t2++)
                #pragma unroll
                for (int nf2 = 0; nf2 < 4; nf2++) {
                    uint32_t r[4];
                    ldsm_x4_t(r, smem_u32(
                        &sB[t2][kk + b_rowk][wn * 64 + nf2 * 16 + b_ncol]));
                    bfr[t2][2 * nf2][0] = r[0]; bfr[t2][2 * nf2][1] = r[1];
                    bfr[t2][2 * nf2 + 1][0] = r[2]; bfr[t2][2 * nf2 + 1][1] = r[3];
                }
            #pragma unroll
            for (int mf = 0; mf < 2; mf++)
                #pragma unroll
                for (int nf = 0; nf < 8; nf++) {
                    mma_f16(d[mf][nf], afr[mf], bfr[0][nf]);
                    mma_f16(d[mf][nf], afr[mf], bfr[1][nf]);
                }
        }
        __syncthreads();
        if (more) { storeA(); storeB(); __syncthreads(); }
    }

    #pragma unroll
    for (int mf = 0; mf < 2; mf++) {
        int r = o0 + wm * 32 + mf * 16 + (lane >> 2);
        float b0v = bias ? bias[r] : 0.0f;
        float b1v = bias ? bias[r + 8] : 0.0f;
        #pragma unroll
        for (int nf = 0; nf < 8; nf++) {
            int cb = p0 + wn * 64 + nf * 8 + (lane & 3) * 2;
            float v00 = d[mf][nf][0] + b0v, v01 = d[mf][nf][1] + b0v;
            float v10 = d[mf][nf][2] + b1v, v11 = d[mf][nf][3] + b1v;
            if (OMODE & 1) {
                *reinterpret_cast<float2*>(Yf + bY + (size_t)r * Pn + cb) =
                    make_float2(v00, v01);
                *reinterpret_cast<float2*>(Yf + bY + (size_t)(r + 8) * Pn + cb) =
                    make_float2(v10, v11);
            }
            if (OMODE & 2) {
                uint32_t h0, l0, h1, l1;
                split2h(v00, v01, h0, l0);
                split2h(v10, v11, h1, l1);
                *reinterpret_cast<uint32_t*>(Yh + bY + (size_t)r * Pn + cb)       = h0;
                *reinterpret_cast<uint32_t*>(Yl + bY + (size_t)r * Pn + cb)       = l0;
                *reinterpret_cast<uint32_t*>(Yh + bY + (size_t)(r + 8) * Pn + cb) = h1;
                *reinterpret_cast<uint32_t*>(Yl + bY + (size_t)(r + 8) * Pn + cb) = l1;
            }
        }
    }
}

// =====================================================================
// Fused K+V projection (fp16, 2 mma). K -> single plane; V -> split.
// grid (8, 4, 8), 256 threads: warps 0-3 -> K, warps 4-7 -> V.
// =====================================================================
__global__ void __launch_bounds__(256) gemm_kv()
{
    __shared__ __align__(16) __half sAk[64][SA_STRIDE];
    __shared__ __align__(16) __half sAv[64][SA_STRIDE];
    __shared__ __align__(16) __half sB[2][32][SB_STRIDE];
    const int b  = blockIdx.z;
    const int o0 = blockIdx.y * 64;
    const int p0 = blockIdx.x * 128;
    const size_t bB = (size_t)b * Cn * Pn;
    const int tid  = threadIdx.x;
    const int lane = tid & 31;
    const int wid  = tid >> 5;
    const int half = wid >> 2;
    const int w2   = wid & 3;
    const int wm   = w2 & 1;
    const int wn   = w2 >> 1;

    float d[2][8][4];
    #pragma unroll
    for (int mf = 0; mf < 2; mf++)
        #pragma unroll
        for (int nf = 0; nf < 8; nf++)
            #pragma unroll
            for (int i = 0; i < 4; i++) d[mf][nf][i] = 0.0f;

    const int a_row  = (lane & 7) + ((lane >> 3) & 1) * 8;
    const int a_colk = ((lane >> 4) & 1) * 8;
    const int b_rowk = (lane & 7) + ((lane >> 3) & 1) * 8;
    const int b_ncol = ((lane >> 4) & 1) * 8;

    const int ao = tid >> 2, ac8 = (tid & 3) * 8;
    uint4 ra[2];
    uint4 rb[2][2];
    auto loadA = [&](int c0) {
        size_t off = (size_t)(o0 + ao) * Cn + c0 + ac8;
        ra[0] = *reinterpret_cast<const uint4*>(w_k16 + off);
        ra[1] = *reinterpret_cast<const uint4*>(w_v16 + off);
    };
    auto storeA = [&]() {
        *reinterpret_cast<uint4*>(&sAk[ao][ac8]) = ra[0];
        *reinterpret_cast<uint4*>(&sAv[ao][ac8]) = ra[1];
    };
    auto loadB = [&](int c0) {
        #pragma unroll
        for (int t = 0; t < 2; t++) {
            const __half* Bp = t ? g_sl : g_sh;
            #pragma unroll
            for (int i = 0; i < 2; i++) {
                int e = tid + i * 256;
                int k = e >> 4, p8 = (e & 15) * 8;
                rb[t][i] = *reinterpret_cast<const uint4*>(
                    Bp + bB + (size_t)(c0 + k) * Pn + p0 + p8);
            }
        }
    };
    auto storeB = [&]() {
        #pragma unroll
        for (int t = 0; t < 2; t++)
            #pragma unroll
            for (int i = 0; i < 2; i++) {
                int e = tid + i * 256;
                int k = e >> 4, p8 = (e & 15) * 8;
                *reinterpret_cast<uint4*>(&sB[t][k][p8]) = rb[t][i];
            }
    };

    loadA(0); loadB(0);
    storeA(); storeB();
    __syncthreads();

    for (int c0 = 0; c0 < Cn; c0 += 32) {
        bool more = (c0 + 32 < Cn);
        if (more) { loadA(c0 + 32); loadB(c0 + 32); }

        #pragma unroll
        for (int kk = 0; kk < 32; kk += 16) {
            uint32_t afr[2][4];
            #pragma unroll
            for (int mf = 0; mf < 2; mf++) {
                const __half* base = half
                    ? &sAv[wm * 32 + mf * 16 + a_row][kk + a_colk]
                    : &sAk[wm * 32 + mf * 16 + a_row][kk + a_colk];
                ldsm_x4(afr[mf], smem_u32(base));
            }
            uint32_t bfr[2][8][2];
            #pragma unroll
            for (int t2 = 0; t2 < 2; t2++)
                #pragma unroll
                for (int nf2 = 0; nf2 < 4; nf2++) {
                    uint32_t r[4];
                    ldsm_x4_t(r, smem_u32(
                        &sB[t2][kk + b_rowk][wn * 64 + nf2 * 16 + b_ncol]));
                    bfr[t2][2 * nf2][0] = r[0]; bfr[t2][2 * nf2][1] = r[1];
                    bfr[t2][2 * nf2 + 1][0] = r[2]; bfr[t2][2 * nf2 + 1][1] = r[3];
                }
            #pragma unroll
            for (int mf = 0; mf < 2; mf++)
                #pragma unroll
                for (int nf = 0; nf < 8; nf++) {
                    mma_f16(d[mf][nf], afr[mf], bfr[0][nf]);
                    mma_f16(d[mf][nf], afr[mf], bfr[1][nf]);
                }
        }
        __syncthreads();
        if (more) { storeA(); storeB(); __syncthreads(); }
    }

    #pragma unroll
    for (int mf = 0; mf < 2; mf++) {
        int r = o0 + wm * 32 + mf * 16 + (lane >> 2);
        #pragma unroll
        for (int nf = 0; nf < 8; nf++) {
            int cb = p0 + wn * 64 + nf * 8 + (lane & 3) * 2;
            if (half == 0) {
                uint32_t p0w = cvt_h2(d[mf][nf][0], d[mf][nf][1]);
                uint32_t p1w = cvt_h2(d[mf][nf][2], d[mf][nf][3]);
                *reinterpret_cast<uint32_t*>(g_kf + bB + (size_t)r * Pn + cb)       = p0w;
                *reinterpret_cast<uint32_t*>(g_kf + bB + (size_t)(r + 8) * Pn + cb) = p1w;
            } else {
                uint32_t h0, l0, h1, l1;
                split2h(d[mf][nf][0], d[mf][nf][1], h0, l0);
                split2h(d[mf][nf][2], d[mf][nf][3], h1, l1);
                *reinterpret_cast<uint32_t*>(g_vh + bB + (size_t)r * Pn + cb)       = h0;
                *reinterpret_cast<uint32_t*>(g_vl + bB + (size_t)r * Pn + cb)       = l0;
                *reinterpret_cast<uint32_t*>(g_vh + bB + (size_t)(r + 8) * Pn + cb) = h1;
                *reinterpret_cast<uint32_t*>(g_vl + bB + (size_t)(r + 8) * Pn + cb) = l1;
            }
        }
    }
}

// =====================================================================
// Conv as GEMM with FUSED shift (fp16, 2 mma). splitK=2.
// grid (16, 2, 8), 256 threads.
// =====================================================================
__global__ void __launch_bounds__(256) conv_mma3()
{
    __shared__ __align__(16) __half sA[128][SA_STRIDE];
    __shared__ __align__(16) __half sB[2][32][SC_STRIDE];
    const int b  = blockIdx.z;
    const int ks = blockIdx.y;
    const int p0 = blockIdx.x * 64;
    float* Yb = (ks ? g_h1b : g_h1a) + (size_t)b * 128 * Pn;
    const size_t bQ = (size_t)b * Cn * Pn;
    const int tid  = threadIdx.x;
    const int lane = tid & 31;
    const int wid  = tid >> 5;
    const int wm   = wid & 3;
    const int wn   = wid >> 2;

    float d[2][4][4];
    #pragma unroll
    for (int mf = 0; mf < 2; mf++)
        #pragma unroll
        for (int nf = 0; nf < 4; nf++)
            #pragma unroll
            for (int i = 0; i < 4; i++) d[mf][nf][i] = 0.0f;

    const int a_row  = (lane & 7) + ((lane >> 3) & 1) * 8;
    const int a_colk = ((lane >> 4) & 1) * 8;
    const int b_rowk = (lane & 7) + ((lane >> 3) & 1) * 8;
    const int b_ncol = ((lane >> 4) & 1) * 8;

    uint4 ra[2], rb[2];
    auto loadA = [&](int c0) {
        #pragma unroll
        for (int i = 0; i < 2; i++) {
            int e = tid + i * 256;
            int o = e >> 2, c8 = (e & 3) * 8;
            ra[i] = *reinterpret_cast<const uint4*>(
                w_c16 + (size_t)o * 2304 + c0 + c8);
        }
    };
    auto storeA = [&]() {
        #pragma unroll
        for (int i = 0; i < 2; i++) {
            int e = tid + i * 256;
            int o = e >> 2, c8 = (e & 3) * 8;
            *reinterpret_cast<uint4*>(&sA[o][c8]) = ra[i];
        }
    };
    const int bk = tid >> 3, bp8 = (tid & 7) * 8;
    const int P  = p0 + bp8;
    const int x0 = P & 31;
    const int yb = P >> 5;
    auto loadB = [&](int c0) {
        int t  = c0 >> 8;
        int cc = (c0 & 255) + bk;
        int ty = t / 3;
        int dy = ty - 1;
        int dx = t - ty * 3 - 1;
        int ys = yb + dy;
        bool yok = (unsigned)ys < 32u;
        size_t rowoff = bQ + (size_t)cc * Pn + ys * 32;
        #pragma unroll
        for (int pl = 0; pl < 2; pl++) {
            const __half* Qp = pl ? g_ql : g_qh;
            uint4 v = make_uint4(0u, 0u, 0u, 0u);
            if (yok) {
                uint4 w = *reinterpret_cast<const uint4*>(Qp + rowoff + x0);
                if (dx == 0) {
                    v = w;
                } else if (dx > 0) {
                    uint32_t extra = 0;
                    if (x0 != 24)
                        extra = *reinterpret_cast<const uint16_t*>(
                            Qp + rowoff + x0 + 8);
                    v.x = __funnelshift_r(w.x, w.y, 16);
                    v.y = __funnelshift_r(w.y, w.z, 16);
                    v.z = __funnelshift_r(w.z, w.w, 16);
                    v.w = (w.w >> 16) | (extra << 16);
                } else {
                    uint32_t extra = 0;
                    if (x0 != 0)
                        extra = *reinterpret_cast<const uint16_t*>(
                            Qp + rowoff + x0 - 1);
                    v.x = (w.x << 16) | extra;
                    v.y = __funnelshift_l(w.x, w.y, 16);
                    v.z = __funnelshift_l(w.y, w.z, 16);
                    v.w = __funnelshift_l(w.z, w.w, 16);
                }
            }
            rb[pl] = v;
        }
    };
    auto storeB = [&]() {
        *reinterpret_cast<uint4*>(&sB[0][bk][bp8]) = rb[0];
        *reinterpret_cast<uint4*>(&sB[1][bk][bp8]) = rb[1];
    };

    const int cbeg = ks * 1152, cend = cbeg + 1152;
    loadA(cbeg); loadB(cbeg);
    storeA(); storeB();
    __syncthreads();

    for (int c0 = cbeg; c0 < cend; c0 += 32) {
        bool more = (c0 + 32 < cend);
        if (more) { loadA(c0 + 32); loadB(c0 + 32); }

        #pragma unroll
        for (int kk = 0; kk < 32; kk += 16) {
            uint32_t afr[2][4];
            #pragma unroll
            for (int mf = 0; mf < 2; mf++)
                ldsm_x4(afr[mf],
                    smem_u32(&sA[wm * 32 + mf * 16 + a_row][kk + a_colk]));
            uint32_t bfr[2][4][2];
            #pragma unroll
            for (int t2 = 0; t2 < 2; t2++)
                #pragma unroll
                for (int nf2 = 0; nf2 < 2; nf2++) {
                    uint32_t r[4];
                    ldsm_x4_t(r, smem_u32(
                        &sB[t2][kk + b_rowk][wn * 32 + nf2 * 16 + b_ncol]));
                    bfr[t2][2 * nf2][0] = r[0]; bfr[t2][2 * nf2][1] = r[1];
                    bfr[t2][2 * nf2 + 1][0] = r[2]; bfr[t2][2 * nf2 + 1][1] = r[3];
                }
            #pragma unroll
            for (int mf = 0; mf < 2; mf++)
                #pragma unroll
                for (int nf = 0; nf < 4; nf++) {
                    mma_f16(d[mf][nf], afr[mf], bfr[0][nf]);
                    mma_f16(d[mf][nf], afr[mf], bfr[1][nf]);
                }
        }
        __syncthreads();
        if (more) { storeA(); storeB(); __syncthreads(); }
    }
    #pragma unroll
    for (int mf = 0; mf < 2; mf++) {
        int r = wm * 32 + mf * 16 + (lane >> 2);
        #pragma unroll
        for (int nf = 0; nf < 4; nf++) {
            int cb = p0 + wn * 32 + nf * 8 + (lane & 3) * 2;
            *reinterpret_cast<float2*>(Yb + (size_t)r * Pn + cb) =
                make_float2(d[mf][nf][0], d[mf][nf][1]);
            *reinterpret_cast<float2*>(Yb + (size_t)(r + 8) * Pn + cb) =
                make_float2(d[mf][nf][2], d[mf][nf][3]);
        }
    }
}

// =====================================================================
// Offsets, 16-way channel split. grid (64, 8) = 512 CTAs.
// =====================================================================
__global__ void __launch_bounds__(256) offs_kernel4(
    const float* __restrict__ Woff2, const float* __restrict__ boff2,
    const float* __restrict__ boff1)
{
    __shared__ float red[2][16][16];
    const int b   = blockIdx.y;
    const int px  = threadIdx.x & 15;
    const int seg = threadIdx.x >> 4;          // 0..15
    const int p   = blockIdx.x * 16 + px;
    const float* h1a = g_h1a + (size_t)b * 128 * Pn;
    const float* h1b = g_h1b + (size_t)b * 128 * Pn;
    const int c0 = seg * 8;
    float ox0 = 0.0f, oy0 = 0.0f, ox1 = 0.0f, oy1 = 0.0f;
    #pragma unroll
    for (int c = c0; c < c0 + 8; c += 2) {
        size_t i0 = (size_t)c * Pn + p;
        size_t i1 = (size_t)(c + 1) * Pn + p;
        float h0 = fmaxf(h1a[i0] + h1b[i0] + boff1[c], 0.0f);
        float h1 = fmaxf(h1a[i1] + h1b[i1] + boff1[c + 1], 0.0f);
        ox0 += Woff2[c] * h0;       oy0 += Woff2[128 + c] * h0;
        ox1 += Woff2[c + 1] * h1;   oy1 += Woff2[128 + c + 1] * h1;
    }
    red[0][seg][px] = ox0 + ox1;
    red[1][seg][px] = oy0 + oy1;
    __syncthreads();
    if (threadIdx.x < 16) {
        float sx = boff2[0], sy = boff2[1];
        #pragma unroll
        for (int s = 0; s < 16; s++) {
            sx += red[0][s][threadIdx.x];
            sy += red[1][s][threadIdx.x];
        }
        g_off[((size_t)b * 2 + 0) * Pn + blockIdx.x * 16 + threadIdx.x] = sx * 0.1f;
        g_off[((size_t)b * 2 + 1) * Pn + blockIdx.x * 16 + threadIdx.x] = sy * 0.1f;
    }
}

// =====================================================================
// Bilinear grid sample -> fp16 split planes. grid (4, 8, 16).
// =====================================================================
__global__ void __launch_bounds__(256) samp_kernel(const float* __restrict__ kv)
{
    const int b  = blockIdx.y;
    const int p  = blockIdx.x * 256 + threadIdx.x;
    const int c0 = blockIdx.z * 16;
    float ox = g_off[((size_t)b * 2 + 0) * Pn + p];
    float oy = g_off[((size_t)b * 2 + 1) * Pn + p];
    int px = p & 31, py = p >> 5;
    float gx = -1.0f + px * (2.0f / 31.0f);
    float gy = -1.0f + py * (2.0f / 31.0f);
    float x = (gx + ox + 1.0f) * 0.5f * 31.0f;
    float y = (gy + oy + 1.0f) * 0.5f * 31.0f;
    x = fminf(fmaxf(x, 0.0f), 31.0f);
    y = fminf(fmaxf(y, 0.0f), 31.0f);
    float x0f = floorf(x), y0f = floorf(y);
    float wx = x - x0f, wy = y - y0f;
    int x0 = (int)x0f, y0 = (int)y0f;
    int x1 = min(x0 + 1, 31), y1 = min(y0 + 1, 31);
    float w00 = (1.0f - wx) * (1.0f - wy);
    float w01 = wx * (1.0f - wy);
    float w10 = (1.0f - wx) * wy;
    float w11 = wx * wy;
    int i00 = (y0 << 5) + x0, i01 = (y0 << 5) + x1;
    int i10 = (y1 << 5) + x0, i11 = (y1 << 5) + x1;
    const float* kvb = kv + (size_t)b * Cn * Pn;
    const size_t ob = (size_t)b * Cn * Pn;
    #pragma unroll 4
    for (int c = c0; c < c0 + 16; c++) {
        const float* pl = kvb + (size_t)c * Pn;
        float v = w00 * pl[i00] + w01 * pl[i01] + w10 * pl[i10] + w11 * pl[i11];
        __half h, l;
        split_h(v, h, l);
        g_sh[ob + (size_t)c * Pn + p] = h;
        g_sl[ob + (size_t)c * Pn + p] = l;
    }
}

// =====================================================================
// Flash attention, pipelined KV loads (round-15 structure; Q planes
// now fp16 -> no conversion). grid (8, 64), 256 threads.
// =====================================================================
__global__ void __launch_bounds__(256) attn_mma()
{
    __shared__ __align__(16) __half sK[32][SB_STRIDE];
    __shared__ __align__(16) __half sV[2][32][SB_STRIDE];

    const int bh = blockIdx.y;
    const int b  = bh >> 3, h = bh & 7;
    const int p0 = blockIdx.x * 128;
    const int tid  = threadIdx.x;
    const int lane = tid & 31;
    const int wm   = tid >> 5;
    const size_t base = ((size_t)b * Cn + h * HD) * Pn;

    const int krow = (lane & 7) + ((lane >> 3) & 1) * 8;
    const int ncol = ((lane >> 4) & 1) * 8;

    // ---- stage Q fp16 planes into sV region, extract A-frags ----
    __half* stage = &sV[0][0][0];
    #pragma unroll
    for (int t = 0; t < 2; t++) {
        const __half* Qp = (t ? g_ql : g_qh) + base;
        #pragma unroll
        for (int i = 0; i < 2; i++) {
            int e = tid + i * 256;
            int d = e >> 4, p8 = (e & 15) * 8;
            uint4 v = *reinterpret_cast<const uint4*>(Qp + (size_t)d * Pn + p0 + p8);
            *reinterpret_cast<uint4*>(stage + (size_t)(t * 32 + d) * SB_STRIDE + p8) = v;
        }
    }
    __syncthreads();
    uint32_t aQ[2][2][4];   // [plane][kstep][4]
    #pragma unroll
    for (int t = 0; t < 2; t++)
        #pragma unroll
        for (int ks = 0; ks < 2; ks++) {
            uint32_t r[4];
            ldsm_x4_t(r, smem_u32(
                stage + (size_t)(t * 32 + ks * 16 + krow) * SB_STRIDE + wm * 16 + ncol));
            aQ[t][ks][0] = r[0]; aQ[t][ks][1] = r[2];
            aQ[t][ks][2] = r[1]; aQ[t][ks][3] = r[3];
        }

    float O[4][4];
    #pragma unroll
    for (int nf = 0; nf < 4; nf++)
        #pragma unroll
        for (int i = 0; i < 4; i++) O[nf][i] = 0.0f;
    float lsum0 = 0.0f, lsum1 = 0.0f;

    const int vrow = (lane & 7) + ((lane >> 3) & 1) * 8;
    const int vcol = ((lane >> 4) & 1) * 8;

    const int ld_d  = tid >> 4;
    const int ld_p8 = (tid & 15) * 8;
    uint4 rk[2], rv[2][2];
    auto loadKV = [&](int kv0) {
        const __half* Kp = g_kf + base;
        #pragma unroll
        for (int i = 0; i < 2; i++) {
            int d = ld_d + i * 16;
            rk[i] = *reinterpret_cast<const uint4*>(Kp + (size_t)d * Pn + kv0 + ld_p8);
        }
        #pragma unroll
        for (int t = 0; t < 2; t++) {
            const __half* Vp = (t ? g_vl : g_vh) + base;
            #pragma unroll
            for (int i = 0; i < 2; i++) {
                int d = ld_d + i * 16;
                rv[t][i] = *reinterpret_cast<const uint4*>(
                    Vp + (size_t)d * Pn + kv0 + ld_p8);
            }
        }
    };
    auto storeKV = [&]() {
        #pragma unroll
        for (int i = 0; i < 2; i++) {
            int d = ld_d + i * 16;
            *reinterpret_cast<uint4*>(&sK[d][ld_p8]) = rk[i];
            #pragma unroll
            for (int t = 0; t < 2; t++)
                *reinterpret_cast<uint4*>(&sV[t][d][ld_p8]) = rv[t][i];
        }
    };

    loadKV(0);

    for (int kt = 0; kt < 8; kt++) {
        __syncthreads();     // staging/compute reads done before overwrite
        storeKV();
        __syncthreads();
        if (kt + 1 < 8) loadKV((kt + 1) * 128);

        float S[16][4];
        #pragma unroll
        for (int f = 0; f < 16; f++)
            #pragma unroll
            for (int i = 0; i < 4; i++) S[f][i] = 0.0f;

        #pragma unroll
        for (int nb = 0; nb < 8; nb++) {
            uint32_t bk[2][4];
            #pragma unroll
            for (int ks = 0; ks < 2; ks++)
                ldsm_x4_t(bk[ks],
                    smem_u32(&sK[ks * 16 + krow][nb * 16 + ncol]));
            #pragma unroll
            for (int half = 0; half < 2; half++) {
                float* s = S[nb * 2 + half];
                #pragma unroll
                for (int ks = 0; ks < 2; ks++) {
                    uint32_t bb[2] = {bk[ks][2 * half], bk[ks][2 * half + 1]};
                    mma_f16(s, aQ[0][ks], bb);
                    mma_f16(s, aQ[1][ks], bb);
                }
            }
        }
        #pragma unroll
        for (int f = 0; f < 16; f++) {
            S[f][0] = ex2f(S[f][0]); S[f][1] = ex2f(S[f][1]);
            S[f][2] = ex2f(S[f][2]); S[f][3] = ex2f(S[f][3]);
            lsum0 += S[f][0] + S[f][1];
            lsum1 += S[f][2] + S[f][3];
        }
        #pragma unroll
        for (int ks8 = 0; ks8 < 8; ks8++) {
            uint32_t ah[4];
            const float* f0 = S[2 * ks8];
            const float* f1 = S[2 * ks8 + 1];
            ah[0] = cvt_h2(f0[0], f0[1]);
            ah[1] = cvt_h2(f0[2], f0[3]);
            ah[2] = cvt_h2(f1[0], f1[1]);
            ah[3] = cvt_h2(f1[2], f1[3]);
            uint32_t bv[2][2][4];
            #pragma unroll
            for (int t = 0; t < 2; t++)
                #pragma unroll
                for (int db = 0; db < 2; db++)
                    ldsm_x4(bv[t][db],
                        smem_u32(&sV[t][db * 16 + vrow][ks8 * 16 + vcol]));
            #pragma unroll
            for (int nf = 0; nf < 4; nf++) {
                int db = nf >> 1, wh = nf & 1;
                uint32_t vhi[2] = {bv[0][db][wh], bv[0][db][wh + 2]};
                uint32_t vlo[2] = {bv[1][db][wh], bv[1][db][wh + 2]};
                mma_f16(O[nf], ah, vhi);
                mma_f16(O[nf], ah, vlo);
            }
        }
    }
    lsum0 += __shfl_xor_sync(0xffffffffu, lsum0, 1);
    lsum0 += __shfl_xor_sync(0xffffffffu, lsum0, 2);
    lsum1 += __shfl_xor_sync(0xffffffffu, lsum1, 1);
    lsum1 += __shfl_xor_sync(0xffffffffu, lsum1, 2);
    float inv0 = 1.0f / lsum0, inv1 = 1.0f / lsum1;
    int p = p0 + wm * 16 + (lane >> 2);
    #pragma unroll
    for (int nf = 0; nf < 4; nf++) {
        int d = nf * 8 + (lane & 3) * 2;
        float v0 = O[nf][0] * inv0, v1 = O[nf][1] * inv0;
        float v2 = O[nf][2] * inv1, v3 = O[nf][3] * inv1;
        __half hh, ll;
        split_h(v0, hh, ll);
        g_oh[base + (size_t)d * Pn + p] = hh;       g_ol[base + (size_t)d * Pn + p] = ll;
        split_h(v1, hh, ll);
        g_oh[base + (size_t)(d + 1) * Pn + p] = hh; g_ol[base + (size_t)(d + 1) * Pn + p] = ll;
        split_h(v2, hh, ll);
        g_oh[base + (size_t)d * Pn + p + 8] = hh;   g_ol[base + (size_t)d * Pn + p + 8] = ll;
        split_h(v3, hh, ll);
        g_oh[base + (size_t)(d + 1) * Pn + p + 8] = hh;
        g_ol[base + (size_t)(d + 1) * Pn + p + 8] = ll;
    }
}

// =====================================================================
extern "C" void kernel_launch(void* const* d_in, const int* in_sizes, int n_in,
                              void* d_out, int out_size)
{
    (void)in_sizes; (void)n_in; (void)out_size;
    const float* query_map = (const float*)d_in[0];
    const float* kv_map    = (const float*)d_in[1];
    const float* Wq        = (const float*)d_in[2];
    const float* Wk        = (const float*)d_in[3];
    const float* Wv        = (const float*)d_in[4];
    const float* Woff1     = (const float*)d_in[5];
    const float* boff1     = (const float*)d_in[6];
    const float* Woff2     = (const float*)d_in[7];
    const float* boff2     = (const float*)d_in[8];
    const float* Wout      = (const float*)d_in[9];
    const float* bout      = (const float*)d_in[10];
    float* out = (float*)d_out;

    const float kscale = 0.17677669529663687f * 1.4426950408889634f;

    __half *pqh, *pql, *poh, *pol, *pwq, *pwo;
    cudaGetSymbolAddress((void**)&pqh, g_qh);  cudaGetSymbolAddress((void**)&pql, g_ql);
    cudaGetSymbolAddress((void**)&poh, g_oh);  cudaGetSymbolAddress((void**)&pol, g_ol);
    cudaGetSymbolAddress((void**)&pwq, w_q16); cudaGetSymbolAddress((void**)&pwo, w_o16);

    // 0) one-shot weight prep (all fp16 single plane)
    split_all<<<2176, 256>>>(Wq, Wk, Wv, Wout, Woff1, kscale);
    // 1) q projection -> fp16 split planes (conv + attn)
    gemm_mma<0, 2><<<dim3(8, 2, 8), 256>>>(
        pwq, query_map, nullptr, nullptr, nullptr,
        nullptr, pqh, pql, 256);
    // 2) conv GEMM with fused shift (splitK=2)
    conv_mma3<<<dim3(16, 2, 8), 256>>>();
    // 3) offsets — 16-way split reduction
    offs_kernel4<<<dim3(64, 8), 256>>>(Woff2, boff2, boff1);
    // 4) bilinear sample -> fp16 split planes
    samp_kernel<<<dim3(4, 8, 16), 256>>>(kv_map);
    // 5) fused K+V projections
    gemm_kv<<<dim3(8, 4, 8), 256>>>();
    // 6) attention (pipelined; 2-mma QK, 2-mma PV)
    attn_mma<<<dim3(8, 64), 256>>>();
    // 7) out = Wout @ attn_out + bout
    gemm_mma<1, 1><<<dim3(8, 2, 8), 256>>>(
        pwo, nullptr, poh, pol, bout,
        out, nullptr, nullptr, 256);
}

// round 17
// speedup vs baseline: 1.7536x; 1.0649x over previous
#include <cuda_runtime.h>
#include <cuda_bf16.h>
#include <cuda_fp16.h>
#include <cstdint>

#define Bn 8
#define Cn 256
#define Pn 1024
#define HEADS 8
#define HD 32

// ---- fp32 scratch ----
__device__ float g_h1a[Bn*128*Pn];  // conv partial sums (splitK halves)
__device__ float g_h1b[Bn*128*Pn];
__device__ float g_off[Bn*2*Pn];

// ---- fp16 interchange planes ----
__device__ __half g_qh[Bn*Cn*Pn], g_ql[Bn*Cn*Pn];   // q 2-term (conv needs both; attn uses hi)
__device__ __half g_kf[Bn*Cn*Pn];                   // K single plane (scale folded)
__device__ __half g_vf[Bn*Cn*Pn];                   // V single plane
__device__ __half g_sh[Bn*Cn*Pn], g_sl[Bn*Cn*Pn];   // sampled kv 2-term
__device__ __half g_oh[Bn*Cn*Pn], g_ol[Bn*Cn*Pn];   // attn out 2-term

// ---- fp16 weights ----
__device__ __half w_qh16[Cn*Cn], w_ql16[Cn*Cn];     // Wq 2-term (offsets path)
__device__ __half w_k16[Cn*Cn];                     // single, pre-scaled by kscale
__device__ __half w_v16[Cn*Cn];                     // single
__device__ __half w_o16[Cn*Cn];                     // single
__device__ __half w_ch16[128*2304], w_cl16[128*2304]; // conv W 2-term [o][t*256+c]

// ---- helpers ----
__device__ __forceinline__ uint32_t smem_u32(const void* p) {
    uint32_t a;
    asm("{ .reg .u64 t; cvta.to.shared.u64 t, %1; cvt.u32.u64 %0, t; }"
        : "=r"(a) : "l"(p));
    return a;
}
__device__ __forceinline__ void ldsm_x4(uint32_t r[4], uint32_t addr) {
    asm volatile("ldmatrix.sync.aligned.m8n8.x4.shared.b16 {%0,%1,%2,%3}, [%4];"
        : "=r"(r[0]), "=r"(r[1]), "=r"(r[2]), "=r"(r[3]) : "r"(addr));
}
__device__ __forceinline__ void ldsm_x4_t(uint32_t r[4], uint32_t addr) {
    asm volatile("ldmatrix.sync.aligned.m8n8.x4.trans.shared.b16 {%0,%1,%2,%3}, [%4];"
        : "=r"(r[0]), "=r"(r[1]), "=r"(r[2]), "=r"(r[3]) : "r"(addr));
}
__device__ __forceinline__ void mma_f16(float d[4], const uint32_t a[4],
                                        const uint32_t b[2]) {
    asm volatile(
        "mma.sync.aligned.m16n8k16.row.col.f32.f16.f16.f32 "
        "{%0,%1,%2,%3}, {%4,%5,%6,%7}, {%8,%9}, {%0,%1,%2,%3};"
        : "+f"(d[0]), "+f"(d[1]), "+f"(d[2]), "+f"(d[3])
        : "r"(a[0]), "r"(a[1]), "r"(a[2]), "r"(a[3]), "r"(b[0]), "r"(b[1]));
}
__device__ __forceinline__ void split_h(float x, __half& hi, __half& lo) {
    hi = __float2half_rn(x);
    lo = __float2half_rn(x - __half2float(hi));
}
__device__ __forceinline__ void split2h(float a, float b, uint32_t& hi, uint32_t& lo) {
    __half ha, la, hb, lb;
    split_h(a, ha, la);
    split_h(b, hb, lb);
    __half2 th = __halves2half2(ha, hb);
    __half2 tl = __halves2half2(la, lb);
    hi = *reinterpret_cast<uint32_t*>(&th);
    lo = *reinterpret_cast<uint32_t*>(&tl);
}
__device__ __forceinline__ uint32_t cvt_h2(float a, float b) {
    __half2 t = __floats2half2_rn(a, b);
    return *reinterpret_cast<uint32_t*>(&t);
}
__device__ __forceinline__ float ex2f(float x) {
    float y; asm("ex2.approx.ftz.f32 %0, %1;" : "=f"(y) : "f"(x)); return y;
}

#define SA_STRIDE 40
#define SB_STRIDE 136
#define SC_STRIDE 72

// =====================================================================
// One-shot weight prep: Wq/convW 2-term; Wk/Wv/Wout single plane.
// conv W reordered [o][c*9+t] -> [o][t*256+c].
// =====================================================================
__global__ void __launch_bounds__(256) split_all(
    const float* __restrict__ Wq, const float* __restrict__ Wk,
    const float* __restrict__ Wv, const float* __restrict__ Wout,
    const float* __restrict__ Woff1, float kscale)
{
    int idx = blockIdx.x * 256 + threadIdx.x;
    if (idx < 4 * 65536) {
        int w = idx >> 16, i = idx & 65535;
        if (w == 0) {
            split_h(Wq[i], w_qh16[i], w_ql16[i]);
        } else if (w == 1) {
            w_k16[i] = __float2half_rn(Wk[i] * kscale);
        } else if (w == 2) {
            w_v16[i] = __float2half_rn(Wv[i]);
        } else {
            w_o16[i] = __float2half_rn(Wout[i]);
        }
    } else {
        int i = idx - 4 * 65536;
        int o = i / 2304;
        int r = i - o * 2304;
        int c = r / 9;
        int t = r - c * 9;
        int dst = o * 2304 + t * 256 + c;
        split_h(Woff1[i], w_ch16[dst], w_cl16[dst]);
    }
}

// =====================================================================
// GEMM via mma.sync fp16.
// AMODE: 0 = A single plane (2 mma), 1 = A 2-term (3 mma, Al*Bl dropped)
// BMODE: 0 = fp32 B (split at store), 1 = fp16 plane B (Bh/Bl).
// OMODE bit0: fp32 out (+bias); bit1: fp16 split planes out.
// CTA tile 128x128, grid (8, O/128, 8), 256 threads.
// =====================================================================
template<int AMODE, int BMODE, int OMODE>
__global__ void __launch_bounds__(256) gemm_mma(
    const __half* __restrict__ Ah, const __half* __restrict__ Al,
    const float* __restrict__ Bf,
    const __half* __restrict__ Bh, const __half* __restrict__ Bl,
    const float* __restrict__ bias,
    float* __restrict__ Yf,
    __half* __restrict__ Yh, __half* __restrict__ Yl,
    int Cin)
{
    __shared__ __align__(16) __half sA[AMODE + 1][128][SA_STRIDE];
    __shared__ __align__(16) __half sB[2][32][SB_STRIDE];
    const int b  = blockIdx.z;
    const int o0 = blockIdx.y * 128;
    const int p0 = blockIdx.x * 128;
    const int O  = gridDim.y * 128;
    const size_t bB = (size_t)b * Cin * Pn;
    const size_t bY = (size_t)b * O * Pn;
    const int tid  = threadIdx.x;
    const int lane = tid & 31;
    const int wid  = tid >> 5;
    const int wm   = wid & 3;
    const int wn   = wid >> 2;

    float d[2][8][4];
    #pragma unroll
    for (int mf = 0; mf < 2; mf++)
        #pragma unroll
        for (int nf = 0; nf < 8; nf++)
            #pragma unroll
            for (int i = 0; i < 4; i++) d[mf][nf][i] = 0.0f;

    const int a_row  = (lane & 7) + ((lane >> 3) & 1) * 8;
    const int a_colk = ((lane >> 4) & 1) * 8;
    const int b_rowk = (lane & 7) + ((lane >> 3) & 1) * 8;
    const int b_ncol = ((lane >> 4) & 1) * 8;

    uint4  ra[AMODE + 1][2];
    float4 rbf[4];
    uint4  rb[2][2];

    auto loadA = [&](int c0) {
        #pragma unroll
        for (int t = 0; t < AMODE + 1; t++) {
            const __half* Ap = t ? Al : Ah;
            #pragma unroll
            for (int i = 0; i < 2; i++) {
                int e = tid + i * 256;
                int o = e >> 2, c8 = (e & 3) * 8;
                ra[t][i] = *reinterpret_cast<const uint4*>(
                    Ap + (size_t)(o0 + o) * Cin + c0 + c8);
            }
        }
    };
    auto storeA = [&]() {
        #pragma unroll
        for (int t = 0; t < AMODE + 1; t++)
            #pragma unroll
            for (int i = 0; i < 2; i++) {
                int e = tid + i * 256;
                int o = e >> 2, c8 = (e & 3) * 8;
                *reinterpret_cast<uint4*>(&sA[t][o][c8]) = ra[t][i];
            }
    };
    auto loadB = [&](int c0) {
        if (BMODE == 0) {
            #pragma unroll
            for (int i = 0; i < 4; i++) {
                int e = tid + i * 256;
                int k = e >> 5, p4 = (e & 31) * 4;
                rbf[i] = *reinterpret_cast<const float4*>(
                    Bf + bB + (size_t)(c0 + k) * Pn + p0 + p4);
            }
        } else {
            #pragma unroll
            for (int t = 0; t < 2; t++) {
                const __half* Bp = t ? Bl : Bh;
                #pragma unroll
                for (int i = 0; i < 2; i++) {
                    int e = tid + i * 256;
                    int k = e >> 4, p8 = (e & 15) * 8;
                    rb[t][i] = *reinterpret_cast<const uint4*>(
                        Bp + bB + (size_t)(c0 + k) * Pn + p0 + p8);
                }
            }
        }
    };
    auto storeB = [&]() {
        if (BMODE == 0) {
            #pragma unroll
            for (int i = 0; i < 4; i++) {
                int e = tid + i * 256;
                int k = e >> 5, p4 = (e & 31) * 4;
                float4 x = rbf[i];
                uint32_t h0, l0, h1, l1;
                split2h(x.x, x.y, h0, l0);
                split2h(x.z, x.w, h1, l1);
                *reinterpret_cast<uint32_t*>(&sB[0][k][p4])     = h0;
                *reinterpret_cast<uint32_t*>(&sB[0][k][p4 + 2]) = h1;
                *reinterpret_cast<uint32_t*>(&sB[1][k][p4])     = l0;
                *reinterpret_cast<uint32_t*>(&sB[1][k][p4 + 2]) = l1;
            }
        } else {
            #pragma unroll
            for (int t = 0; t < 2; t++)
                #pragma unroll
                for (int i = 0; i < 2; i++) {
                    int e = tid + i * 256;
                    int k = e >> 4, p8 = (e & 15) * 8;
                    *reinterpret_cast<uint4*>(&sB[t][k][p8]) = rb[t][i];
                }
        }
    };

    loadA(0); loadB(0);
    storeA(); storeB();
    __syncthreads();

    for (int c0 = 0; c0 < Cin; c0 += 32) {
        bool more = (c0 + 32 < Cin);
        if (more) { loadA(c0 + 32); loadB(c0 + 32); }

        #pragma unroll
        for (int kk = 0; kk < 32; kk += 16) {
            uint32_t afr[AMODE + 1][2][4];
            #pragma unroll
            for (int t2 = 0; t2 < AMODE + 1; t2++)
                #pragma unroll
                for (int mf = 0; mf < 2; mf++)
                    ldsm_x4(afr[t2][mf],
                        smem_u32(&sA[t2][wm * 32 + mf * 16 + a_row][kk + a_colk]));
            uint32_t bfr[2][8][2];
            #pragma unroll
            for (int t2 = 0; t2 < 2; t2++)
                #pragma unroll
                for (int nf2 = 0; nf2 < 4; nf2++) {
                    uint32_t r[4];
                    ldsm_x4_t(r, smem_u32(
                        &sB[t2][kk + b_rowk][wn * 64 + nf2 * 16 + b_ncol]));
                    bfr[t2][2 * nf2][0] = r[0]; bfr[t2][2 * nf2][1] = r[1];
                    bfr[t2][2 * nf2 + 1][0] = r[2]; bfr[t2][2 * nf2 + 1][1] = r[3];
                }
            #pragma unroll
            for (int mf = 0; mf < 2; mf++)
                #pragma unroll
                for (int nf = 0; nf < 8; nf++) {
                    mma_f16(d[mf][nf], afr[0][mf], bfr[0][nf]);
                    mma_f16(d[mf][nf], afr[0][mf], bfr[1][nf]);
                    if (AMODE == 1)
                        mma_f16(d[mf][nf], afr[1][mf], bfr[0][nf]);
                }
        }
        __syncthreads();
        if (more) { storeA(); storeB(); __syncthreads(); }
    }

    #pragma unroll
    for (int mf = 0; mf < 2; mf++) {
        int r = o0 + wm * 32 + mf * 16 + (lane >> 2);
        float b0v = bias ? bias[r] : 0.0f;
        float b1v = bias ? bias[r + 8] : 0.0f;
        #pragma unroll
        for (int nf = 0; nf < 8; nf++) {
            int cb = p0 + wn * 64 + nf * 8 + (lane & 3) * 2;
            float v00 = d[mf][nf][0] + b0v, v01 = d[mf][nf][1] + b0v;
            float v10 = d[mf][nf][2] + b1v, v11 = d[mf][nf][3] + b1v;
            if (OMODE & 1) {
                *reinterpret_cast<float2*>(Yf + bY + (size_t)r * Pn + cb) =
                    make_float2(v00, v01);
                *reinterpret_cast<float2*>(Yf + bY + (size_t)(r + 8) * Pn + cb) =
                    make_float2(v10, v11);
            }
            if (OMODE & 2) {
                uint32_t h0, l0, h1, l1;
                split2h(v00, v01, h0, l0);
                split2h(v10, v11, h1, l1);
                *reinterpret_cast<uint32_t*>(Yh + bY + (size_t)r * Pn + cb)       = h0;
                *reinterpret_cast<uint32_t*>(Yl + bY + (size_t)r * Pn + cb)       = l0;
                *reinterpret_cast<uint32_t*>(Yh + bY + (size_t)(r + 8) * Pn + cb) = h1;
                *reinterpret_cast<uint32_t*>(Yl + bY + (size_t)(r + 8) * Pn + cb) = l1;
            }
        }
    }
}

// =====================================================================
// Fused K+V projection (fp16, 2 mma). K, V -> single fp16 planes.
// grid (8, 4, 8), 256 threads: warps 0-3 -> K, warps 4-7 -> V.
// =====================================================================
__global__ void __launch_bounds__(256) gemm_kv()
{
    __shared__ __align__(16) __half sAk[64][SA_STRIDE];
    __shared__ __align__(16) __half sAv[64][SA_STRIDE];
    __shared__ __align__(16) __half sB[2][32][SB_STRIDE];
    const int b  = blockIdx.z;
    const int o0 = blockIdx.y * 64;
    const int p0 = blockIdx.x * 128;
    const size_t bB = (size_t)b * Cn * Pn;
    const int tid  = threadIdx.x;
    const int lane = tid & 31;
    const int wid  = tid >> 5;
    const int half = wid >> 2;
    const int w2   = wid & 3;
    const int wm   = w2 & 1;
    const int wn   = w2 >> 1;

    float d[2][8][4];
    #pragma unroll
    for (int mf = 0; mf < 2; mf++)
        #pragma unroll
        for (int nf = 0; nf < 8; nf++)
            #pragma unroll
            for (int i = 0; i < 4; i++) d[mf][nf][i] = 0.0f;

    const int a_row  = (lane & 7) + ((lane >> 3) & 1) * 8;
    const int a_colk = ((lane >> 4) & 1) * 8;
    const int b_rowk = (lane & 7) + ((lane >> 3) & 1) * 8;
    const int b_ncol = ((lane >> 4) & 1) * 8;

    const int ao = tid >> 2, ac8 = (tid & 3) * 8;
    uint4 ra[2];
    uint4 rb[2][2];
    auto loadA = [&](int c0) {
        size_t off = (size_t)(o0 + ao) * Cn + c0 + ac8;
        ra[0] = *reinterpret_cast<const uint4*>(w_k16 + off);
        ra[1] = *reinterpret_cast<const uint4*>(w_v16 + off);
    };
    auto storeA = [&]() {
        *reinterpret_cast<uint4*>(&sAk[ao][ac8]) = ra[0];
        *reinterpret_cast<uint4*>(&sAv[ao][ac8]) = ra[1];
    };
    auto loadB = [&](int c0) {
        #pragma unroll
        for (int t = 0; t < 2; t++) {
            const __half* Bp = t ? g_sl : g_sh;
            #pragma unroll
            for (int i = 0; i < 2; i++) {
                int e = tid + i * 256;
                int k = e >> 4, p8 = (e & 15) * 8;
                rb[t][i] = *reinterpret_cast<const uint4*>(
                    Bp + bB + (size_t)(c0 + k) * Pn + p0 + p8);
            }
        }
    };
    auto storeB = [&]() {
        #pragma unroll
        for (int t = 0; t < 2; t++)
            #pragma unroll
            for (int i = 0; i < 2; i++) {
                int e = tid + i * 256;
                int k = e >> 4, p8 = (e & 15) * 8;
                *reinterpret_cast<uint4*>(&sB[t][k][p8]) = rb[t][i];
            }
    };

    loadA(0); loadB(0);
    storeA(); storeB();
    __syncthreads();

    for (int c0 = 0; c0 < Cn; c0 += 32) {
        bool more = (c0 + 32 < Cn);
        if (more) { loadA(c0 + 32); loadB(c0 + 32); }

        #pragma unroll
        for (int kk = 0; kk < 32; kk += 16) {
            uint32_t afr[2][4];
            #pragma unroll
            for (int mf = 0; mf < 2; mf++) {
                const __half* base = half
                    ? &sAv[wm * 32 + mf * 16 + a_row][kk + a_colk]
                    : &sAk[wm * 32 + mf * 16 + a_row][kk + a_colk];
                ldsm_x4(afr[mf], smem_u32(base));
            }
            uint32_t bfr[2][8][2];
            #pragma unroll
            for (int t2 = 0; t2 < 2; t2++)
                #pragma unroll
                for (int nf2 = 0; nf2 < 4; nf2++) {
                    uint32_t r[4];
                    ldsm_x4_t(r, smem_u32(
                        &sB[t2][kk + b_rowk][wn * 64 + nf2 * 16 + b_ncol]));
                    bfr[t2][2 * nf2][0] = r[0]; bfr[t2][2 * nf2][1] = r[1];
                    bfr[t2][2 * nf2 + 1][0] = r[2]; bfr[t2][2 * nf2 + 1][1] = r[3];
                }
            #pragma unroll
            for (int mf = 0; mf < 2; mf++)
                #pragma unroll
                for (int nf = 0; nf < 8; nf++) {
                    mma_f16(d[mf][nf], afr[mf], bfr[0][nf]);
                    mma_f16(d[mf][nf], afr[mf], bfr[1][nf]);
                }
        }
        __syncthreads();
        if (more) { storeA(); storeB(); __syncthreads(); }
    }

    __half* Yp = (half ? g_vf : g_kf);
    #pragma unroll
    for (int mf = 0; mf < 2; mf++) {
        int r = o0 + wm * 32 + mf * 16 + (lane >> 2);
        #pragma unroll
        for (int nf = 0; nf < 8; nf++) {
            int cb = p0 + wn * 64 + nf * 8 + (lane & 3) * 2;
            uint32_t p0w = cvt_h2(d[mf][nf][0], d[mf][nf][1]);
            uint32_t p1w = cvt_h2(d[mf][nf][2], d[mf][nf][3]);
            *reinterpret_cast<uint32_t*>(Yp + bB + (size_t)r * Pn + cb)       = p0w;
            *reinterpret_cast<uint32_t*>(Yp + bB + (size_t)(r + 8) * Pn + cb) = p1w;
        }
    }
}

// =====================================================================
// Conv as GEMM with FUSED shift (fp16 2-term W, 3 mma). splitK=2.
// grid (16, 2, 8), 256 threads.
// =====================================================================
__global__ void __launch_bounds__(256) conv_mma3()
{
    __shared__ __align__(16) __half sA[2][128][SA_STRIDE];
    __shared__ __align__(16) __half sB[2][32][SC_STRIDE];
    const int b  = blockIdx.z;
    const int ks = blockIdx.y;
    const int p0 = blockIdx.x * 64;
    float* Yb = (ks ? g_h1b : g_h1a) + (size_t)b * 128 * Pn;
    const size_t bQ = (size_t)b * Cn * Pn;
    const int tid  = threadIdx.x;
    const int lane = tid & 31;
    const int wid  = tid >> 5;
    const int wm   = wid & 3;
    const int wn   = wid >> 2;

    float d[2][4][4];
    #pragma unroll
    for (int mf = 0; mf < 2; mf++)
        #pragma unroll
        for (int nf = 0; nf < 4; nf++)
            #pragma unroll
            for (int i = 0; i < 4; i++) d[mf][nf][i] = 0.0f;

    const int a_row  = (lane & 7) + ((lane >> 3) & 1) * 8;
    const int a_colk = ((lane >> 4) & 1) * 8;
    const int b_rowk = (lane & 7) + ((lane >> 3) & 1) * 8;
    const int b_ncol = ((lane >> 4) & 1) * 8;

    uint4 ra[2][2], rb[2];
    auto loadA = [&](int c0) {
        #pragma unroll
        for (int t = 0; t < 2; t++) {
            const __half* Ap = t ? w_cl16 : w_ch16;
            #pragma unroll
            for (int i = 0; i < 2; i++) {
                int e = tid + i * 256;
                int o = e >> 2, c8 = (e & 3) * 8;
                ra[t][i] = *reinterpret_cast<const uint4*>(
                    Ap + (size_t)o * 2304 + c0 + c8);
            }
        }
    };
    auto storeA = [&]() {
        #pragma unroll
        for (int t = 0; t < 2; t++)
            #pragma unroll
            for (int i = 0; i < 2; i++) {
                int e = tid + i * 256;
                int o = e >> 2, c8 = (e & 3) * 8;
                *reinterpret_cast<uint4*>(&sA[t][o][c8]) = ra[t][i];
            }
    };
    const int bk = tid >> 3, bp8 = (tid & 7) * 8;
    const int P  = p0 + bp8;
    const int x0 = P & 31;
    const int yb = P >> 5;
    auto loadB = [&](int c0) {
        int t  = c0 >> 8;
        int cc = (c0 & 255) + bk;
        int ty = t / 3;
        int dy = ty - 1;
        int dx = t - ty * 3 - 1;
        int ys = yb + dy;
        bool yok = (unsigned)ys < 32u;
        size_t rowoff = bQ + (size_t)cc * Pn + ys * 32;
        #pragma unroll
        for (int pl = 0; pl < 2; pl++) {
            const __half* Qp = pl ? g_ql : g_qh;
            uint4 v = make_uint4(0u, 0u, 0u, 0u);
            if (yok) {
                uint4 w = *reinterpret_cast<const uint4*>(Qp + rowoff + x0);
                if (dx == 0) {
                    v = w;
                } else if (dx > 0) {
                    uint32_t extra = 0;
                    if (x0 != 24)
                        extra = *reinterpret_cast<const uint16_t*>(
                            Qp + rowoff + x0 + 8);
                    v.x = __funnelshift_r(w.x, w.y, 16);
                    v.y = __funnelshift_r(w.y, w.z, 16);
                    v.z = __funnelshift_r(w.z, w.w, 16);
                    v.w = (w.w >> 16) | (extra << 16);
                } else {
                    uint32_t extra = 0;
                    if (x0 != 0)
                        extra = *reinterpret_cast<const uint16_t*>(
                            Qp + rowoff + x0 - 1);
                    v.x = (w.x << 16) | extra;
                    v.y = __funnelshift_l(w.x, w.y, 16);
                    v.z = __funnelshift_l(w.y, w.z, 16);
                    v.w = __funnelshift_l(w.z, w.w, 16);
                }
            }
            rb[pl] = v;
        }
    };
    auto storeB = [&]() {
        *reinterpret_cast<uint4*>(&sB[0][bk][bp8]) = rb[0];
        *reinterpret_cast<uint4*>(&sB[1][bk][bp8]) = rb[1];
    };

    const int cbeg = ks * 1152, cend = cbeg + 1152;
    loadA(cbeg); loadB(cbeg);
    storeA(); storeB();
    __syncthreads();

    for (int c0 = cbeg; c0 < cend; c0 += 32) {
        bool more = (c0 + 32 < cend);
        if (more) { loadA(c0 + 32); loadB(c0 + 32); }

        #pragma unroll
        for (int kk = 0; kk < 32; kk += 16) {
            uint32_t afr[2][2][4];
            #pragma unroll
            for (int t2 = 0; t2 < 2; t2++)
                #pragma unroll
                for (int mf = 0; mf < 2; mf++)
                    ldsm_x4(afr[t2][mf],
                        smem_u32(&sA[t2][wm * 32 + mf * 16 + a_row][kk + a_colk]));
            uint32_t bfr[2][4][2];
            #pragma unroll
            for (int t2 = 0; t2 < 2; t2++)
                #pragma unroll
                for (int nf2 = 0; nf2 < 2; nf2++) {
                    uint32_t r[4];
                    ldsm_x4_t(r, smem_u32(
                        &sB[t2][kk + b_rowk][wn * 32 + nf2 * 16 + b_ncol]));
                    bfr[t2][2 * nf2][0] = r[0]; bfr[t2][2 * nf2][1] = r[1];
                    bfr[t2][2 * nf2 + 1][0] = r[2]; bfr[t2][2 * nf2 + 1][1] = r[3];
                }
            #pragma unroll
            for (int mf = 0; mf < 2; mf++)
                #pragma unroll
                for (int nf = 0; nf < 4; nf++) {
                    mma_f16(d[mf][nf], afr[0][mf], bfr[0][nf]);
                    mma_f16(d[mf][nf], afr[0][mf], bfr[1][nf]);
                    mma_f16(d[mf][nf], afr[1][mf], bfr[0][nf]);
                }
        }
        __syncthreads();
        if (more) { storeA(); storeB(); __syncthreads(); }
    }
    #pragma unroll
    for (int mf = 0; mf < 2; mf++) {
        int r = wm * 32 + mf * 16 + (lane >> 2);
        #pragma unroll
        for (int nf = 0; nf < 4; nf++) {
            int cb = p0 + wn * 32 + nf * 8 + (lane & 3) * 2;
            *reinterpret_cast<float2*>(Yb + (size_t)r * Pn + cb) =
                make_float2(d[mf][nf][0], d[mf][nf][1]);
            *reinterpret_cast<float2*>(Yb + (size_t)(r + 8) * Pn + cb) =
                make_float2(d[mf][nf][2], d[mf][nf][3]);
        }
    }
}

// =====================================================================
// Offsets, 16-way channel split. grid (64, 8) = 512 CTAs.
// =====================================================================
__global__ void __launch_bounds__(256) offs_kernel4(
    const float* __restrict__ Woff2, const float* __restrict__ boff2,
    const float* __restrict__ boff1)
{
    __shared__ float red[2][16][16];
    const int b   = blockIdx.y;
    const int px  = threadIdx.x & 15;
    const int seg = threadIdx.x >> 4;          // 0..15
    const int p   = blockIdx.x * 16 + px;
    const float* h1a = g_h1a + (size_t)b * 128 * Pn;
    const float* h1b = g_h1b + (size_t)b * 128 * Pn;
    const int c0 = seg * 8;
    float ox0 = 0.0f, oy0 = 0.0f, ox1 = 0.0f, oy1 = 0.0f;
    #pragma unroll
    for (int c = c0; c < c0 + 8; c += 2) {
        size_t i0 = (size_t)c * Pn + p;
        size_t i1 = (size_t)(c + 1) * Pn + p;
        float h0 = fmaxf(h1a[i0] + h1b[i0] + boff1[c], 0.0f);
        float h1 = fmaxf(h1a[i1] + h1b[i1] + boff1[c + 1], 0.0f);
        ox0 += Woff2[c] * h0;       oy0 += Woff2[128 + c] * h0;
        ox1 += Woff2[c + 1] * h1;   oy1 += Woff2[128 + c + 1] * h1;
    }
    red[0][seg][px] = ox0 + ox1;
    red[1][seg][px] = oy0 + oy1;
    __syncthreads();
    if (threadIdx.x < 16) {
        float sx = boff2[0], sy = boff2[1];
        #pragma unroll
        for (int s = 0; s < 16; s++) {
            sx += red[0][s][threadIdx.x];
            sy += red[1][s][threadIdx.x];
        }
        g_off[((size_t)b * 2 + 0) * Pn + blockIdx.x * 16 + threadIdx.x] = sx * 0.1f;
        g_off[((size_t)b * 2 + 1) * Pn + blockIdx.x * 16 + threadIdx.x] = sy * 0.1f;
    }
}

// =====================================================================
// Bilinear grid sample -> fp16 split planes. grid (4, 8, 16).
// =====================================================================
__global__ void __launch_bounds__(256) samp_kernel(const float* __restrict__ kv)
{
    const int b  = blockIdx.y;
    const int p  = blockIdx.x * 256 + threadIdx.x;
    const int c0 = blockIdx.z * 16;
    float ox = g_off[((size_t)b * 2 + 0) * Pn + p];
    float oy = g_off[((size_t)b * 2 + 1) * Pn + p];
    int px = p & 31, py = p >> 5;
    float gx = -1.0f + px * (2.0f / 31.0f);
    float gy = -1.0f + py * (2.0f / 31.0f);
    float x = (gx + ox + 1.0f) * 0.5f * 31.0f;
    float y = (gy + oy + 1.0f) * 0.5f * 31.0f;
    x = fminf(fmaxf(x, 0.0f), 31.0f);
    y = fminf(fmaxf(y, 0.0f), 31.0f);
    float x0f = floorf(x), y0f = floorf(y);
    float wx = x - x0f, wy = y - y0f;
    int x0 = (int)x0f, y0 = (int)y0f;
    int x1 = min(x0 + 1, 31), y1 = min(y0 + 1, 31);
    float w00 = (1.0f - wx) * (1.0f - wy);
    float w01 = wx * (1.0f - wy);
    float w10 = (1.0f - wx) * wy;
    float w11 = wx * wy;
    int i00 = (y0 << 5) + x0, i01 = (y0 << 5) + x1;
    int i10 = (y1 << 5) + x0, i11 = (y1 << 5) + x1;
    const float* kvb = kv + (size_t)b * Cn * Pn;
    const size_t ob = (size_t)b * Cn * Pn;
    #pragma unroll 4
    for (int c = c0; c < c0 + 16; c++) {
        const float* pl = kvb + (size_t)c * Pn;
        float v = w00 * pl[i00] + w01 * pl[i01] + w10 * pl[i10] + w11 * pl[i11];
        __half h, l;
        split_h(v, h, l);
        g_sh[ob + (size_t)c * Pn + p] = h;
        g_sl[ob + (size_t)c * Pn + p] = l;
    }
}

// =====================================================================
// Flash attention, pipelined KV loads. Q, K, V all single fp16 plane:
// QK 1 mma, PV 2 mma (P, V single; V_lo dropped -> 1 mma)... total
// per (nb/ks8 group): QK 32 mma/kt, PV 32 mma/kt. grid (8, 64).
// =====================================================================
__global__ void __launch_bounds__(256) attn_mma()
{
    __shared__ __align__(16) __half sK[32][SB_STRIDE];
    __shared__ __align__(16) __half sV[32][SB_STRIDE];

    const int bh = blockIdx.y;
    const int b  = bh >> 3, h = bh & 7;
    const int p0 = blockIdx.x * 128;
    const int tid  = threadIdx.x;
    const int lane = tid & 31;
    const int wm   = tid >> 5;
    const size_t base = ((size_t)b * Cn + h * HD) * Pn;

    const int krow = (lane & 7) + ((lane >> 3) & 1) * 8;
    const int ncol = ((lane >> 4) & 1) * 8;

    // ---- stage Q hi plane into sV region, extract A-frags ----
    __half* stage = &sV[0][0];
    #pragma unroll
    for (int i = 0; i < 2; i++) {
        int e = tid + i * 256;
        int d = e >> 4, p8 = (e & 15) * 8;
        uint4 v = *reinterpret_cast<const uint4*>(g_qh + base + (size_t)d * Pn + p0 + p8);
        *reinterpret_cast<uint4*>(stage + (size_t)d * SB_STRIDE + p8) = v;
    }
    __syncthreads();
    uint32_t aQ[2][4];   // [kstep][4]
    #pragma unroll
    for (int ks = 0; ks < 2; ks++) {
        uint32_t r[4];
        ldsm_x4_t(r, smem_u32(
            stage + (size_t)(ks * 16 + krow) * SB_STRIDE + wm * 16 + ncol));
        aQ[ks][0] = r[0]; aQ[ks][1] = r[2];
        aQ[ks][2] = r[1]; aQ[ks][3] = r[3];
    }

    float O[4][4];
    #pragma unroll
    for (int nf = 0; nf < 4; nf++)
        #pragma unroll
        for (int i = 0; i < 4; i++) O[nf][i] = 0.0f;
    float lsum0 = 0.0f, lsum1 = 0.0f;

    const int vrow = (lane & 7) + ((lane >> 3) & 1) * 8;
    const int vcol = ((lane >> 4) & 1) * 8;

    const int ld_d  = tid >> 4;
    const int ld_p8 = (tid & 15) * 8;
    uint4 rk[2], rv[2];
    auto loadKV = [&](int kv0) {
        #pragma unroll
        for (int i = 0; i < 2; i++) {
            int d = ld_d + i * 16;
            rk[i] = *reinterpret_cast<const uint4*>(
                g_kf + base + (size_t)d * Pn + kv0 + ld_p8);
            rv[i] = *reinterpret_cast<const uint4*>(
                g_vf + base + (size_t)d * Pn + kv0 + ld_p8);
        }
    };
    auto storeKV = [&]() {
        #pragma unroll
        for (int i = 0; i < 2; i++) {
            int d = ld_d + i * 16;
            *reinterpret_cast<uint4*>(&sK[d][ld_p8]) = rk[i];
            *reinterpret_cast<uint4*>(&sV[d][ld_p8]) = rv[i];
        }
    };

    loadKV(0);

    for (int kt = 0; kt < 8; kt++) {
        __syncthreads();
        storeKV();
        __syncthreads();
        if (kt + 1 < 8) loadKV((kt + 1) * 128);

        float S[16][4];
        #pragma unroll
        for (int f = 0; f < 16; f++)
            #pragma unroll
            for (int i = 0; i < 4; i++) S[f][i] = 0.0f;

        #pragma unroll
        for (int nb = 0; nb < 8; nb++) {
            uint32_t bk[2][4];
            #pragma unroll
            for (int ks = 0; ks < 2; ks++)
                ldsm_x4_t(bk[ks],
                    smem_u32(&sK[ks * 16 + krow][nb * 16 + ncol]));
            #pragma unroll
            for (int half = 0; half < 2; half++) {
                float* s = S[nb * 2 + half];
                #pragma unroll
                for (int ks = 0; ks < 2; ks++) {
                    uint32_t bb[2] = {bk[ks][2 * half], bk[ks][2 * half + 1]};
                    mma_f16(s, aQ[ks], bb);
                }
            }
        }
        #pragma unroll
        for (int f = 0; f < 16; f++) {
            S[f][0] = ex2f(S[f][0]); S[f][1] = ex2f(S[f][1]);
            S[f][2] = ex2f(S[f][2]); S[f][3] = ex2f(S[f][3]);
            lsum0 += S[f][0] + S[f][1];
            lsum1 += S[f][2] + S[f][3];
        }
        #pragma unroll
        for (int ks8 = 0; ks8 < 8; ks8++) {
            uint32_t ah[4];
            const float* f0 = S[2 * ks8];
            const float* f1 = S[2 * ks8 + 1];
            ah[0] = cvt_h2(f0[0], f0[1]);
            ah[1] = cvt_h2(f0[2], f0[3]);
            ah[2] = cvt_h2(f1[0], f1[1]);
            ah[3] = cvt_h2(f1[2], f1[3]);
            uint32_t bv[2][4];
            #pragma unroll
            for (int db = 0; db < 2; db++)
                ldsm_x4(bv[db],
                    smem_u32(&sV[db * 16 + vrow][ks8 * 16 + vcol]));
            #pragma unroll
            for (int nf = 0; nf < 4; nf++) {
                int db = nf >> 1, wh = nf & 1;
                uint32_t vv[2] = {bv[db][wh], bv[db][wh + 2]};
                mma_f16(O[nf], ah, vv);
            }
        }
    }
    lsum0 += __shfl_xor_sync(0xffffffffu, lsum0, 1);
    lsum0 += __shfl_xor_sync(0xffffffffu, lsum0, 2);
    lsum1 += __shfl_xor_sync(0xffffffffu, lsum1, 1);
    lsum1 += __shfl_xor_sync(0xffffffffu, lsum1, 2);
    float inv0 = 1.0f / lsum0, inv1 = 1.0f / lsum1;
    int p = p0 + wm * 16 + (lane >> 2);
    #pragma unroll
    for (int nf = 0; nf < 4; nf++) {
        int d = nf * 8 + (lane & 3) * 2;
        float v0 = O[nf][0] * inv0, v1 = O[nf][1] * inv0;
        float v2 = O[nf][2] * inv1, v3 = O[nf][3] * inv1;
        __half hh, ll;
        split_h(v0, hh, ll);
        g_oh[base + (size_t)d * Pn + p] = hh;       g_ol[base + (size_t)d * Pn + p] = ll;
        split_h(v1, hh, ll);
        g_oh[base + (size_t)(d + 1) * Pn + p] = hh; g_ol[base + (size_t)(d + 1) * Pn + p] = ll;
        split_h(v2, hh, ll);
        g_oh[base + (size_t)d * Pn + p + 8] = hh;   g_ol[base + (size_t)d * Pn + p + 8] = ll;
        split_h(v3, hh, ll);
        g_oh[base + (size_t)(d + 1) * Pn + p + 8] = hh;
        g_ol[base + (size_t)(d + 1) * Pn + p + 8] = ll;
    }
}

// =====================================================================
extern "C" void kernel_launch(void* const* d_in, const int* in_sizes, int n_in,
                              void* d_out, int out_size)
{
    (void)in_sizes; (void)n_in; (void)out_size;
    const float* query_map = (const float*)d_in[0];
    const float* kv_map    = (const float*)d_in[1];
    const float* Wq        = (const float*)d_in[2];
    const float* Wk        = (const float*)d_in[3];
    const float* Wv        = (const float*)d_in[4];
    const float* Woff1     = (const float*)d_in[5];
    const float* boff1     = (const float*)d_in[6];
    const float* Woff2     = (const float*)d_in[7];
    const float* boff2     = (const float*)d_in[8];
    const float* Wout      = (const float*)d_in[9];
    const float* bout      = (const float*)d_in[10];
    float* out = (float*)d_out;

    const float kscale = 0.17677669529663687f * 1.4426950408889634f;

    __half *pqh, *pql, *poh, *pol, *pwqh, *pwql, *pwo;
    cudaGetSymbolAddress((void**)&pqh, g_qh);    cudaGetSymbolAddress((void**)&pql, g_ql);
    cudaGetSymbolAddress((void**)&poh, g_oh);    cudaGetSymbolAddress((void**)&pol, g_ol);
    cudaGetSymbolAddress((void**)&pwqh, w_qh16); cudaGetSymbolAddress((void**)&pwql, w_ql16);
    cudaGetSymbolAddress((void**)&pwo, w_o16);

    // 0) one-shot weight prep (Wq/convW 2-term; Wk/Wv/Wout single)
    split_all<<<2176, 256>>>(Wq, Wk, Wv, Wout, Woff1, kscale);
    // 1) q projection (3-mma, precise) -> fp16 split planes
    gemm_mma<1, 0, 2><<<dim3(8, 2, 8), 256>>>(
        pwqh, pwql, query_map, nullptr, nullptr, nullptr,
        nullptr, pqh, pql, 256);
    // 2) conv GEMM with fused shift (3-mma, precise offsets path)
    conv_mma3<<<dim3(16, 2, 8), 256>>>();
    // 3) offsets — 16-way split reduction
    offs_kernel4<<<dim3(64, 8), 256>>>(Woff2, boff2, boff1);
    // 4) bilinear sample -> fp16 split planes
    samp_kernel<<<dim3(4, 8, 16), 256>>>(kv_map);
    // 5) fused K+V projections (single fp16 plane outputs)
    gemm_kv<<<dim3(8, 4, 8), 256>>>();
    // 6) attention (1-mma QK, 1-mma PV — 64 mma/kt)
    attn_mma<<<dim3(8, 64), 256>>>();
    // 7) out = Wout @ attn_out + bout
    gemm_mma<0, 1, 1><<<dim3(8, 2, 8), 256>>>(
        pwo, nullptr, nullptr, poh, pol, bout,
        out, nullptr, nullptr, 256);
}